// round 7
// baseline (speedup 1.0000x reference)
#include <cuda_runtime.h>
#include <cuda_bf16.h>
#include <float.h>
#include <math.h>
#include <cstdint>

#define BB  8
#define NN  2048
#define KNN 20

// ---------------- scratch (device globals; no allocations) ----------------
__device__ __align__(16) float g_xx[BB * NN];
__device__ __align__(16) int   g_idx[BB * NN * KNN];
__device__ __align__(16) float g_yc[(size_t)BB * NN * 512];    // y | c combined
__device__ __align__(16) float g_hcat[(size_t)BB * NN * 512];
__device__ __align__(16) float g_tmp[(size_t)BB * NN * 1024];
__device__ __align__(16) float g_bias2[512];
__device__ __align__(16) __nv_bfloat16 g_a3[(size_t)BB * NN * 1536];  // split A (h|l|h)
__device__ __align__(16) __nv_bfloat16 g_b3[(size_t)BB * NN * 384];   // split B (h|h|l)
__device__ __align__(16) __nv_bfloat16 g_bf3[1024 * 1536];            // split Wf
__device__ __align__(16) __nv_bfloat16 g_w3[512 * 384];               // split layer W (y|c)

// =================== split-precision conversion kernels ===================
// fused A+B split for X: one read, writes a3 (h|l|h) and b3 (h|h|l)
__global__ void convAB_kernel(const float* __restrict__ in, int ld, int C,
                              __nv_bfloat16* __restrict__ a3,
                              __nv_bfloat16* __restrict__ b3, int K3) {
    int r = blockIdx.y;
    int c = blockIdx.x * 256 + threadIdx.x;
    if (c >= K3) return;
    size_t ro = (size_t)r * K3;
    if (c < C) {
        float xv = in[(size_t)r * ld + c];
        __nv_bfloat16 h = __float2bfloat16(xv);
        __nv_bfloat16 l = __float2bfloat16(xv - __bfloat162float(h));
        a3[ro + c] = h; a3[ro + C + c] = l; a3[ro + 2 * C + c] = h;
        b3[ro + c] = h; b3[ro + C + c] = h; b3[ro + 2 * C + c] = l;
    } else if (c >= 3 * C) {
        __nv_bfloat16 z = __float2bfloat16(0.f);
        a3[ro + c] = z; b3[ro + c] = z;
    }
}
__global__ void convA_kernel(const float* __restrict__ in, int ld, int C,
                             __nv_bfloat16* __restrict__ out, int K3) {
    int r = blockIdx.y;
    int c = blockIdx.x * 256 + threadIdx.x;
    if (c >= K3) return;
    size_t ro = (size_t)r * K3;
    if (c < C) {
        float xv = in[(size_t)r * ld + c];
        __nv_bfloat16 h = __float2bfloat16(xv);
        __nv_bfloat16 l = __float2bfloat16(xv - __bfloat162float(h));
        out[ro + c] = h; out[ro + C + c] = l; out[ro + 2 * C + c] = h;
    } else if (c >= 3 * C) {
        out[ro + c] = __float2bfloat16(0.f);
    }
}
__global__ void convB_kernel(const float* __restrict__ in, int ld, int C,
                             __nv_bfloat16* __restrict__ out, int K3) {
    int r = blockIdx.y;
    int c = blockIdx.x * 256 + threadIdx.x;
    if (c >= K3) return;
    size_t ro = (size_t)r * K3;
    if (c < C) {
        float xv = in[(size_t)r * ld + c];
        __nv_bfloat16 h = __float2bfloat16(xv);
        __nv_bfloat16 l = __float2bfloat16(xv - __bfloat162float(h));
        out[ro + c] = h; out[ro + C + c] = h; out[ro + 2 * C + c] = l;
    } else if (c >= 3 * C) {
        out[ro + c] = __float2bfloat16(0.f);
    }
}
__global__ void biascat(const float* __restrict__ bl, float* __restrict__ out, int O) {
    int i = threadIdx.x;
    if (i < O) out[i] = 0.f;
    else if (i < 2 * O) out[i] = bl[i - O];
}

#define LDP 72   // padded k-stride (bf16) -> conflict-free fragment loads

__device__ __forceinline__ void mma16816(float* d, const uint32_t* a, const uint32_t* b) {
    asm volatile(
        "mma.sync.aligned.m16n8k16.row.col.f32.bf16.bf16.f32 "
        "{%0,%1,%2,%3}, {%4,%5,%6,%7}, {%8,%9}, {%0,%1,%2,%3};"
        : "+f"(d[0]), "+f"(d[1]), "+f"(d[2]), "+f"(d[3])
        : "r"(a[0]), "r"(a[1]), "r"(a[2]), "r"(a[3]), "r"(b[0]), "r"(b[1]));
}
__device__ __forceinline__ uint32_t smem_u32(const void* p) {
    uint32_t a;
    asm("{ .reg .u64 t; cvta.to.shared.u64 t, %1; cvt.u32.u64 %0, t; }" : "=r"(a) : "l"(p));
    return a;
}
#define CPA(dst, src, n) \
    asm volatile("cp.async.cg.shared.global [%0], [%1], 16, %2;" \
                 :: "r"(dst), "l"(src), "r"(n))
#define CPA_COMMIT() asm volatile("cp.async.commit_group;" ::: "memory")
#define CPA_WAIT1()  asm volatile("cp.async.wait_group 1;" ::: "memory")
#define CPA_WAIT0()  asm volatile("cp.async.wait_group 0;" ::: "memory")

// register insertion into sorted KNN list (strict < keeps lowest idx on ties)
#define INS(keys, kidx, v, ix) do { \
    if ((v) < keys[KNN - 1]) { \
        float _cv = (v); int _ci = (ix); \
        _Pragma("unroll") \
        for (int _j = 0; _j < KNN; ++_j) { \
            if (_cv < keys[_j]) { \
                float _tv = keys[_j]; keys[_j] = _cv; _cv = _tv; \
                int _ti = kidx[_j]; kidx[_j] = _ci; _ci = _ti; \
            } \
        } \
    } } while (0)

#define MMA_SMEM (2 * 2 * 128 * LDP * 2)   // gemm: 2 stages x (A,B) x 128xLDP bf16

// =================== cp.async-pipelined mma.sync GEMM, 128x128 tile ===============
// out[m][o] = acc + bias[o]  (leaky if act)
__global__ void __launch_bounds__(256)
mma_gemm(const __nv_bfloat16* __restrict__ A3, int lda3, size_t zsA,
         const __nv_bfloat16* __restrict__ B3, int ldb3, size_t zsB,
         int Nvalid, int K3,
         float* __restrict__ out, int ldo, size_t zsO,
         const float* __restrict__ bias, int act) {
    extern __shared__ __nv_bfloat16 sm[];
    int tid = threadIdx.x;
    int wid = tid >> 5, lane = tid & 31;
    int wr = wid & 3, wc = wid >> 2;
    int gr = lane >> 2, tg = lane & 3;

    int m0 = blockIdx.y * 128, o0 = blockIdx.x * 128;
    const __nv_bfloat16* Ab = A3 + blockIdx.z * zsA;
    const __nv_bfloat16* Bb = B3 + blockIdx.z * zsB;
    uint32_t sbase = smem_u32(sm);
    int nch = K3 / 64;

    auto issue = [&](int s, int k0) {
#pragma unroll
        for (int i = 0; i < 4; ++i) {
            int e = tid + i * 256;
            int row = e >> 3, seg = e & 7;
            uint32_t da = sbase + (uint32_t)(s * 2 * 128 * LDP + row * LDP + seg * 8) * 2;
            CPA(da, Ab + (size_t)(m0 + row) * lda3 + k0 + seg * 8, 16);
            int brow = o0 + row;
            int srow = brow < Nvalid ? brow : (Nvalid - 1);
            uint32_t db = sbase + (uint32_t)((s * 2 + 1) * 128 * LDP + row * LDP + seg * 8) * 2;
            CPA(db, Bb + (size_t)srow * ldb3 + k0 + seg * 8, brow < Nvalid ? 16 : 0);
        }
        CPA_COMMIT();
    };

    float acc[2][8][4] = {};
    issue(0, 0);
    for (int ch = 0; ch < nch; ++ch) {
        if (ch + 1 < nch) { issue((ch + 1) & 1, (ch + 1) * 64); CPA_WAIT1(); }
        else              { CPA_WAIT0(); }
        __syncthreads();
        const __nv_bfloat16 (*As)[LDP] =
            (const __nv_bfloat16(*)[LDP])(sm + (ch & 1) * 2 * 128 * LDP);
        const __nv_bfloat16 (*Bs)[LDP] = As + 128;
#pragma unroll
        for (int kk = 0; kk < 64; kk += 16) {
            uint32_t af[2][4], bfr[8][2];
#pragma unroll
            for (int mi = 0; mi < 2; ++mi) {
                const __nv_bfloat16* pa = &As[wr * 32 + mi * 16 + gr][kk + tg * 2];
                af[mi][0] = *(const uint32_t*)pa;
                af[mi][1] = *(const uint32_t*)(pa + 8 * LDP);
                af[mi][2] = *(const uint32_t*)(pa + 8);
                af[mi][3] = *(const uint32_t*)(pa + 8 * LDP + 8);
            }
#pragma unroll
            for (int ni = 0; ni < 8; ++ni) {
                const __nv_bfloat16* pb = &Bs[wc * 64 + ni * 8 + gr][kk + tg * 2];
                bfr[ni][0] = *(const uint32_t*)pb;
                bfr[ni][1] = *(const uint32_t*)(pb + 8);
            }
#pragma unroll
            for (int mi = 0; mi < 2; ++mi)
#pragma unroll
                for (int ni = 0; ni < 8; ++ni)
                    mma16816(acc[mi][ni], af[mi], bfr[ni]);
        }
        __syncthreads();
    }

    float* outb = out + blockIdx.z * zsO;
#pragma unroll
    for (int mi = 0; mi < 2; ++mi) {
        int mA = m0 + wr * 32 + mi * 16 + gr;
#pragma unroll
        for (int ni = 0; ni < 8; ++ni) {
            int o = o0 + wc * 64 + ni * 8 + tg * 2;
            if (o < Nvalid) {
                float u0 = acc[mi][ni][0], u1 = acc[mi][ni][1];
                float u2 = acc[mi][ni][2], u3 = acc[mi][ni][3];
                float b0 = bias ? bias[o] : 0.f, b1 = bias ? bias[o + 1] : 0.f;
                u0 += b0; u1 += b1; u2 += b0; u3 += b1;
                if (act) {
                    u0 = u0 > 0.f ? u0 : 0.2f * u0;
                    u1 = u1 > 0.f ? u1 : 0.2f * u1;
                    u2 = u2 > 0.f ? u2 : 0.2f * u2;
                    u3 = u3 > 0.f ? u3 : 0.2f * u3;
                }
                *(float2*)(outb + (size_t)mA * ldo + o)       = make_float2(u0, u1);
                *(float2*)(outb + (size_t)(mA + 8) * ldo + o) = make_float2(u2, u3);
            }
        }
    }
}

// =================== fused pairwise + top-K, register lists (v2) ===================
// 8 warps; warp w owns rows [w*16, w*16+16). Per 128-col tile: 16 m16n8k16 MMAs
// per k-step; each thread keeps 2 register top-20 lists (rows gr, gr+8).
// A strip (128 x K3) persistent in smem; B chunks cp.async double-buffered.
#define KNN_SMEM_MAX 137216
__global__ void __launch_bounds__(256, 1)
knn_fused2(const __nv_bfloat16* __restrict__ A3, const __nv_bfloat16* __restrict__ B3,
           int K3, const float* __restrict__ xx, int* __restrict__ idxout) {
    extern __shared__ __nv_bfloat16 sm[];
    int tid = threadIdx.x;
    int w = tid >> 5, lane = tid & 31;
    int gr = lane >> 2, tg = lane & 3;
    int b = blockIdx.y, m0 = blockIdx.x * 128;

    int lda = K3 + 8;
    __nv_bfloat16* As = sm;                       // 128 * lda
    __nv_bfloat16* Bsb = sm + 128 * lda;          // 2 stages * 128 * LDP
    uint32_t bbase = smem_u32(Bsb);

    const __nv_bfloat16* Ab = A3 + ((size_t)b * NN + m0) * K3;
    const __nv_bfloat16* Bb = B3 + (size_t)b * NN * K3;
    const float* xxb = xx + (size_t)b * NN;

    // load A strip once (vectorized, coalesced)
    int nvecA = 128 * (K3 >> 3);
    for (int v = tid; v < nvecA; v += 256) {
        int row = v / (K3 >> 3), seg = v % (K3 >> 3);
        *(uint4*)&As[row * lda + seg * 8] = *((const uint4*)(Ab + (size_t)row * K3) + seg);
    }
    __syncthreads();

    int r0 = w * 16 + gr;                          // local row of list0; list1 = r0+8
    float xr0 = xxb[m0 + r0], xr1 = xxb[m0 + r0 + 8];

    float key0[KNN], key1[KNN];
    int   ki0[KNN], ki1[KNN];
#pragma unroll
    for (int j = 0; j < KNN; ++j) {
        key0[j] = FLT_MAX; key1[j] = FLT_MAX; ki0[j] = 0; ki1[j] = 0;
    }

    int nch = K3 / 64;
    auto issueB = [&](int s, int c0, int k0) {
#pragma unroll
        for (int i = 0; i < 4; ++i) {
            int e = tid + i * 256;
            int row = e >> 3, seg = e & 7;
            uint32_t db = bbase + (uint32_t)(s * 128 * LDP + row * LDP + seg * 8) * 2;
            CPA(db, Bb + (size_t)(c0 + row) * K3 + k0 + seg * 8, 16);
        }
        CPA_COMMIT();
    };

    for (int ct = 0; ct < 16; ++ct) {
        int c0 = ct * 128;
        float acc[16][4] = {};
        issueB(0, c0, 0);
        for (int ch = 0; ch < nch; ++ch) {
            if (ch + 1 < nch) { issueB((ch + 1) & 1, c0, (ch + 1) * 64); CPA_WAIT1(); }
            else              { CPA_WAIT0(); }
            __syncthreads();
            const __nv_bfloat16* Bs = Bsb + (ch & 1) * 128 * LDP;
#pragma unroll
            for (int kk = 0; kk < 64; kk += 16) {
                uint32_t af[4];
                const __nv_bfloat16* pa = &As[(size_t)r0 * lda + ch * 64 + kk + tg * 2];
                af[0] = *(const uint32_t*)pa;
                af[1] = *(const uint32_t*)(pa + 8 * lda);
                af[2] = *(const uint32_t*)(pa + 8);
                af[3] = *(const uint32_t*)(pa + 8 * lda + 8);
#pragma unroll
                for (int ni = 0; ni < 16; ++ni) {
                    uint32_t bfr[2];
                    const __nv_bfloat16* pb = &Bs[(ni * 8 + gr) * LDP + kk + tg * 2];
                    bfr[0] = *(const uint32_t*)pb;
                    bfr[1] = *(const uint32_t*)(pb + 8);
                    mma16816(acc[ni], af, bfr);
                }
            }
            __syncthreads();
        }
        // epilogue: d2 values -> register top-20 lists (cols ascending)
#pragma unroll
        for (int ni = 0; ni < 16; ++ni) {
            int c = c0 + ni * 8 + tg * 2;
            float xc0 = xxb[c], xc1 = xxb[c + 1];
            float v00 = xr0 - 2.f * acc[ni][0] + xc0;
            float v01 = xr0 - 2.f * acc[ni][1] + xc1;
            float v10 = xr1 - 2.f * acc[ni][2] + xc0;
            float v11 = xr1 - 2.f * acc[ni][3] + xc1;
            INS(key0, ki0, v00, c);
            INS(key0, ki0, v01, c + 1);
            INS(key1, ki1, v10, c);
            INS(key1, ki1, v11, c + 1);
        }
    }
    __syncthreads();   // done with As/Bs; reuse smem for list merge

    float* sk = (float*)sm;                        // [2][256][KNN]
    int*   sx = (int*)(sm + 2 * 256 * KNN * 2);    // after 40960 B of floats
#pragma unroll
    for (int j = 0; j < KNN; ++j) {
        sk[tid * KNN + j]          = key0[j];
        sx[tid * KNN + j]          = ki0[j];
        sk[(256 + tid) * KNN + j]  = key1[j];
        sx[(256 + tid) * KNN + j]  = ki1[j];
    }
    __syncthreads();

    // merge 4 sorted lists per row (tie -> lowest index)
    if (tid < 128) {
        int mw = tid >> 4, rr = tid & 15;
        int g = rr & 7, lsel = rr >> 3;
        int base0 = (lsel * 256 + mw * 32 + g * 4 + 0) * KNN;
        int base1 = (lsel * 256 + mw * 32 + g * 4 + 1) * KNN;
        int base2 = (lsel * 256 + mw * 32 + g * 4 + 2) * KNN;
        int base3 = (lsel * 256 + mw * 32 + g * 4 + 3) * KNN;
        int p0 = 0, p1 = 0, p2 = 0, p3 = 0;
        size_t ob = ((size_t)b * NN + m0 + tid) * KNN;
#pragma unroll
        for (int k = 0; k < KNN; ++k) {
            float v0 = sk[base0 + p0], v1 = sk[base1 + p1];
            float v2 = sk[base2 + p2], v3 = sk[base3 + p3];
            int   x0 = sx[base0 + p0], x1 = sx[base1 + p1];
            int   x2 = sx[base2 + p2], x3 = sx[base3 + p3];
            bool aA = (v0 < v1) || (v0 == v1 && x0 < x1);
            float vA = aA ? v0 : v1; int xA = aA ? x0 : x1;
            bool aB = (v2 < v3) || (v2 == v3 && x2 < x3);
            float vB = aB ? v2 : v3; int xB = aB ? x2 : x3;
            bool aF = (vA < vB) || (vA == vB && xA < xB);
            int xw = aF ? xA : xB;
            idxout[ob + k] = xw;
            if (aF) { if (aA) ++p0; else ++p1; }
            else    { if (aB) ++p2; else ++p3; }
        }
    }
}

// =================== small kernels ===================
__global__ void xx_kernel(const float* __restrict__ X, int ldx, int C,
                          float* __restrict__ xx) {
    int i = blockIdx.x * blockDim.x + threadIdx.x;
    if (i >= BB * NN) return;
    const float* p = X + (size_t)i * ldx;
    float s = 0.f;
    for (int c = 0; c < C; ++c) { float v = p[c]; s += v * v; }
    xx[i] = s;
}

// h[n,o] = leaky(max_k y[j_k,o] - y[n,o] + c[n,o])   (leaky/max commute)
__global__ void edgemax4(const float* __restrict__ yc, const int* __restrict__ idx,
                         float* __restrict__ out, int O, int ldo) {
    __shared__ int sid[KNN];
    int b = blockIdx.y, n = blockIdx.x;
    int t = threadIdx.x;                      // 0 .. O/4-1
    for (int i = t; i < KNN; i += blockDim.x)
        sid[i] = idx[((size_t)b * NN + n) * KNN + i];
    __syncthreads();
    size_t mbase = (size_t)b * NN;
    int ld2 = 2 * O;
    float4 m = make_float4(-FLT_MAX, -FLT_MAX, -FLT_MAX, -FLT_MAX);
#pragma unroll
    for (int k = 0; k < KNN; ++k) {
        float4 yn = *(const float4*)(yc + (mbase + sid[k]) * ld2 + 4 * t);
        m.x = fmaxf(m.x, yn.x); m.y = fmaxf(m.y, yn.y);
        m.z = fmaxf(m.z, yn.z); m.w = fmaxf(m.w, yn.w);
    }
    const float* prow = yc + (mbase + n) * ld2 + 4 * t;
    float4 ycn = *(const float4*)prow;
    float4 ccn = *(const float4*)(prow + O);
    float v0 = m.x - ycn.x + ccn.x;
    float v1 = m.y - ycn.y + ccn.y;
    float v2 = m.z - ycn.z + ccn.z;
    float v3 = m.w - ycn.w + ccn.w;
    v0 = v0 > 0.f ? v0 : 0.2f * v0;
    v1 = v1 > 0.f ? v1 : 0.2f * v1;
    v2 = v2 > 0.f ? v2 : 0.2f * v2;
    v3 = v3 > 0.f ? v3 : 0.2f * v3;
    *(float4*)(out + (mbase + n) * ldo + 4 * t) = make_float4(v0, v1, v2, v3);
}

__global__ void maxpool(const float* __restrict__ tmp, float* __restrict__ out) {
    int b = blockIdx.y;
    int f = blockIdx.x * blockDim.x + threadIdx.x;
    const float* p = tmp + (size_t)b * NN * 1024 + f;
    float m = -FLT_MAX;
    for (int n = 0; n < NN; ++n) m = fmaxf(m, p[(size_t)n * 1024]);
    out[b * 1024 + f] = m;
}

// =================== launch ===================
extern "C" void kernel_launch(void* const* d_in, const int* in_sizes, int n_in,
                              void* d_out, int out_size) {
    const float* x     = (const float*)d_in[0];
    const float* Wl[4] = {(const float*)d_in[1], (const float*)d_in[3],
                          (const float*)d_in[5], (const float*)d_in[7]};
    const float* bl[4] = {(const float*)d_in[2], (const float*)d_in[4],
                          (const float*)d_in[6], (const float*)d_in[8]};
    const float* Wf = (const float*)d_in[9];
    const float* bf = (const float*)d_in[10];
    float* out = (float*)d_out;

    float *p_xx, *p_yc, *p_hcat, *p_tmp, *p_bias2;
    __nv_bfloat16 *p_a3, *p_b3, *p_bf3, *p_w3;
    int* p_idx;
    cudaGetSymbolAddress((void**)&p_xx,    g_xx);
    cudaGetSymbolAddress((void**)&p_idx,   g_idx);
    cudaGetSymbolAddress((void**)&p_yc,    g_yc);
    cudaGetSymbolAddress((void**)&p_hcat,  g_hcat);
    cudaGetSymbolAddress((void**)&p_tmp,   g_tmp);
    cudaGetSymbolAddress((void**)&p_bias2, g_bias2);
    cudaGetSymbolAddress((void**)&p_a3,    g_a3);
    cudaGetSymbolAddress((void**)&p_b3,    g_b3);
    cudaGetSymbolAddress((void**)&p_bf3,   g_bf3);
    cudaGetSymbolAddress((void**)&p_w3,    g_w3);

    cudaFuncSetAttribute(mma_gemm, cudaFuncAttributeMaxDynamicSharedMemorySize,
                         MMA_SMEM);
    cudaFuncSetAttribute(knn_fused2, cudaFuncAttributeMaxDynamicSharedMemorySize,
                         KNN_SMEM_MAX);

    const int Cs[4]  = {3, 64, 64, 128};
    const int Os[4]  = {64, 64, 128, 256};
    const int off[4] = {0, 64, 128, 256};

    const float* Xin = x;
    int ldx = 3;
    for (int l = 0; l < 4; ++l) {
        int C = Cs[l], O = Os[l];
        int K3 = ((3 * C + 63) / 64) * 64;     // 64, 192, 192, 384
        int ksm = 128 * (K3 + 8) * 2 + 2 * 128 * LDP * 2;
        if (ksm < 81920 + 256) ksm = 81920 + 256;   // list-merge area floor

        xx_kernel<<<(BB * NN + 255) / 256, 256>>>(Xin, ldx, C, p_xx);
        convAB_kernel<<<dim3((K3 + 255) / 256, BB * NN), 256>>>(
            Xin, ldx, C, p_a3, p_b3, K3);
        // fused pairwise distances + exact top-20 (no d2 matrix, register lists)
        knn_fused2<<<dim3(16, BB), 256, ksm>>>(p_a3, p_b3, K3, p_xx, p_idx);
        // combined yc = X * [Wy|Wc]^T + [0|b]
        convB_kernel<<<dim3((K3 + 255) / 256, O), 256>>>(Wl[l], 2 * C, C, p_w3, K3);
        convB_kernel<<<dim3((K3 + 255) / 256, O), 256>>>(Wl[l] + C, 2 * C, C,
                                                         p_w3 + (size_t)O * K3, K3);
        biascat<<<1, 512>>>(bl[l], p_bias2, O);
        mma_gemm<<<dim3((2 * O + 127) / 128, (BB * NN) / 128, 1), 256, MMA_SMEM>>>(
            p_a3, K3, 0, p_w3, K3, 0, 2 * O, K3,
            p_yc, 2 * O, 0, p_bias2, 0);
        edgemax4<<<dim3(NN, BB), O / 4>>>(p_yc, p_idx, p_hcat + off[l], O, 512);
        Xin = p_hcat + off[l];
        ldx = 512;
    }
    // final 512 -> 1024 linear + leaky, then max over N
    convA_kernel<<<dim3(1536 / 256, BB * NN), 256>>>(p_hcat, 512, 512, p_a3, 1536);
    convB_kernel<<<dim3(1536 / 256, 1024), 256>>>(Wf, 512, 512, p_bf3, 1536);
    mma_gemm<<<dim3(1024 / 128, (BB * NN) / 128, 1), 256, MMA_SMEM>>>(
        p_a3, 1536, 0, p_bf3, 1536, 0, 1024, 1536,
        p_tmp, 1024, 0, bf, 1);
    maxpool<<<dim3(1024 / 256, BB), 256>>>(p_tmp, out);
}

// round 8
// speedup vs baseline: 1.1253x; 1.1253x over previous
#include <cuda_runtime.h>
#include <cuda_bf16.h>
#include <float.h>
#include <math.h>
#include <cstdint>

#define BB  8
#define NN  2048
#define KNN 20

// ---------------- scratch (device globals; no allocations) ----------------
__device__ __align__(16) float g_d2[(size_t)NN * NN];          // ONE batch (L2-resident)
__device__ __align__(16) float g_xx[BB * NN];
__device__ __align__(16) int   g_idx[BB * NN * KNN];
__device__ __align__(16) float g_yc[(size_t)BB * NN * 512];    // y | c combined
__device__ __align__(16) float g_hcat[(size_t)BB * NN * 512];
__device__ __align__(16) float g_tmp[(size_t)BB * NN * 1024];
__device__ __align__(16) float g_bias2[512];
__device__ __align__(16) __nv_bfloat16 g_a3[(size_t)BB * NN * 1536];  // split A (h|l|h)
__device__ __align__(16) __nv_bfloat16 g_b3[(size_t)BB * NN * 384];   // split B (h|h|l)
__device__ __align__(16) __nv_bfloat16 g_bf3[1024 * 1536];            // split Wf
__device__ __align__(16) __nv_bfloat16 g_w3[512 * 384];               // split layer W (y|c)

// =================== split-precision conversion kernels ===================
// fused A+B split for X: one read, writes a3 (h|l|h) and b3 (h|h|l)
__global__ void convAB_kernel(const float* __restrict__ in, int ld, int C,
                              __nv_bfloat16* __restrict__ a3,
                              __nv_bfloat16* __restrict__ b3, int K3) {
    int r = blockIdx.y;
    int c = blockIdx.x * 256 + threadIdx.x;
    if (c >= K3) return;
    size_t ro = (size_t)r * K3;
    if (c < C) {
        float xv = in[(size_t)r * ld + c];
        __nv_bfloat16 h = __float2bfloat16(xv);
        __nv_bfloat16 l = __float2bfloat16(xv - __bfloat162float(h));
        a3[ro + c] = h; a3[ro + C + c] = l; a3[ro + 2 * C + c] = h;
        b3[ro + c] = h; b3[ro + C + c] = h; b3[ro + 2 * C + c] = l;
    } else if (c >= 3 * C) {
        __nv_bfloat16 z = __float2bfloat16(0.f);
        a3[ro + c] = z; b3[ro + c] = z;
    }
}
__global__ void convA_kernel(const float* __restrict__ in, int ld, int C,
                             __nv_bfloat16* __restrict__ out, int K3) {
    int r = blockIdx.y;
    int c = blockIdx.x * 256 + threadIdx.x;
    if (c >= K3) return;
    size_t ro = (size_t)r * K3;
    if (c < C) {
        float xv = in[(size_t)r * ld + c];
        __nv_bfloat16 h = __float2bfloat16(xv);
        __nv_bfloat16 l = __float2bfloat16(xv - __bfloat162float(h));
        out[ro + c] = h; out[ro + C + c] = l; out[ro + 2 * C + c] = h;
    } else if (c >= 3 * C) {
        out[ro + c] = __float2bfloat16(0.f);
    }
}
__global__ void convB_kernel(const float* __restrict__ in, int ld, int C,
                             __nv_bfloat16* __restrict__ out, int K3) {
    int r = blockIdx.y;
    int c = blockIdx.x * 256 + threadIdx.x;
    if (c >= K3) return;
    size_t ro = (size_t)r * K3;
    if (c < C) {
        float xv = in[(size_t)r * ld + c];
        __nv_bfloat16 h = __float2bfloat16(xv);
        __nv_bfloat16 l = __float2bfloat16(xv - __bfloat162float(h));
        out[ro + c] = h; out[ro + C + c] = h; out[ro + 2 * C + c] = l;
    } else if (c >= 3 * C) {
        out[ro + c] = __float2bfloat16(0.f);
    }
}
__global__ void biascat(const float* __restrict__ bl, float* __restrict__ out, int O) {
    int i = threadIdx.x;
    if (i < O) out[i] = 0.f;
    else if (i < 2 * O) out[i] = bl[i - O];
}

#define LDP 72   // padded k-stride (bf16) -> conflict-free fragment loads

__device__ __forceinline__ void mma16816(float* d, const uint32_t* a, const uint32_t* b) {
    asm volatile(
        "mma.sync.aligned.m16n8k16.row.col.f32.bf16.bf16.f32 "
        "{%0,%1,%2,%3}, {%4,%5,%6,%7}, {%8,%9}, {%0,%1,%2,%3};"
        : "+f"(d[0]), "+f"(d[1]), "+f"(d[2]), "+f"(d[3])
        : "r"(a[0]), "r"(a[1]), "r"(a[2]), "r"(a[3]), "r"(b[0]), "r"(b[1]));
}
__device__ __forceinline__ uint32_t smem_u32(const void* p) {
    uint32_t a;
    asm("{ .reg .u64 t; cvta.to.shared.u64 t, %1; cvt.u32.u64 %0, t; }" : "=r"(a) : "l"(p));
    return a;
}
#define CPA(dst, src, n) \
    asm volatile("cp.async.cg.shared.global [%0], [%1], 16, %2;" \
                 :: "r"(dst), "l"(src), "r"(n))
#define CPA_COMMIT() asm volatile("cp.async.commit_group;" ::: "memory")
#define CPA_WAIT1()  asm volatile("cp.async.wait_group 1;" ::: "memory")
#define CPA_WAIT0()  asm volatile("cp.async.wait_group 0;" ::: "memory")

#define MMA_SMEM (2 * 2 * 128 * LDP * 2)   // 2 stages x (A,B) x 128xLDP bf16

// =================== cp.async-pipelined mma.sync GEMM, 128x128 tile ===============
// mode 0: out[m][o] = acc + bias[o]  (leaky if act)
// mode 1: out[m][o] = xx[m] - 2*acc + xx[o]
__global__ void __launch_bounds__(256)
mma_gemm(const __nv_bfloat16* __restrict__ A3, int lda3,
         const __nv_bfloat16* __restrict__ B3, int ldb3,
         int Nvalid, int K3,
         float* __restrict__ out, int ldo,
         const float* __restrict__ bias, int act,
         int mode, const float* __restrict__ xx) {
    extern __shared__ __nv_bfloat16 sm[];
    int tid = threadIdx.x;
    int wid = tid >> 5, lane = tid & 31;
    int wr = wid & 3, wc = wid >> 2;
    int gr = lane >> 2, tg = lane & 3;

    int m0 = blockIdx.y * 128, o0 = blockIdx.x * 128;
    uint32_t sbase = smem_u32(sm);
    int nch = K3 / 64;

    auto issue = [&](int s, int k0) {
#pragma unroll
        for (int i = 0; i < 4; ++i) {
            int e = tid + i * 256;
            int row = e >> 3, seg = e & 7;
            uint32_t da = sbase + (uint32_t)(s * 2 * 128 * LDP + row * LDP + seg * 8) * 2;
            CPA(da, A3 + (size_t)(m0 + row) * lda3 + k0 + seg * 8, 16);
            int brow = o0 + row;
            int srow = brow < Nvalid ? brow : (Nvalid - 1);
            uint32_t db = sbase + (uint32_t)((s * 2 + 1) * 128 * LDP + row * LDP + seg * 8) * 2;
            CPA(db, B3 + (size_t)srow * ldb3 + k0 + seg * 8, brow < Nvalid ? 16 : 0);
        }
        CPA_COMMIT();
    };

    float acc[2][8][4] = {};
    issue(0, 0);
    for (int ch = 0; ch < nch; ++ch) {
        if (ch + 1 < nch) { issue((ch + 1) & 1, (ch + 1) * 64); CPA_WAIT1(); }
        else              { CPA_WAIT0(); }
        __syncthreads();
        const __nv_bfloat16 (*As)[LDP] =
            (const __nv_bfloat16(*)[LDP])(sm + (ch & 1) * 2 * 128 * LDP);
        const __nv_bfloat16 (*Bs)[LDP] = As + 128;
#pragma unroll
        for (int kk = 0; kk < 64; kk += 16) {
            uint32_t af[2][4], bfr[8][2];
#pragma unroll
            for (int mi = 0; mi < 2; ++mi) {
                const __nv_bfloat16* pa = &As[wr * 32 + mi * 16 + gr][kk + tg * 2];
                af[mi][0] = *(const uint32_t*)pa;
                af[mi][1] = *(const uint32_t*)(pa + 8 * LDP);
                af[mi][2] = *(const uint32_t*)(pa + 8);
                af[mi][3] = *(const uint32_t*)(pa + 8 * LDP + 8);
            }
#pragma unroll
            for (int ni = 0; ni < 8; ++ni) {
                const __nv_bfloat16* pb = &Bs[wc * 64 + ni * 8 + gr][kk + tg * 2];
                bfr[ni][0] = *(const uint32_t*)pb;
                bfr[ni][1] = *(const uint32_t*)(pb + 8);
            }
#pragma unroll
            for (int mi = 0; mi < 2; ++mi)
#pragma unroll
                for (int ni = 0; ni < 8; ++ni)
                    mma16816(acc[mi][ni], af[mi], bfr[ni]);
        }
        __syncthreads();
    }

#pragma unroll
    for (int mi = 0; mi < 2; ++mi) {
        int mA = m0 + wr * 32 + mi * 16 + gr;
        float xrA = 0.f, xrB = 0.f;
        if (mode == 1) { xrA = xx[mA]; xrB = xx[mA + 8]; }
#pragma unroll
        for (int ni = 0; ni < 8; ++ni) {
            int o = o0 + wc * 64 + ni * 8 + tg * 2;
            if (o < Nvalid) {
                float u0 = acc[mi][ni][0], u1 = acc[mi][ni][1];
                float u2 = acc[mi][ni][2], u3 = acc[mi][ni][3];
                if (mode == 0) {
                    float b0 = bias ? bias[o] : 0.f, b1 = bias ? bias[o + 1] : 0.f;
                    u0 += b0; u1 += b1; u2 += b0; u3 += b1;
                    if (act) {
                        u0 = u0 > 0.f ? u0 : 0.2f * u0;
                        u1 = u1 > 0.f ? u1 : 0.2f * u1;
                        u2 = u2 > 0.f ? u2 : 0.2f * u2;
                        u3 = u3 > 0.f ? u3 : 0.2f * u3;
                    }
                } else {
                    float xc0 = xx[o], xc1 = xx[o + 1];
                    u0 = xrA - 2.f * u0 + xc0; u1 = xrA - 2.f * u1 + xc1;
                    u2 = xrB - 2.f * u2 + xc0; u3 = xrB - 2.f * u3 + xc1;
                }
                *(float2*)(out + (size_t)mA * ldo + o)       = make_float2(u0, u1);
                *(float2*)(out + (size_t)(mA + 8) * ldo + o) = make_float2(u2, u3);
            }
        }
    }
}

// =================== warp-per-row top-K, float4 scan (single batch) ===============
__global__ void topk_warp(const float* __restrict__ d2, int* __restrict__ idx) {
    __shared__ float sk[8][32 * KNN];
    __shared__ int   si[8][32 * KNN];
    int w = threadIdx.x >> 5, lane = threadIdx.x & 31;
    int row = blockIdx.x * 8 + w;                 // 0 .. NN-1
    const float* r = d2 + (size_t)row * NN;
    float key[KNN]; int ki[KNN];
#pragma unroll
    for (int j = 0; j < KNN; ++j) { key[j] = FLT_MAX; ki[j] = 0; }

#pragma unroll 2
    for (int j = 0; j < 16; ++j) {
        int e0 = 4 * (j * 32 + lane);
        float4 v4 = *(const float4*)(r + e0);
        float vmin = fminf(fminf(v4.x, v4.y), fminf(v4.z, v4.w));
        if (vmin < key[KNN - 1]) {
            float vals[4] = {v4.x, v4.y, v4.z, v4.w};
#pragma unroll
            for (int q = 0; q < 4; ++q) {
                float cv = vals[q];
                if (cv < key[KNN - 1]) {
                    int ci = e0 + q;
#pragma unroll
                    for (int jj = 0; jj < KNN; ++jj) {
                        if (cv < key[jj]) {
                            float tv = key[jj]; key[jj] = cv; cv = tv;
                            int ti = ki[jj]; ki[jj] = ci; ci = ti;
                        }
                    }
                }
            }
        }
    }
#pragma unroll
    for (int j = 0; j < KNN; ++j) {
        sk[w][lane * KNN + j] = key[j];
        si[w][lane * KNN + j] = ki[j];
    }
    __syncwarp();
    int h = 0;
    float hv = key[0]; int hi = ki[0];
    for (int k = 0; k < KNN; ++k) {
        unsigned ub = __float_as_uint(hv);
        ub = (ub & 0x80000000u) ? ~ub : (ub | 0x80000000u);
        unsigned long long pk = ((unsigned long long)ub << 32) | (unsigned)lane;
#pragma unroll
        for (int off = 16; off; off >>= 1) {
            unsigned long long o = __shfl_xor_sync(0xffffffffu, pk, off);
            pk = (o < pk) ? o : pk;
        }
        int src = (int)(pk & 31u);
        int widx = __shfl_sync(0xffffffffu, hi, src);
        if (lane == 0) idx[(size_t)row * KNN + k] = widx;
        if (lane == src) {
            ++h;
            hv = (h < KNN) ? sk[w][lane * KNN + h] : FLT_MAX;
            hi = (h < KNN) ? si[w][lane * KNN + h] : 0;
        }
    }
}

// =================== small kernels ===================
__global__ void xx_kernel(const float* __restrict__ X, int ldx, int C,
                          float* __restrict__ xx) {
    int i = blockIdx.x * blockDim.x + threadIdx.x;
    if (i >= BB * NN) return;
    const float* p = X + (size_t)i * ldx;
    float s = 0.f;
    for (int c = 0; c < C; ++c) { float v = p[c]; s += v * v; }
    xx[i] = s;
}

// h[n,o] = leaky(max_k y[j_k,o] - y[n,o] + c[n,o])   (leaky/max commute)
__global__ void edgemax4(const float* __restrict__ yc, const int* __restrict__ idx,
                         float* __restrict__ out, int O, int ldo) {
    __shared__ int sid[KNN];
    int b = blockIdx.y, n = blockIdx.x;
    int t = threadIdx.x;                      // 0 .. O/4-1
    for (int i = t; i < KNN; i += blockDim.x)
        sid[i] = idx[((size_t)b * NN + n) * KNN + i];
    __syncthreads();
    size_t mbase = (size_t)b * NN;
    int ld2 = 2 * O;
    float4 m = make_float4(-FLT_MAX, -FLT_MAX, -FLT_MAX, -FLT_MAX);
#pragma unroll
    for (int k = 0; k < KNN; ++k) {
        float4 yn = *(const float4*)(yc + (mbase + sid[k]) * ld2 + 4 * t);
        m.x = fmaxf(m.x, yn.x); m.y = fmaxf(m.y, yn.y);
        m.z = fmaxf(m.z, yn.z); m.w = fmaxf(m.w, yn.w);
    }
    const float* prow = yc + (mbase + n) * ld2 + 4 * t;
    float4 ycn = *(const float4*)prow;
    float4 ccn = *(const float4*)(prow + O);
    float v0 = m.x - ycn.x + ccn.x;
    float v1 = m.y - ycn.y + ccn.y;
    float v2 = m.z - ycn.z + ccn.z;
    float v3 = m.w - ycn.w + ccn.w;
    v0 = v0 > 0.f ? v0 : 0.2f * v0;
    v1 = v1 > 0.f ? v1 : 0.2f * v1;
    v2 = v2 > 0.f ? v2 : 0.2f * v2;
    v3 = v3 > 0.f ? v3 : 0.2f * v3;
    *(float4*)(out + (mbase + n) * ldo + 4 * t) = make_float4(v0, v1, v2, v3);
}

__global__ void maxpool(const float* __restrict__ tmp, float* __restrict__ out) {
    int b = blockIdx.y;
    int f = blockIdx.x * blockDim.x + threadIdx.x;
    const float* p = tmp + (size_t)b * NN * 1024 + f;
    float m = -FLT_MAX;
    for (int n = 0; n < NN; ++n) m = fmaxf(m, p[(size_t)n * 1024]);
    out[b * 1024 + f] = m;
}

// =================== launch ===================
extern "C" void kernel_launch(void* const* d_in, const int* in_sizes, int n_in,
                              void* d_out, int out_size) {
    const float* x     = (const float*)d_in[0];
    const float* Wl[4] = {(const float*)d_in[1], (const float*)d_in[3],
                          (const float*)d_in[5], (const float*)d_in[7]};
    const float* bl[4] = {(const float*)d_in[2], (const float*)d_in[4],
                          (const float*)d_in[6], (const float*)d_in[8]};
    const float* Wf = (const float*)d_in[9];
    const float* bf = (const float*)d_in[10];
    float* out = (float*)d_out;

    float *p_d2, *p_xx, *p_yc, *p_hcat, *p_tmp, *p_bias2;
    __nv_bfloat16 *p_a3, *p_b3, *p_bf3, *p_w3;
    int* p_idx;
    cudaGetSymbolAddress((void**)&p_d2,    g_d2);
    cudaGetSymbolAddress((void**)&p_xx,    g_xx);
    cudaGetSymbolAddress((void**)&p_idx,   g_idx);
    cudaGetSymbolAddress((void**)&p_yc,    g_yc);
    cudaGetSymbolAddress((void**)&p_hcat,  g_hcat);
    cudaGetSymbolAddress((void**)&p_tmp,   g_tmp);
    cudaGetSymbolAddress((void**)&p_bias2, g_bias2);
    cudaGetSymbolAddress((void**)&p_a3,    g_a3);
    cudaGetSymbolAddress((void**)&p_b3,    g_b3);
    cudaGetSymbolAddress((void**)&p_bf3,   g_bf3);
    cudaGetSymbolAddress((void**)&p_w3,    g_w3);

    cudaFuncSetAttribute(mma_gemm, cudaFuncAttributeMaxDynamicSharedMemorySize,
                         MMA_SMEM);

    const int Cs[4]  = {3, 64, 64, 128};
    const int Os[4]  = {64, 64, 128, 256};
    const int off[4] = {0, 64, 128, 256};

    const float* Xin = x;
    int ldx = 3;
    for (int l = 0; l < 4; ++l) {
        int C = Cs[l], O = Os[l];
        int K3 = ((3 * C + 63) / 64) * 64;     // 64, 192, 192, 384

        xx_kernel<<<(BB * NN + 255) / 256, 256>>>(Xin, ldx, C, p_xx);
        convAB_kernel<<<dim3((K3 + 255) / 256, BB * NN), 256>>>(
            Xin, ldx, C, p_a3, p_b3, K3);
        // per-batch pairwise -> topk (d2 buffer stays L2-resident, 16.8 MB)
        for (int b = 0; b < BB; ++b) {
            mma_gemm<<<dim3(16, 16), 256, MMA_SMEM>>>(
                p_a3 + (size_t)b * NN * K3, K3,
                p_b3 + (size_t)b * NN * K3, K3,
                NN, K3, p_d2, NN, nullptr, 0, 1, p_xx + (size_t)b * NN);
            topk_warp<<<NN / 8, 256>>>(p_d2, p_idx + (size_t)b * NN * KNN);
        }
        // combined yc = X * [Wy|Wc]^T + [0|b]
        convB_kernel<<<dim3((K3 + 255) / 256, O), 256>>>(Wl[l], 2 * C, C, p_w3, K3);
        convB_kernel<<<dim3((K3 + 255) / 256, O), 256>>>(Wl[l] + C, 2 * C, C,
                                                         p_w3 + (size_t)O * K3, K3);
        biascat<<<1, 512>>>(bl[l], p_bias2, O);
        mma_gemm<<<dim3((2 * O + 127) / 128, (BB * NN) / 128), 256, MMA_SMEM>>>(
            p_a3, K3, p_w3, K3, 2 * O, K3,
            p_yc, 2 * O, p_bias2, 0, 0, nullptr);
        edgemax4<<<dim3(NN, BB), O / 4>>>(p_yc, p_idx, p_hcat + off[l], O, 512);
        Xin = p_hcat + off[l];
        ldx = 512;
    }
    // final 512 -> 1024 linear + leaky, then max over N
    convA_kernel<<<dim3(1536 / 256, BB * NN), 256>>>(p_hcat, 512, 512, p_a3, 1536);
    convB_kernel<<<dim3(1536 / 256, 1024), 256>>>(Wf, 512, 512, p_bf3, 1536);
    mma_gemm<<<dim3(1024 / 128, (BB * NN) / 128), 256, MMA_SMEM>>>(
        p_a3, 1536, p_bf3, 1536, 1024, 1536,
        p_tmp, 1024, bf, 1, 0, nullptr);
    maxpool<<<dim3(1024 / 256, BB), 256>>>(p_tmp, out);
}

// round 9
// speedup vs baseline: 1.7705x; 1.5734x over previous
#include <cuda_runtime.h>
#include <cuda_bf16.h>
#include <float.h>
#include <math.h>
#include <cstdint>

#define BB  8
#define NN  2048
#define KNN 20
#define CAP 96   // candidate cap per row before fallback

// ---------------- scratch (device globals; no allocations) ----------------
__device__ __align__(16) float g_d2[(size_t)BB * NN * NN];
__device__ __align__(16) float g_submin[(size_t)BB * NN * 64];
__device__ __align__(16) float g_xx[BB * NN];
__device__ __align__(16) int   g_idx[BB * NN * KNN];
__device__ __align__(16) float g_yc[(size_t)BB * NN * 512];    // y | c combined
__device__ __align__(16) float g_hcat[(size_t)BB * NN * 512];
__device__ __align__(16) float g_tmp[(size_t)BB * NN * 1024];
__device__ __align__(16) float g_bias2[512];
__device__ __align__(16) __nv_bfloat16 g_a3[(size_t)BB * NN * 1536];  // split A (h|l|h)
__device__ __align__(16) __nv_bfloat16 g_b3[(size_t)BB * NN * 384];   // split B (h|h|l)
__device__ __align__(16) __nv_bfloat16 g_bf3[1024 * 1536];            // split Wf
__device__ __align__(16) __nv_bfloat16 g_w3[512 * 384];               // split layer W (y|c)

// =================== split-precision conversion kernels ===================
__global__ void convAB_kernel(const float* __restrict__ in, int ld, int C,
                              __nv_bfloat16* __restrict__ a3,
                              __nv_bfloat16* __restrict__ b3, int K3) {
    int r = blockIdx.y;
    int c = blockIdx.x * 256 + threadIdx.x;
    if (c >= K3) return;
    size_t ro = (size_t)r * K3;
    if (c < C) {
        float xv = in[(size_t)r * ld + c];
        __nv_bfloat16 h = __float2bfloat16(xv);
        __nv_bfloat16 l = __float2bfloat16(xv - __bfloat162float(h));
        a3[ro + c] = h; a3[ro + C + c] = l; a3[ro + 2 * C + c] = h;
        b3[ro + c] = h; b3[ro + C + c] = h; b3[ro + 2 * C + c] = l;
    } else if (c >= 3 * C) {
        __nv_bfloat16 z = __float2bfloat16(0.f);
        a3[ro + c] = z; b3[ro + c] = z;
    }
}
__global__ void convA_kernel(const float* __restrict__ in, int ld, int C,
                             __nv_bfloat16* __restrict__ out, int K3) {
    int r = blockIdx.y;
    int c = blockIdx.x * 256 + threadIdx.x;
    if (c >= K3) return;
    size_t ro = (size_t)r * K3;
    if (c < C) {
        float xv = in[(size_t)r * ld + c];
        __nv_bfloat16 h = __float2bfloat16(xv);
        __nv_bfloat16 l = __float2bfloat16(xv - __bfloat162float(h));
        out[ro + c] = h; out[ro + C + c] = l; out[ro + 2 * C + c] = h;
    } else if (c >= 3 * C) {
        out[ro + c] = __float2bfloat16(0.f);
    }
}
__global__ void convB_kernel(const float* __restrict__ in, int ld, int C,
                             __nv_bfloat16* __restrict__ out, int K3) {
    int r = blockIdx.y;
    int c = blockIdx.x * 256 + threadIdx.x;
    if (c >= K3) return;
    size_t ro = (size_t)r * K3;
    if (c < C) {
        float xv = in[(size_t)r * ld + c];
        __nv_bfloat16 h = __float2bfloat16(xv);
        __nv_bfloat16 l = __float2bfloat16(xv - __bfloat162float(h));
        out[ro + c] = h; out[ro + C + c] = h; out[ro + 2 * C + c] = l;
    } else if (c >= 3 * C) {
        out[ro + c] = __float2bfloat16(0.f);
    }
}
__global__ void biascat(const float* __restrict__ bl, float* __restrict__ out, int O) {
    int i = threadIdx.x;
    if (i < O) out[i] = 0.f;
    else if (i < 2 * O) out[i] = bl[i - O];
}

#define LDP 72

__device__ __forceinline__ void mma16816(float* d, const uint32_t* a, const uint32_t* b) {
    asm volatile(
        "mma.sync.aligned.m16n8k16.row.col.f32.bf16.bf16.f32 "
        "{%0,%1,%2,%3}, {%4,%5,%6,%7}, {%8,%9}, {%0,%1,%2,%3};"
        : "+f"(d[0]), "+f"(d[1]), "+f"(d[2]), "+f"(d[3])
        : "r"(a[0]), "r"(a[1]), "r"(a[2]), "r"(a[3]), "r"(b[0]), "r"(b[1]));
}
__device__ __forceinline__ uint32_t smem_u32(const void* p) {
    uint32_t a;
    asm("{ .reg .u64 t; cvta.to.shared.u64 t, %1; cvt.u32.u64 %0, t; }" : "=r"(a) : "l"(p));
    return a;
}
__device__ __forceinline__ unsigned mono(float v) {
    unsigned u = __float_as_uint(v);
    return (u & 0x80000000u) ? ~u : (u | 0x80000000u);
}
#define CPA(dst, src, n) \
    asm volatile("cp.async.cg.shared.global [%0], [%1], 16, %2;" \
                 :: "r"(dst), "l"(src), "r"(n))
#define CPA_COMMIT() asm volatile("cp.async.commit_group;" ::: "memory")
#define CPA_WAIT1()  asm volatile("cp.async.wait_group 1;" ::: "memory")
#define CPA_WAIT0()  asm volatile("cp.async.wait_group 0;" ::: "memory")

// register insertion into sorted KNN list (strict < keeps lowest idx on ties)
#define INS(keys, kidx, v, ix) do { \
    if ((v) < keys[KNN - 1]) { \
        float _cv = (v); int _ci = (ix); \
        _Pragma("unroll") \
        for (int _j = 0; _j < KNN; ++_j) { \
            if (_cv < keys[_j]) { \
                float _tv = keys[_j]; keys[_j] = _cv; _cv = _tv; \
                int _ti = kidx[_j]; kidx[_j] = _ci; _ci = _ti; \
            } \
        } \
    } } while (0)

#define MMA_SMEM (2 * 2 * 128 * LDP * 2)

// =================== cp.async-pipelined mma.sync GEMM, 128x128 tile ===============
// mode 0: out[m][o] = acc + bias[o]  (leaky if act)
// mode 1: out[m][o] = xx[m] - 2*acc + xx[o]; also emits 32-col subtile row-mins
__global__ void __launch_bounds__(256)
mma_gemm(const __nv_bfloat16* __restrict__ A3, int lda3, size_t zsA,
         const __nv_bfloat16* __restrict__ B3, int ldb3, size_t zsB,
         int Nvalid, int K3,
         float* __restrict__ out, int ldo, size_t zsO,
         const float* __restrict__ bias, int act,
         int mode, const float* __restrict__ xx, int zsXX,
         float* __restrict__ submin) {
    extern __shared__ __nv_bfloat16 sm[];
    int tid = threadIdx.x;
    int wid = tid >> 5, lane = tid & 31;
    int wr = wid & 3, wc = wid >> 2;
    int gr = lane >> 2, tg = lane & 3;

    int m0 = blockIdx.y * 128, o0 = blockIdx.x * 128;
    const __nv_bfloat16* Ab = A3 + blockIdx.z * zsA;
    const __nv_bfloat16* Bb = B3 + blockIdx.z * zsB;
    uint32_t sbase = smem_u32(sm);
    int nch = K3 / 64;

    auto issue = [&](int s, int k0) {
#pragma unroll
        for (int i = 0; i < 4; ++i) {
            int e = tid + i * 256;
            int row = e >> 3, seg = e & 7;
            uint32_t da = sbase + (uint32_t)(s * 2 * 128 * LDP + row * LDP + seg * 8) * 2;
            CPA(da, Ab + (size_t)(m0 + row) * lda3 + k0 + seg * 8, 16);
            int brow = o0 + row;
            int srow = brow < Nvalid ? brow : (Nvalid - 1);
            uint32_t db = sbase + (uint32_t)((s * 2 + 1) * 128 * LDP + row * LDP + seg * 8) * 2;
            CPA(db, Bb + (size_t)srow * ldb3 + k0 + seg * 8, brow < Nvalid ? 16 : 0);
        }
        CPA_COMMIT();
    };

    float acc[2][8][4] = {};
    issue(0, 0);
    for (int ch = 0; ch < nch; ++ch) {
        if (ch + 1 < nch) { issue((ch + 1) & 1, (ch + 1) * 64); CPA_WAIT1(); }
        else              { CPA_WAIT0(); }
        __syncthreads();
        const __nv_bfloat16 (*As)[LDP] =
            (const __nv_bfloat16(*)[LDP])(sm + (ch & 1) * 2 * 128 * LDP);
        const __nv_bfloat16 (*Bs)[LDP] = As + 128;
#pragma unroll
        for (int kk = 0; kk < 64; kk += 16) {
            uint32_t af[2][4], bfr[8][2];
#pragma unroll
            for (int mi = 0; mi < 2; ++mi) {
                const __nv_bfloat16* pa = &As[wr * 32 + mi * 16 + gr][kk + tg * 2];
                af[mi][0] = *(const uint32_t*)pa;
                af[mi][1] = *(const uint32_t*)(pa + 8 * LDP);
                af[mi][2] = *(const uint32_t*)(pa + 8);
                af[mi][3] = *(const uint32_t*)(pa + 8 * LDP + 8);
            }
#pragma unroll
            for (int ni = 0; ni < 8; ++ni) {
                const __nv_bfloat16* pb = &Bs[wc * 64 + ni * 8 + gr][kk + tg * 2];
                bfr[ni][0] = *(const uint32_t*)pb;
                bfr[ni][1] = *(const uint32_t*)(pb + 8);
            }
#pragma unroll
            for (int mi = 0; mi < 2; ++mi)
#pragma unroll
                for (int ni = 0; ni < 8; ++ni)
                    mma16816(acc[mi][ni], af[mi], bfr[ni]);
        }
        __syncthreads();
    }

    float* outb = out + blockIdx.z * zsO;
    const float* xxb = (mode == 1) ? xx + (size_t)blockIdx.z * zsXX : nullptr;
    float rmn[2][2][2];
#pragma unroll
    for (int i = 0; i < 2; ++i)
#pragma unroll
        for (int j = 0; j < 2; ++j) { rmn[i][j][0] = FLT_MAX; rmn[i][j][1] = FLT_MAX; }

#pragma unroll
    for (int mi = 0; mi < 2; ++mi) {
        int mA = m0 + wr * 32 + mi * 16 + gr;
        float xrA = 0.f, xrB = 0.f;
        if (mode == 1) { xrA = xxb[mA]; xrB = xxb[mA + 8]; }
#pragma unroll
        for (int ni = 0; ni < 8; ++ni) {
            int o = o0 + wc * 64 + ni * 8 + tg * 2;
            if (o < Nvalid) {
                float u0 = acc[mi][ni][0], u1 = acc[mi][ni][1];
                float u2 = acc[mi][ni][2], u3 = acc[mi][ni][3];
                if (mode == 0) {
                    float b0 = bias ? bias[o] : 0.f, b1 = bias ? bias[o + 1] : 0.f;
                    u0 += b0; u1 += b1; u2 += b0; u3 += b1;
                    if (act) {
                        u0 = u0 > 0.f ? u0 : 0.2f * u0;
                        u1 = u1 > 0.f ? u1 : 0.2f * u1;
                        u2 = u2 > 0.f ? u2 : 0.2f * u2;
                        u3 = u3 > 0.f ? u3 : 0.2f * u3;
                    }
                } else {
                    float xc0 = xxb[o], xc1 = xxb[o + 1];
                    u0 = xrA - 2.f * u0 + xc0; u1 = xrA - 2.f * u1 + xc1;
                    u2 = xrB - 2.f * u2 + xc0; u3 = xrB - 2.f * u3 + xc1;
                    int s = ni >> 2;
                    rmn[mi][s][0] = fminf(rmn[mi][s][0], fminf(u0, u1));
                    rmn[mi][s][1] = fminf(rmn[mi][s][1], fminf(u2, u3));
                }
                *(float2*)(outb + (size_t)mA * ldo + o)       = make_float2(u0, u1);
                *(float2*)(outb + (size_t)(mA + 8) * ldo + o) = make_float2(u2, u3);
            }
        }
    }
    if (mode == 1) {
        float* sb = submin + (size_t)blockIdx.z * NN * 64;
#pragma unroll
        for (int mi = 0; mi < 2; ++mi)
#pragma unroll
            for (int s = 0; s < 2; ++s)
#pragma unroll
                for (int rr = 0; rr < 2; ++rr) {
                    float v = rmn[mi][s][rr];
                    v = fminf(v, __shfl_xor_sync(0xffffffffu, v, 1));
                    v = fminf(v, __shfl_xor_sync(0xffffffffu, v, 2));
                    if (tg == 0) {
                        int grow = m0 + wr * 32 + mi * 16 + gr + rr * 8;
                        sb[(size_t)grow * 64 + blockIdx.x * 4 + wc * 2 + s] = v;
                    }
                }
    }
}

// =================== threshold-filter top-K (exact) ===================
// Per warp-row: T = 20th smallest of the 64 subtile mins (valid upper bound on the
// row's 20th distance); collect values <= T (~24 expected); exact (val,idx) select.
// Fallback to full insertion scan if candidates overflow CAP.
__global__ void __launch_bounds__(256)
topk_sel(const float* __restrict__ d2, const float* __restrict__ submin,
         int* __restrict__ idxout) {
    __shared__ unsigned long long fl[8][640];   // cand buffer overlay / fallback lists
    __shared__ int cnt[8];
    int w = threadIdx.x >> 5, lane = threadIdx.x & 31;
    const unsigned FM = 0xffffffffu;
    size_t row = (size_t)blockIdx.x * 8 + w;
    const float* r = d2 + row * NN;

    if (lane == 0) cnt[w] = 0;
    fl[w][lane] = ~0ULL; fl[w][lane + 32] = ~0ULL; fl[w][lane + 64] = ~0ULL;
    __syncwarp();

    // ---- phase 1: T = 20th smallest subtile-min (monotone bits) ----
    unsigned u0 = mono(submin[row * 64 + lane]);
    unsigned u1 = mono(submin[row * 64 + 32 + lane]);
    unsigned T = 0;
#pragma unroll
    for (int k = 0; k < KNN; ++k) {
        unsigned m = u0 < u1 ? u0 : u1;
        unsigned rmv = m;
#pragma unroll
        for (int off = 16; off; off >>= 1) {
            unsigned o = __shfl_xor_sync(FM, rmv, off);
            rmv = o < rmv ? o : rmv;
        }
        T = rmv;
        if (m == rmv) { if (u0 == rmv) u0 = ~0u; else u1 = ~0u; }
    }

    // ---- phase 2: collect candidates <= T ----
    for (int j = 0; j < 16; ++j) {
        int e0 = 4 * (j * 32 + lane);
        float4 v4 = *(const float4*)(r + e0);
        unsigned q0 = mono(v4.x), q1 = mono(v4.y), q2 = mono(v4.z), q3 = mono(v4.w);
        bool h0 = q0 <= T, h1 = q1 <= T, h2 = q2 <= T, h3 = q3 <= T;
        if (__ballot_sync(FM, h0 | h1 | h2 | h3)) {
            if (h0) { int p = atomicAdd(&cnt[w], 1);
                      if (p < CAP) fl[w][p] = ((unsigned long long)q0 << 32) | (unsigned)e0; }
            if (h1) { int p = atomicAdd(&cnt[w], 1);
                      if (p < CAP) fl[w][p] = ((unsigned long long)q1 << 32) | (unsigned)(e0 + 1); }
            if (h2) { int p = atomicAdd(&cnt[w], 1);
                      if (p < CAP) fl[w][p] = ((unsigned long long)q2 << 32) | (unsigned)(e0 + 2); }
            if (h3) { int p = atomicAdd(&cnt[w], 1);
                      if (p < CAP) fl[w][p] = ((unsigned long long)q3 << 32) | (unsigned)(e0 + 3); }
        }
    }
    __syncwarp();

    if (cnt[w] <= CAP) {
        // ---- phase 3: exact select of 20 by (val, idx) ----
        unsigned long long c0 = fl[w][lane], c1 = fl[w][lane + 32], c2 = fl[w][lane + 64];
#pragma unroll
        for (int k = 0; k < KNN; ++k) {
            unsigned long long loc = c0 < c1 ? c0 : c1;
            loc = c2 < loc ? c2 : loc;
            unsigned long long red = loc;
#pragma unroll
            for (int off = 16; off; off >>= 1) {
                unsigned long long o = __shfl_xor_sync(FM, red, off);
                red = o < red ? o : red;
            }
            if (lane == 0) idxout[row * KNN + k] = (int)(red & 0xffffffffu);
            if (loc == red) {
                if (c0 == red) c0 = ~0ULL;
                else if (c1 == red) c1 = ~0ULL;
                else c2 = ~0ULL;
            }
        }
    } else {
        // ---- fallback: proven insertion scan + merge (exact, rare) ----
        float key[KNN]; int ki[KNN];
#pragma unroll
        for (int j = 0; j < KNN; ++j) { key[j] = FLT_MAX; ki[j] = 0; }
        for (int j = 0; j < 16; ++j) {
            int e0 = 4 * (j * 32 + lane);
            float4 v4 = *(const float4*)(r + e0);
            float vmin = fminf(fminf(v4.x, v4.y), fminf(v4.z, v4.w));
            if (vmin < key[KNN - 1]) {
                float vals[4] = {v4.x, v4.y, v4.z, v4.w};
#pragma unroll
                for (int q = 0; q < 4; ++q) INS(key, ki, vals[q], e0 + q);
            }
        }
#pragma unroll
        for (int j = 0; j < KNN; ++j)
            fl[w][lane * KNN + j] = ((unsigned long long)mono(key[j]) << 32) | (unsigned)ki[j];
        __syncwarp();
        int h = 0;
        unsigned long long hv = fl[w][lane * KNN];
#pragma unroll
        for (int k = 0; k < KNN; ++k) {
            unsigned long long red = hv;
#pragma unroll
            for (int off = 16; off; off >>= 1) {
                unsigned long long o = __shfl_xor_sync(FM, red, off);
                red = o < red ? o : red;
            }
            if (lane == 0) idxout[row * KNN + k] = (int)(red & 0xffffffffu);
            if (hv == red) { ++h; hv = (h < KNN) ? fl[w][lane * KNN + h] : ~0ULL; }
        }
    }
}

// =================== small kernels ===================
__global__ void xx_kernel(const float* __restrict__ X, int ldx, int C,
                          float* __restrict__ xx) {
    int i = blockIdx.x * blockDim.x + threadIdx.x;
    if (i >= BB * NN) return;
    const float* p = X + (size_t)i * ldx;
    float s = 0.f;
    for (int c = 0; c < C; ++c) { float v = p[c]; s += v * v; }
    xx[i] = s;
}

// h[n,o] = leaky(max_k y[j_k,o] - y[n,o] + c[n,o])   (leaky/max commute)
__global__ void edgemax4(const float* __restrict__ yc, const int* __restrict__ idx,
                         float* __restrict__ out, int O, int ldo) {
    __shared__ int sid[KNN];
    int b = blockIdx.y, n = blockIdx.x;
    int t = threadIdx.x;
    for (int i = t; i < KNN; i += blockDim.x)
        sid[i] = idx[((size_t)b * NN + n) * KNN + i];
    __syncthreads();
    size_t mbase = (size_t)b * NN;
    int ld2 = 2 * O;
    float4 m = make_float4(-FLT_MAX, -FLT_MAX, -FLT_MAX, -FLT_MAX);
#pragma unroll
    for (int k = 0; k < KNN; ++k) {
        float4 yn = *(const float4*)(yc + (mbase + sid[k]) * ld2 + 4 * t);
        m.x = fmaxf(m.x, yn.x); m.y = fmaxf(m.y, yn.y);
        m.z = fmaxf(m.z, yn.z); m.w = fmaxf(m.w, yn.w);
    }
    const float* prow = yc + (mbase + n) * ld2 + 4 * t;
    float4 ycn = *(const float4*)prow;
    float4 ccn = *(const float4*)(prow + O);
    float v0 = m.x - ycn.x + ccn.x;
    float v1 = m.y - ycn.y + ccn.y;
    float v2 = m.z - ycn.z + ccn.z;
    float v3 = m.w - ycn.w + ccn.w;
    v0 = v0 > 0.f ? v0 : 0.2f * v0;
    v1 = v1 > 0.f ? v1 : 0.2f * v1;
    v2 = v2 > 0.f ? v2 : 0.2f * v2;
    v3 = v3 > 0.f ? v3 : 0.2f * v3;
    *(float4*)(out + (mbase + n) * ldo + 4 * t) = make_float4(v0, v1, v2, v3);
}

__global__ void maxpool(const float* __restrict__ tmp, float* __restrict__ out) {
    int b = blockIdx.y;
    int f = blockIdx.x * blockDim.x + threadIdx.x;
    const float* p = tmp + (size_t)b * NN * 1024 + f;
    float m = -FLT_MAX;
    for (int n = 0; n < NN; ++n) m = fmaxf(m, p[(size_t)n * 1024]);
    out[b * 1024 + f] = m;
}

// =================== launch ===================
extern "C" void kernel_launch(void* const* d_in, const int* in_sizes, int n_in,
                              void* d_out, int out_size) {
    const float* x     = (const float*)d_in[0];
    const float* Wl[4] = {(const float*)d_in[1], (const float*)d_in[3],
                          (const float*)d_in[5], (const float*)d_in[7]};
    const float* bl[4] = {(const float*)d_in[2], (const float*)d_in[4],
                          (const float*)d_in[6], (const float*)d_in[8]};
    const float* Wf = (const float*)d_in[9];
    const float* bf = (const float*)d_in[10];
    float* out = (float*)d_out;

    float *p_d2, *p_sub, *p_xx, *p_yc, *p_hcat, *p_tmp, *p_bias2;
    __nv_bfloat16 *p_a3, *p_b3, *p_bf3, *p_w3;
    int* p_idx;
    cudaGetSymbolAddress((void**)&p_d2,    g_d2);
    cudaGetSymbolAddress((void**)&p_sub,   g_submin);
    cudaGetSymbolAddress((void**)&p_xx,    g_xx);
    cudaGetSymbolAddress((void**)&p_idx,   g_idx);
    cudaGetSymbolAddress((void**)&p_yc,    g_yc);
    cudaGetSymbolAddress((void**)&p_hcat,  g_hcat);
    cudaGetSymbolAddress((void**)&p_tmp,   g_tmp);
    cudaGetSymbolAddress((void**)&p_bias2, g_bias2);
    cudaGetSymbolAddress((void**)&p_a3,    g_a3);
    cudaGetSymbolAddress((void**)&p_b3,    g_b3);
    cudaGetSymbolAddress((void**)&p_bf3,   g_bf3);
    cudaGetSymbolAddress((void**)&p_w3,    g_w3);

    cudaFuncSetAttribute(mma_gemm, cudaFuncAttributeMaxDynamicSharedMemorySize,
                         MMA_SMEM);

    const int Cs[4]  = {3, 64, 64, 128};
    const int Os[4]  = {64, 64, 128, 256};
    const int off[4] = {0, 64, 128, 256};

    const float* Xin = x;
    int ldx = 3;
    for (int l = 0; l < 4; ++l) {
        int C = Cs[l], O = Os[l];
        int K3 = ((3 * C + 63) / 64) * 64;     // 64, 192, 192, 384

        xx_kernel<<<(BB * NN + 255) / 256, 256>>>(Xin, ldx, C, p_xx);
        convAB_kernel<<<dim3((K3 + 255) / 256, BB * NN), 256>>>(
            Xin, ldx, C, p_a3, p_b3, K3);
        // pairwise d2 + subtile mins (batched over z)
        mma_gemm<<<dim3(16, 16, BB), 256, MMA_SMEM>>>(
            p_a3, K3, (size_t)NN * K3, p_b3, K3, (size_t)NN * K3,
            NN, K3, p_d2, NN, (size_t)NN * NN, nullptr, 0, 1, p_xx, NN, p_sub);
        topk_sel<<<(BB * NN) / 8, 256>>>(p_d2, p_sub, p_idx);
        // combined yc = X * [Wy|Wc]^T + [0|b]
        convB_kernel<<<dim3((K3 + 255) / 256, O), 256>>>(Wl[l], 2 * C, C, p_w3, K3);
        convB_kernel<<<dim3((K3 + 255) / 256, O), 256>>>(Wl[l] + C, 2 * C, C,
                                                         p_w3 + (size_t)O * K3, K3);
        biascat<<<1, 512>>>(bl[l], p_bias2, O);
        mma_gemm<<<dim3((2 * O + 127) / 128, (BB * NN) / 128, 1), 256, MMA_SMEM>>>(
            p_a3, K3, 0, p_w3, K3, 0, 2 * O, K3,
            p_yc, 2 * O, 0, p_bias2, 0, 0, nullptr, 0, nullptr);
        edgemax4<<<dim3(NN, BB), O / 4>>>(p_yc, p_idx, p_hcat + off[l], O, 512);
        Xin = p_hcat + off[l];
        ldx = 512;
    }
    // final 512 -> 1024 linear + leaky, then max over N
    convA_kernel<<<dim3(1536 / 256, BB * NN), 256>>>(p_hcat, 512, 512, p_a3, 1536);
    convB_kernel<<<dim3(1536 / 256, 1024), 256>>>(Wf, 512, 512, p_bf3, 1536);
    mma_gemm<<<dim3(1024 / 128, (BB * NN) / 128, 1), 256, MMA_SMEM>>>(
        p_a3, 1536, 0, p_bf3, 1536, 0, 1024, 1536,
        p_tmp, 1024, 0, bf, 1, 0, nullptr, 0, nullptr);
    maxpool<<<dim3(1024 / 256, BB), 256>>>(p_tmp, out);
}

// round 10
// speedup vs baseline: 2.1467x; 1.2125x over previous
#include <cuda_runtime.h>
#include <cuda_bf16.h>
#include <float.h>
#include <math.h>
#include <cstdint>

#define BB  8
#define NN  2048
#define KNN 20
#define CAP 96   // candidate cap per row before fallback

// ---------------- scratch (device globals; no allocations) ----------------
__device__ __align__(16) float g_d2[(size_t)BB * NN * NN];
__device__ __align__(16) float g_submin[(size_t)BB * NN * 64];
__device__ __align__(16) float g_xx[BB * NN];
__device__ __align__(16) int   g_idx[BB * NN * KNN];
__device__ __align__(16) int   g_ov[BB * NN];
__device__ __align__(16) float g_yc[(size_t)BB * NN * 512];    // y | c combined
__device__ __align__(16) float g_hcat[(size_t)BB * NN * 512];
__device__ __align__(16) float g_tmp[(size_t)BB * NN * 1024];
__device__ __align__(16) float g_bias2[512];
__device__ __align__(16) __nv_bfloat16 g_a3[(size_t)BB * NN * 1536];  // split A (h|l|h)
__device__ __align__(16) __nv_bfloat16 g_b3[(size_t)BB * NN * 384];   // split B (h|h|l)
__device__ __align__(16) __nv_bfloat16 g_bf3[1024 * 1536];            // split Wf
__device__ __align__(16) __nv_bfloat16 g_w3[512 * 384];               // split layer W (y|c)

// =================== split-precision conversion kernels ===================
__global__ void convAB_kernel(const float* __restrict__ in, int ld, int C,
                              __nv_bfloat16* __restrict__ a3,
                              __nv_bfloat16* __restrict__ b3, int K3) {
    int r = blockIdx.y;
    int c = blockIdx.x * 256 + threadIdx.x;
    if (c >= K3) return;
    size_t ro = (size_t)r * K3;
    if (c < C) {
        float xv = in[(size_t)r * ld + c];
        __nv_bfloat16 h = __float2bfloat16(xv);
        __nv_bfloat16 l = __float2bfloat16(xv - __bfloat162float(h));
        a3[ro + c] = h; a3[ro + C + c] = l; a3[ro + 2 * C + c] = h;
        b3[ro + c] = h; b3[ro + C + c] = h; b3[ro + 2 * C + c] = l;
    } else if (c >= 3 * C) {
        __nv_bfloat16 z = __float2bfloat16(0.f);
        a3[ro + c] = z; b3[ro + c] = z;
    }
}
__global__ void convA_kernel(const float* __restrict__ in, int ld, int C,
                             __nv_bfloat16* __restrict__ out, int K3) {
    int r = blockIdx.y;
    int c = blockIdx.x * 256 + threadIdx.x;
    if (c >= K3) return;
    size_t ro = (size_t)r * K3;
    if (c < C) {
        float xv = in[(size_t)r * ld + c];
        __nv_bfloat16 h = __float2bfloat16(xv);
        __nv_bfloat16 l = __float2bfloat16(xv - __bfloat162float(h));
        out[ro + c] = h; out[ro + C + c] = l; out[ro + 2 * C + c] = h;
    } else if (c >= 3 * C) {
        out[ro + c] = __float2bfloat16(0.f);
    }
}
__global__ void convB_kernel(const float* __restrict__ in, int ld, int C,
                             __nv_bfloat16* __restrict__ out, int K3) {
    int r = blockIdx.y;
    int c = blockIdx.x * 256 + threadIdx.x;
    if (c >= K3) return;
    size_t ro = (size_t)r * K3;
    if (c < C) {
        float xv = in[(size_t)r * ld + c];
        __nv_bfloat16 h = __float2bfloat16(xv);
        __nv_bfloat16 l = __float2bfloat16(xv - __bfloat162float(h));
        out[ro + c] = h; out[ro + C + c] = h; out[ro + 2 * C + c] = l;
    } else if (c >= 3 * C) {
        out[ro + c] = __float2bfloat16(0.f);
    }
}
__global__ void biascat(const float* __restrict__ bl, float* __restrict__ out, int O) {
    int i = threadIdx.x;
    if (i < O) out[i] = 0.f;
    else if (i < 2 * O) out[i] = bl[i - O];
}

#define LDP 72

__device__ __forceinline__ void mma16816(float* d, const uint32_t* a, const uint32_t* b) {
    asm volatile(
        "mma.sync.aligned.m16n8k16.row.col.f32.bf16.bf16.f32 "
        "{%0,%1,%2,%3}, {%4,%5,%6,%7}, {%8,%9}, {%0,%1,%2,%3};"
        : "+f"(d[0]), "+f"(d[1]), "+f"(d[2]), "+f"(d[3])
        : "r"(a[0]), "r"(a[1]), "r"(a[2]), "r"(a[3]), "r"(b[0]), "r"(b[1]));
}
__device__ __forceinline__ uint32_t smem_u32(const void* p) {
    uint32_t a;
    asm("{ .reg .u64 t; cvta.to.shared.u64 t, %1; cvt.u32.u64 %0, t; }" : "=r"(a) : "l"(p));
    return a;
}
__device__ __forceinline__ unsigned mono(float v) {
    unsigned u = __float_as_uint(v);
    return (u & 0x80000000u) ? ~u : (u | 0x80000000u);
}
#define CPA(dst, src, n) \
    asm volatile("cp.async.cg.shared.global [%0], [%1], 16, %2;" \
                 :: "r"(dst), "l"(src), "r"(n))
#define CPA_COMMIT() asm volatile("cp.async.commit_group;" ::: "memory")
#define CPA_WAIT1()  asm volatile("cp.async.wait_group 1;" ::: "memory")
#define CPA_WAIT0()  asm volatile("cp.async.wait_group 0;" ::: "memory")

// register insertion into sorted KNN list (strict < keeps lowest idx on ties)
#define INS(keys, kidx, v, ix) do { \
    if ((v) < keys[KNN - 1]) { \
        float _cv = (v); int _ci = (ix); \
        _Pragma("unroll") \
        for (int _j = 0; _j < KNN; ++_j) { \
            if (_cv < keys[_j]) { \
                float _tv = keys[_j]; keys[_j] = _cv; _cv = _tv; \
                int _ti = kidx[_j]; kidx[_j] = _ci; _ci = _ti; \
            } \
        } \
    } } while (0)

#define MMA_SMEM (2 * 2 * 128 * LDP * 2)

// =================== cp.async-pipelined mma.sync GEMM, 128x128 tile ===============
// mode 0: out[m][o] = acc + bias[o]  (leaky if act)
// mode 1: out[m][o] = xx[m] - 2*acc + xx[o]; also emits 32-col subtile row-mins
__global__ void __launch_bounds__(256)
mma_gemm(const __nv_bfloat16* __restrict__ A3, int lda3, size_t zsA,
         const __nv_bfloat16* __restrict__ B3, int ldb3, size_t zsB,
         int Nvalid, int K3,
         float* __restrict__ out, int ldo, size_t zsO,
         const float* __restrict__ bias, int act,
         int mode, const float* __restrict__ xx, int zsXX,
         float* __restrict__ submin) {
    extern __shared__ __nv_bfloat16 sm[];
    int tid = threadIdx.x;
    int wid = tid >> 5, lane = tid & 31;
    int wr = wid & 3, wc = wid >> 2;
    int gr = lane >> 2, tg = lane & 3;

    int m0 = blockIdx.y * 128, o0 = blockIdx.x * 128;
    const __nv_bfloat16* Ab = A3 + blockIdx.z * zsA;
    const __nv_bfloat16* Bb = B3 + blockIdx.z * zsB;
    uint32_t sbase = smem_u32(sm);
    int nch = K3 / 64;

    auto issue = [&](int s, int k0) {
#pragma unroll
        for (int i = 0; i < 4; ++i) {
            int e = tid + i * 256;
            int row = e >> 3, seg = e & 7;
            uint32_t da = sbase + (uint32_t)(s * 2 * 128 * LDP + row * LDP + seg * 8) * 2;
            CPA(da, Ab + (size_t)(m0 + row) * lda3 + k0 + seg * 8, 16);
            int brow = o0 + row;
            int srow = brow < Nvalid ? brow : (Nvalid - 1);
            uint32_t db = sbase + (uint32_t)((s * 2 + 1) * 128 * LDP + row * LDP + seg * 8) * 2;
            CPA(db, Bb + (size_t)srow * ldb3 + k0 + seg * 8, brow < Nvalid ? 16 : 0);
        }
        CPA_COMMIT();
    };

    float acc[2][8][4] = {};
    issue(0, 0);
    for (int ch = 0; ch < nch; ++ch) {
        if (ch + 1 < nch) { issue((ch + 1) & 1, (ch + 1) * 64); CPA_WAIT1(); }
        else              { CPA_WAIT0(); }
        __syncthreads();
        const __nv_bfloat16 (*As)[LDP] =
            (const __nv_bfloat16(*)[LDP])(sm + (ch & 1) * 2 * 128 * LDP);
        const __nv_bfloat16 (*Bs)[LDP] = As + 128;
#pragma unroll
        for (int kk = 0; kk < 64; kk += 16) {
            uint32_t af[2][4], bfr[8][2];
#pragma unroll
            for (int mi = 0; mi < 2; ++mi) {
                const __nv_bfloat16* pa = &As[wr * 32 + mi * 16 + gr][kk + tg * 2];
                af[mi][0] = *(const uint32_t*)pa;
                af[mi][1] = *(const uint32_t*)(pa + 8 * LDP);
                af[mi][2] = *(const uint32_t*)(pa + 8);
                af[mi][3] = *(const uint32_t*)(pa + 8 * LDP + 8);
            }
#pragma unroll
            for (int ni = 0; ni < 8; ++ni) {
                const __nv_bfloat16* pb = &Bs[wc * 64 + ni * 8 + gr][kk + tg * 2];
                bfr[ni][0] = *(const uint32_t*)pb;
                bfr[ni][1] = *(const uint32_t*)(pb + 8);
            }
#pragma unroll
            for (int mi = 0; mi < 2; ++mi)
#pragma unroll
                for (int ni = 0; ni < 8; ++ni)
                    mma16816(acc[mi][ni], af[mi], bfr[ni]);
        }
        __syncthreads();
    }

    float* outb = out + blockIdx.z * zsO;
    const float* xxb = (mode == 1) ? xx + (size_t)blockIdx.z * zsXX : nullptr;
    float rmn[2][2][2];
#pragma unroll
    for (int i = 0; i < 2; ++i)
#pragma unroll
        for (int j = 0; j < 2; ++j) { rmn[i][j][0] = FLT_MAX; rmn[i][j][1] = FLT_MAX; }

#pragma unroll
    for (int mi = 0; mi < 2; ++mi) {
        int mA = m0 + wr * 32 + mi * 16 + gr;
        float xrA = 0.f, xrB = 0.f;
        if (mode == 1) { xrA = xxb[mA]; xrB = xxb[mA + 8]; }
#pragma unroll
        for (int ni = 0; ni < 8; ++ni) {
            int o = o0 + wc * 64 + ni * 8 + tg * 2;
            if (o < Nvalid) {
                float u0 = acc[mi][ni][0], u1 = acc[mi][ni][1];
                float u2 = acc[mi][ni][2], u3 = acc[mi][ni][3];
                if (mode == 0) {
                    float b0 = bias ? bias[o] : 0.f, b1 = bias ? bias[o + 1] : 0.f;
                    u0 += b0; u1 += b1; u2 += b0; u3 += b1;
                    if (act) {
                        u0 = u0 > 0.f ? u0 : 0.2f * u0;
                        u1 = u1 > 0.f ? u1 : 0.2f * u1;
                        u2 = u2 > 0.f ? u2 : 0.2f * u2;
                        u3 = u3 > 0.f ? u3 : 0.2f * u3;
                    }
                } else {
                    float xc0 = xxb[o], xc1 = xxb[o + 1];
                    u0 = xrA - 2.f * u0 + xc0; u1 = xrA - 2.f * u1 + xc1;
                    u2 = xrB - 2.f * u2 + xc0; u3 = xrB - 2.f * u3 + xc1;
                    int s = ni >> 2;
                    rmn[mi][s][0] = fminf(rmn[mi][s][0], fminf(u0, u1));
                    rmn[mi][s][1] = fminf(rmn[mi][s][1], fminf(u2, u3));
                }
                *(float2*)(outb + (size_t)mA * ldo + o)       = make_float2(u0, u1);
                *(float2*)(outb + (size_t)(mA + 8) * ldo + o) = make_float2(u2, u3);
            }
        }
    }
    if (mode == 1) {
        float* sb = submin + (size_t)blockIdx.z * NN * 64;
#pragma unroll
        for (int mi = 0; mi < 2; ++mi)
#pragma unroll
            for (int s = 0; s < 2; ++s)
#pragma unroll
                for (int rr = 0; rr < 2; ++rr) {
                    float v = rmn[mi][s][rr];
                    v = fminf(v, __shfl_xor_sync(0xffffffffu, v, 1));
                    v = fminf(v, __shfl_xor_sync(0xffffffffu, v, 2));
                    if (tg == 0) {
                        int grow = m0 + wr * 32 + mi * 16 + gr + rr * 8;
                        sb[(size_t)grow * 64 + blockIdx.x * 4 + wc * 2 + s] = v;
                    }
                }
    }
}

// =================== threshold-filter top-K (exact, no in-kernel fallback) =========
__global__ void __launch_bounds__(256, 4)
topk_sel(const float* __restrict__ d2, const float* __restrict__ submin,
         int* __restrict__ idxout, int* __restrict__ ovflag) {
    __shared__ unsigned long long fl[8][CAP];
    __shared__ int cnt[8];
    int w = threadIdx.x >> 5, lane = threadIdx.x & 31;
    const unsigned FM = 0xffffffffu;
    size_t row = (size_t)blockIdx.x * 8 + w;
    const float* r = d2 + row * NN;

    if (lane == 0) cnt[w] = 0;
    fl[w][lane] = ~0ULL; fl[w][lane + 32] = ~0ULL; fl[w][lane + 64] = ~0ULL;
    __syncwarp();

    // ---- phase 1: T = 20th smallest subtile-min (monotone bits) ----
    unsigned u0 = mono(submin[row * 64 + lane]);
    unsigned u1 = mono(submin[row * 64 + 32 + lane]);
    unsigned T = 0;
#pragma unroll
    for (int k = 0; k < KNN; ++k) {
        unsigned m = u0 < u1 ? u0 : u1;
        unsigned rmv = m;
#pragma unroll
        for (int off = 16; off; off >>= 1) {
            unsigned o = __shfl_xor_sync(FM, rmv, off);
            rmv = o < rmv ? o : rmv;
        }
        T = rmv;
        if (m == rmv) { if (u0 == rmv) u0 = ~0u; else u1 = ~0u; }
    }

    // ---- phase 2: collect candidates <= T ----
    for (int j = 0; j < 16; ++j) {
        int e0 = 4 * (j * 32 + lane);
        float4 v4 = *(const float4*)(r + e0);
        unsigned q0 = mono(v4.x), q1 = mono(v4.y), q2 = mono(v4.z), q3 = mono(v4.w);
        bool h0 = q0 <= T, h1 = q1 <= T, h2 = q2 <= T, h3 = q3 <= T;
        if (__ballot_sync(FM, h0 | h1 | h2 | h3)) {
            if (h0) { int p = atomicAdd(&cnt[w], 1);
                      if (p < CAP) fl[w][p] = ((unsigned long long)q0 << 32) | (unsigned)e0; }
            if (h1) { int p = atomicAdd(&cnt[w], 1);
                      if (p < CAP) fl[w][p] = ((unsigned long long)q1 << 32) | (unsigned)(e0 + 1); }
            if (h2) { int p = atomicAdd(&cnt[w], 1);
                      if (p < CAP) fl[w][p] = ((unsigned long long)q2 << 32) | (unsigned)(e0 + 2); }
            if (h3) { int p = atomicAdd(&cnt[w], 1);
                      if (p < CAP) fl[w][p] = ((unsigned long long)q3 << 32) | (unsigned)(e0 + 3); }
        }
    }
    __syncwarp();

    int ov = cnt[w] > CAP;
    if (lane == 0) ovflag[row] = ov;
    if (ov) return;                       // exact fallback kernel handles this row

    // ---- phase 3: exact select of 20 by (val, idx) ----
    unsigned long long c0 = fl[w][lane], c1 = fl[w][lane + 32], c2 = fl[w][lane + 64];
#pragma unroll
    for (int k = 0; k < KNN; ++k) {
        unsigned long long loc = c0 < c1 ? c0 : c1;
        loc = c2 < loc ? c2 : loc;
        unsigned long long red = loc;
#pragma unroll
        for (int off = 16; off; off >>= 1) {
            unsigned long long o = __shfl_xor_sync(FM, red, off);
            red = o < red ? o : red;
        }
        if (lane == 0) idxout[row * KNN + k] = (int)(red & 0xffffffffu);
        if (loc == red) {
            if (c0 == red) c0 = ~0ULL;
            else if (c1 == red) c1 = ~0ULL;
            else c2 = ~0ULL;
        }
    }
}

// =================== exact fallback for overflow rows (rare / usually idle) ========
__global__ void __launch_bounds__(256)
topk_fb(const float* __restrict__ d2, const int* __restrict__ ovflag,
        int* __restrict__ idxout) {
    __shared__ unsigned long long fb[8][32 * KNN];
    int w = threadIdx.x >> 5, lane = threadIdx.x & 31;
    const unsigned FM = 0xffffffffu;
    size_t row = (size_t)blockIdx.x * 8 + w;
    if (!ovflag[row]) return;
    const float* r = d2 + row * NN;

    float key[KNN]; int ki[KNN];
#pragma unroll
    for (int j = 0; j < KNN; ++j) { key[j] = FLT_MAX; ki[j] = 0; }
    for (int j = 0; j < 16; ++j) {
        int e0 = 4 * (j * 32 + lane);
        float4 v4 = *(const float4*)(r + e0);
        float vmin = fminf(fminf(v4.x, v4.y), fminf(v4.z, v4.w));
        if (vmin < key[KNN - 1]) {
            float vals[4] = {v4.x, v4.y, v4.z, v4.w};
#pragma unroll
            for (int q = 0; q < 4; ++q) INS(key, ki, vals[q], e0 + q);
        }
    }
#pragma unroll
    for (int j = 0; j < KNN; ++j)
        fb[w][lane * KNN + j] = ((unsigned long long)mono(key[j]) << 32) | (unsigned)ki[j];
    __syncwarp();
    int h = 0;
    unsigned long long hv = fb[w][lane * KNN];
#pragma unroll
    for (int k = 0; k < KNN; ++k) {
        unsigned long long red = hv;
#pragma unroll
        for (int off = 16; off; off >>= 1) {
            unsigned long long o = __shfl_xor_sync(FM, red, off);
            red = o < red ? o : red;
        }
        if (lane == 0) idxout[row * KNN + k] = (int)(red & 0xffffffffu);
        if (hv == red) { ++h; hv = (h < KNN) ? fb[w][lane * KNN + h] : ~0ULL; }
    }
}

// =================== small kernels ===================
// warp-per-row squared norms (coalesced)
__global__ void xx_kernel(const float* __restrict__ X, int ldx, int C,
                          float* __restrict__ xx) {
    int w = threadIdx.x >> 5, lane = threadIdx.x & 31;
    int row = blockIdx.x * 8 + w;
    if (row >= BB * NN) return;
    const float* p = X + (size_t)row * ldx;
    float s = 0.f;
    for (int c = lane; c < C; c += 32) { float v = p[c]; s += v * v; }
#pragma unroll
    for (int off = 16; off; off >>= 1)
        s += __shfl_xor_sync(0xffffffffu, s, off);
    if (lane == 0) xx[row] = s;
}

// h[n,o] = leaky(max_k y[j_k,o] - y[n,o] + c[n,o])   (leaky/max commute)
__global__ void edgemax4(const float* __restrict__ yc, const int* __restrict__ idx,
                         float* __restrict__ out, int O, int ldo) {
    __shared__ int sid[KNN];
    int b = blockIdx.y, n = blockIdx.x;
    int t = threadIdx.x;
    for (int i = t; i < KNN; i += blockDim.x)
        sid[i] = idx[((size_t)b * NN + n) * KNN + i];
    __syncthreads();
    size_t mbase = (size_t)b * NN;
    int ld2 = 2 * O;
    float4 m = make_float4(-FLT_MAX, -FLT_MAX, -FLT_MAX, -FLT_MAX);
#pragma unroll
    for (int k = 0; k < KNN; ++k) {
        float4 yn = *(const float4*)(yc + (mbase + sid[k]) * ld2 + 4 * t);
        m.x = fmaxf(m.x, yn.x); m.y = fmaxf(m.y, yn.y);
        m.z = fmaxf(m.z, yn.z); m.w = fmaxf(m.w, yn.w);
    }
    const float* prow = yc + (mbase + n) * ld2 + 4 * t;
    float4 ycn = *(const float4*)prow;
    float4 ccn = *(const float4*)(prow + O);
    float v0 = m.x - ycn.x + ccn.x;
    float v1 = m.y - ycn.y + ccn.y;
    float v2 = m.z - ycn.z + ccn.z;
    float v3 = m.w - ycn.w + ccn.w;
    v0 = v0 > 0.f ? v0 : 0.2f * v0;
    v1 = v1 > 0.f ? v1 : 0.2f * v1;
    v2 = v2 > 0.f ? v2 : 0.2f * v2;
    v3 = v3 > 0.f ? v3 : 0.2f * v3;
    *(float4*)(out + (mbase + n) * ldo + 4 * t) = make_float4(v0, v1, v2, v3);
}

__global__ void maxpool(const float* __restrict__ tmp, float* __restrict__ out) {
    int b = blockIdx.y;
    int f = blockIdx.x * blockDim.x + threadIdx.x;
    const float* p = tmp + (size_t)b * NN * 1024 + f;
    float m = -FLT_MAX;
    for (int n = 0; n < NN; ++n) m = fmaxf(m, p[(size_t)n * 1024]);
    out[b * 1024 + f] = m;
}

// =================== launch ===================
extern "C" void kernel_launch(void* const* d_in, const int* in_sizes, int n_in,
                              void* d_out, int out_size) {
    const float* x     = (const float*)d_in[0];
    const float* Wl[4] = {(const float*)d_in[1], (const float*)d_in[3],
                          (const float*)d_in[5], (const float*)d_in[7]};
    const float* bl[4] = {(const float*)d_in[2], (const float*)d_in[4],
                          (const float*)d_in[6], (const float*)d_in[8]};
    const float* Wf = (const float*)d_in[9];
    const float* bf = (const float*)d_in[10];
    float* out = (float*)d_out;

    float *p_d2, *p_sub, *p_xx, *p_yc, *p_hcat, *p_tmp, *p_bias2;
    __nv_bfloat16 *p_a3, *p_b3, *p_bf3, *p_w3;
    int *p_idx, *p_ov;
    cudaGetSymbolAddress((void**)&p_d2,    g_d2);
    cudaGetSymbolAddress((void**)&p_sub,   g_submin);
    cudaGetSymbolAddress((void**)&p_xx,    g_xx);
    cudaGetSymbolAddress((void**)&p_idx,   g_idx);
    cudaGetSymbolAddress((void**)&p_ov,    g_ov);
    cudaGetSymbolAddress((void**)&p_yc,    g_yc);
    cudaGetSymbolAddress((void**)&p_hcat,  g_hcat);
    cudaGetSymbolAddress((void**)&p_tmp,   g_tmp);
    cudaGetSymbolAddress((void**)&p_bias2, g_bias2);
    cudaGetSymbolAddress((void**)&p_a3,    g_a3);
    cudaGetSymbolAddress((void**)&p_b3,    g_b3);
    cudaGetSymbolAddress((void**)&p_bf3,   g_bf3);
    cudaGetSymbolAddress((void**)&p_w3,    g_w3);

    cudaFuncSetAttribute(mma_gemm, cudaFuncAttributeMaxDynamicSharedMemorySize,
                         MMA_SMEM);

    const int Cs[4]  = {3, 64, 64, 128};
    const int Os[4]  = {64, 64, 128, 256};
    const int off[4] = {0, 64, 128, 256};

    const float* Xin = x;
    int ldx = 3;
    for (int l = 0; l < 4; ++l) {
        int C = Cs[l], O = Os[l];
        int K3 = ((3 * C + 63) / 64) * 64;     // 64, 192, 192, 384

        xx_kernel<<<(BB * NN) / 8, 256>>>(Xin, ldx, C, p_xx);
        convAB_kernel<<<dim3((K3 + 255) / 256, BB * NN), 256>>>(
            Xin, ldx, C, p_a3, p_b3, K3);
        // pairwise d2 + subtile mins (batched over z)
        mma_gemm<<<dim3(16, 16, BB), 256, MMA_SMEM>>>(
            p_a3, K3, (size_t)NN * K3, p_b3, K3, (size_t)NN * K3,
            NN, K3, p_d2, NN, (size_t)NN * NN, nullptr, 0, 1, p_xx, NN, p_sub);
        topk_sel<<<(BB * NN) / 8, 256>>>(p_d2, p_sub, p_idx, p_ov);
        topk_fb<<<(BB * NN) / 8, 256>>>(p_d2, p_ov, p_idx);
        // combined yc = X * [Wy|Wc]^T + [0|b]
        convB_kernel<<<dim3((K3 + 255) / 256, O), 256>>>(Wl[l], 2 * C, C, p_w3, K3);
        convB_kernel<<<dim3((K3 + 255) / 256, O), 256>>>(Wl[l] + C, 2 * C, C,
                                                         p_w3 + (size_t)O * K3, K3);
        biascat<<<1, 512>>>(bl[l], p_bias2, O);
        mma_gemm<<<dim3((2 * O + 127) / 128, (BB * NN) / 128, 1), 256, MMA_SMEM>>>(
            p_a3, K3, 0, p_w3, K3, 0, 2 * O, K3,
            p_yc, 2 * O, 0, p_bias2, 0, 0, nullptr, 0, nullptr);
        edgemax4<<<dim3(NN, BB), O / 4>>>(p_yc, p_idx, p_hcat + off[l], O, 512);
        Xin = p_hcat + off[l];
        ldx = 512;
    }
    // final 512 -> 1024 linear + leaky, then max over N
    convA_kernel<<<dim3(1536 / 256, BB * NN), 256>>>(p_hcat, 512, 512, p_a3, 1536);
    convB_kernel<<<dim3(1536 / 256, 1024), 256>>>(Wf, 512, 512, p_bf3, 1536);
    mma_gemm<<<dim3(1024 / 128, (BB * NN) / 128, 1), 256, MMA_SMEM>>>(
        p_a3, 1536, 0, p_bf3, 1536, 0, 1024, 1536,
        p_tmp, 1024, 0, bf, 1, 0, nullptr, 0, nullptr);
    maxpool<<<dim3(1024 / 256, BB), 256>>>(p_tmp, out);
}

// round 11
// speedup vs baseline: 2.3459x; 1.0928x over previous
#include <cuda_runtime.h>
#include <cuda_bf16.h>
#include <float.h>
#include <math.h>
#include <cstdint>

#define BB  8
#define NN  2048
#define KNN 20
#define CAP 96   // candidate cap per row before fallback

// ---------------- scratch (device globals; no allocations) ----------------
__device__ __align__(16) float g_d2[(size_t)BB * NN * NN];
__device__ __align__(16) float g_submin[(size_t)BB * NN * 64];
__device__ __align__(16) float g_xx[BB * NN];
__device__ __align__(16) int   g_idx[BB * NN * KNN];
__device__ __align__(16) int   g_ov[BB * NN];
__device__ __align__(16) float g_yc[(size_t)BB * NN * 512];    // y | c combined
__device__ __align__(16) float g_hcat[(size_t)BB * NN * 512];
__device__ __align__(16) float g_tmp[(size_t)BB * NN * 1024];
__device__ __align__(16) float g_part[16 * BB * 1024];
__device__ __align__(16) float g_bias2[512];
__device__ __align__(16) __nv_bfloat16 g_a3[(size_t)BB * NN * 1536];  // split A (h|l|h)
__device__ __align__(16) __nv_bfloat16 g_b3[(size_t)BB * NN * 384];   // split B (h|h|l)
__device__ __align__(16) __nv_bfloat16 g_bf3[1024 * 1536];            // split Wf
__device__ __align__(16) __nv_bfloat16 g_w3[512 * 384];               // split layer W (y|c)

// =================== split-precision conversion kernels ===================
__global__ void convAB_kernel(const float* __restrict__ in, int ld, int C,
                              __nv_bfloat16* __restrict__ a3,
                              __nv_bfloat16* __restrict__ b3, int K3) {
    int r = blockIdx.y;
    int c = blockIdx.x * 256 + threadIdx.x;
    if (c >= K3) return;
    size_t ro = (size_t)r * K3;
    if (c < C) {
        float xv = in[(size_t)r * ld + c];
        __nv_bfloat16 h = __float2bfloat16(xv);
        __nv_bfloat16 l = __float2bfloat16(xv - __bfloat162float(h));
        a3[ro + c] = h; a3[ro + C + c] = l; a3[ro + 2 * C + c] = h;
        b3[ro + c] = h; b3[ro + C + c] = h; b3[ro + 2 * C + c] = l;
    } else if (c >= 3 * C) {
        __nv_bfloat16 z = __float2bfloat16(0.f);
        a3[ro + c] = z; b3[ro + c] = z;
    }
}
__global__ void convA_kernel(const float* __restrict__ in, int ld, int C,
                             __nv_bfloat16* __restrict__ out, int K3) {
    int r = blockIdx.y;
    int c = blockIdx.x * 256 + threadIdx.x;
    if (c >= K3) return;
    size_t ro = (size_t)r * K3;
    if (c < C) {
        float xv = in[(size_t)r * ld + c];
        __nv_bfloat16 h = __float2bfloat16(xv);
        __nv_bfloat16 l = __float2bfloat16(xv - __bfloat162float(h));
        out[ro + c] = h; out[ro + C + c] = l; out[ro + 2 * C + c] = h;
    } else if (c >= 3 * C) {
        out[ro + c] = __float2bfloat16(0.f);
    }
}
__global__ void convB_kernel(const float* __restrict__ in, int ld, int C,
                             __nv_bfloat16* __restrict__ out, int K3) {
    int r = blockIdx.y;
    int c = blockIdx.x * 256 + threadIdx.x;
    if (c >= K3) return;
    size_t ro = (size_t)r * K3;
    if (c < C) {
        float xv = in[(size_t)r * ld + c];
        __nv_bfloat16 h = __float2bfloat16(xv);
        __nv_bfloat16 l = __float2bfloat16(xv - __bfloat162float(h));
        out[ro + c] = h; out[ro + C + c] = h; out[ro + 2 * C + c] = l;
    } else if (c >= 3 * C) {
        out[ro + c] = __float2bfloat16(0.f);
    }
}
__global__ void biascat(const float* __restrict__ bl, float* __restrict__ out, int O) {
    int i = threadIdx.x;
    if (i < O) out[i] = 0.f;
    else if (i < 2 * O) out[i] = bl[i - O];
}

#define LDP 72

__device__ __forceinline__ void mma16816(float* d, const uint32_t* a, const uint32_t* b) {
    asm volatile(
        "mma.sync.aligned.m16n8k16.row.col.f32.bf16.bf16.f32 "
        "{%0,%1,%2,%3}, {%4,%5,%6,%7}, {%8,%9}, {%0,%1,%2,%3};"
        : "+f"(d[0]), "+f"(d[1]), "+f"(d[2]), "+f"(d[3])
        : "r"(a[0]), "r"(a[1]), "r"(a[2]), "r"(a[3]), "r"(b[0]), "r"(b[1]));
}
__device__ __forceinline__ uint32_t smem_u32(const void* p) {
    uint32_t a;
    asm("{ .reg .u64 t; cvta.to.shared.u64 t, %1; cvt.u32.u64 %0, t; }" : "=r"(a) : "l"(p));
    return a;
}
__device__ __forceinline__ unsigned mono(float v) {
    unsigned u = __float_as_uint(v);
    return (u & 0x80000000u) ? ~u : (u | 0x80000000u);
}
__device__ __forceinline__ float unmono(unsigned m) {
    unsigned u = (m & 0x80000000u) ? (m ^ 0x80000000u) : ~m;
    return __uint_as_float(u);
}
#define CPA(dst, src, n) \
    asm volatile("cp.async.cg.shared.global [%0], [%1], 16, %2;" \
                 :: "r"(dst), "l"(src), "r"(n))
#define CPA_COMMIT() asm volatile("cp.async.commit_group;" ::: "memory")
#define CPA_WAIT1()  asm volatile("cp.async.wait_group 1;" ::: "memory")
#define CPA_WAIT0()  asm volatile("cp.async.wait_group 0;" ::: "memory")

// register insertion into sorted KNN list (strict < keeps lowest idx on ties)
#define INS(keys, kidx, v, ix) do { \
    if ((v) < keys[KNN - 1]) { \
        float _cv = (v); int _ci = (ix); \
        _Pragma("unroll") \
        for (int _j = 0; _j < KNN; ++_j) { \
            if (_cv < keys[_j]) { \
                float _tv = keys[_j]; keys[_j] = _cv; _cv = _tv; \
                int _ti = kidx[_j]; kidx[_j] = _ci; _ci = _ti; \
            } \
        } \
    } } while (0)

#define MMA_SMEM (2 * 2 * 128 * LDP * 2)

// =================== cp.async-pipelined mma.sync GEMM, 128x128 tile ===============
// mode 0: out[m][o] = acc + bias[o]  (leaky if act)
// mode 1: out[m][o] = xx[m] - 2*acc + xx[o]; also emits 32-col subtile row-mins
__global__ void __launch_bounds__(256)
mma_gemm(const __nv_bfloat16* __restrict__ A3, int lda3, size_t zsA,
         const __nv_bfloat16* __restrict__ B3, int ldb3, size_t zsB,
         int Nvalid, int K3,
         float* __restrict__ out, int ldo, size_t zsO,
         const float* __restrict__ bias, int act,
         int mode, const float* __restrict__ xx, int zsXX,
         float* __restrict__ submin) {
    extern __shared__ __nv_bfloat16 sm[];
    int tid = threadIdx.x;
    int wid = tid >> 5, lane = tid & 31;
    int wr = wid & 3, wc = wid >> 2;
    int gr = lane >> 2, tg = lane & 3;

    int m0 = blockIdx.y * 128, o0 = blockIdx.x * 128;
    const __nv_bfloat16* Ab = A3 + blockIdx.z * zsA;
    const __nv_bfloat16* Bb = B3 + blockIdx.z * zsB;
    uint32_t sbase = smem_u32(sm);
    int nch = K3 / 64;

    auto issue = [&](int s, int k0) {
#pragma unroll
        for (int i = 0; i < 4; ++i) {
            int e = tid + i * 256;
            int row = e >> 3, seg = e & 7;
            uint32_t da = sbase + (uint32_t)(s * 2 * 128 * LDP + row * LDP + seg * 8) * 2;
            CPA(da, Ab + (size_t)(m0 + row) * lda3 + k0 + seg * 8, 16);
            int brow = o0 + row;
            int srow = brow < Nvalid ? brow : (Nvalid - 1);
            uint32_t db = sbase + (uint32_t)((s * 2 + 1) * 128 * LDP + row * LDP + seg * 8) * 2;
            CPA(db, Bb + (size_t)srow * ldb3 + k0 + seg * 8, brow < Nvalid ? 16 : 0);
        }
        CPA_COMMIT();
    };

    float acc[2][8][4] = {};
    issue(0, 0);
    for (int ch = 0; ch < nch; ++ch) {
        if (ch + 1 < nch) { issue((ch + 1) & 1, (ch + 1) * 64); CPA_WAIT1(); }
        else              { CPA_WAIT0(); }
        __syncthreads();
        const __nv_bfloat16 (*As)[LDP] =
            (const __nv_bfloat16(*)[LDP])(sm + (ch & 1) * 2 * 128 * LDP);
        const __nv_bfloat16 (*Bs)[LDP] = As + 128;
#pragma unroll
        for (int kk = 0; kk < 64; kk += 16) {
            uint32_t af[2][4], bfr[8][2];
#pragma unroll
            for (int mi = 0; mi < 2; ++mi) {
                const __nv_bfloat16* pa = &As[wr * 32 + mi * 16 + gr][kk + tg * 2];
                af[mi][0] = *(const uint32_t*)pa;
                af[mi][1] = *(const uint32_t*)(pa + 8 * LDP);
                af[mi][2] = *(const uint32_t*)(pa + 8);
                af[mi][3] = *(const uint32_t*)(pa + 8 * LDP + 8);
            }
#pragma unroll
            for (int ni = 0; ni < 8; ++ni) {
                const __nv_bfloat16* pb = &Bs[wc * 64 + ni * 8 + gr][kk + tg * 2];
                bfr[ni][0] = *(const uint32_t*)pb;
                bfr[ni][1] = *(const uint32_t*)(pb + 8);
            }
#pragma unroll
            for (int mi = 0; mi < 2; ++mi)
#pragma unroll
                for (int ni = 0; ni < 8; ++ni)
                    mma16816(acc[mi][ni], af[mi], bfr[ni]);
        }
        __syncthreads();
    }

    float* outb = out + blockIdx.z * zsO;
    const float* xxb = (mode == 1) ? xx + (size_t)blockIdx.z * zsXX : nullptr;
    float rmn[2][2][2];
#pragma unroll
    for (int i = 0; i < 2; ++i)
#pragma unroll
        for (int j = 0; j < 2; ++j) { rmn[i][j][0] = FLT_MAX; rmn[i][j][1] = FLT_MAX; }

#pragma unroll
    for (int mi = 0; mi < 2; ++mi) {
        int mA = m0 + wr * 32 + mi * 16 + gr;
        float xrA = 0.f, xrB = 0.f;
        if (mode == 1) { xrA = xxb[mA]; xrB = xxb[mA + 8]; }
#pragma unroll
        for (int ni = 0; ni < 8; ++ni) {
            int o = o0 + wc * 64 + ni * 8 + tg * 2;
            if (o < Nvalid) {
                float u0 = acc[mi][ni][0], u1 = acc[mi][ni][1];
                float u2 = acc[mi][ni][2], u3 = acc[mi][ni][3];
                if (mode == 0) {
                    float b0 = bias ? bias[o] : 0.f, b1 = bias ? bias[o + 1] : 0.f;
                    u0 += b0; u1 += b1; u2 += b0; u3 += b1;
                    if (act) {
                        u0 = u0 > 0.f ? u0 : 0.2f * u0;
                        u1 = u1 > 0.f ? u1 : 0.2f * u1;
                        u2 = u2 > 0.f ? u2 : 0.2f * u2;
                        u3 = u3 > 0.f ? u3 : 0.2f * u3;
                    }
                } else {
                    float xc0 = xxb[o], xc1 = xxb[o + 1];
                    u0 = xrA - 2.f * u0 + xc0; u1 = xrA - 2.f * u1 + xc1;
                    u2 = xrB - 2.f * u2 + xc0; u3 = xrB - 2.f * u3 + xc1;
                    int s = ni >> 2;
                    rmn[mi][s][0] = fminf(rmn[mi][s][0], fminf(u0, u1));
                    rmn[mi][s][1] = fminf(rmn[mi][s][1], fminf(u2, u3));
                }
                *(float2*)(outb + (size_t)mA * ldo + o)       = make_float2(u0, u1);
                *(float2*)(outb + (size_t)(mA + 8) * ldo + o) = make_float2(u2, u3);
            }
        }
    }
    if (mode == 1) {
        float* sb = submin + (size_t)blockIdx.z * NN * 64;
#pragma unroll
        for (int mi = 0; mi < 2; ++mi)
#pragma unroll
            for (int s = 0; s < 2; ++s)
#pragma unroll
                for (int rr = 0; rr < 2; ++rr) {
                    float v = rmn[mi][s][rr];
                    v = fminf(v, __shfl_xor_sync(0xffffffffu, v, 1));
                    v = fminf(v, __shfl_xor_sync(0xffffffffu, v, 2));
                    if (tg == 0) {
                        int grow = m0 + wr * 32 + mi * 16 + gr + rr * 8;
                        sb[(size_t)grow * 64 + blockIdx.x * 4 + wc * 2 + s] = v;
                    }
                }
    }
}

// =================== threshold-filter top-K with subtile skip (exact) =============
// Phase 1: T = 20th smallest of 64 subtile-mins. Only subtiles with min <= T can
// contain top-20 members (all others strictly exceed the 20th distance), so phase 2
// scans ONLY those ~20 subtiles (coalesced 128B loads). Phase 3: exact (val,idx).
__global__ void __launch_bounds__(256, 4)
topk_sel(const float* __restrict__ d2, const float* __restrict__ submin,
         int* __restrict__ idxout, int* __restrict__ ovflag) {
    __shared__ unsigned long long fl[8][CAP];
    __shared__ int cnt[8];
    int w = threadIdx.x >> 5, lane = threadIdx.x & 31;
    const unsigned FM = 0xffffffffu;
    size_t row = (size_t)blockIdx.x * 8 + w;
    const float* r = d2 + row * NN;

    if (lane == 0) cnt[w] = 0;
    fl[w][lane] = ~0ULL; fl[w][lane + 32] = ~0ULL; fl[w][lane + 64] = ~0ULL;
    __syncwarp();

    // ---- phase 1: T = 20th smallest subtile-min (monotone bits) ----
    float s0f = submin[row * 64 + lane];
    float s1f = submin[row * 64 + 32 + lane];
    unsigned u0 = mono(s0f), u1 = mono(s1f);
    unsigned T = 0;
#pragma unroll
    for (int k = 0; k < KNN; ++k) {
        unsigned m = u0 < u1 ? u0 : u1;
        unsigned rmv = m;
#pragma unroll
        for (int off = 16; off; off >>= 1) {
            unsigned o = __shfl_xor_sync(FM, rmv, off);
            rmv = o < rmv ? o : rmv;
        }
        T = rmv;
        if (m == rmv) { if (u0 == rmv) u0 = ~0u; else u1 = ~0u; }
    }
    float Tf = unmono(T);

    // ---- phase 2: scan ONLY qualifying subtiles (submin <= Tf) ----
    unsigned mask0 = __ballot_sync(FM, s0f <= Tf);
    unsigned mask1 = __ballot_sync(FM, s1f <= Tf);
    while (mask0) {
        int s = __ffs(mask0) - 1; mask0 &= mask0 - 1;
        int e = s * 32 + lane;
        float v = r[e];
        if (v <= Tf) {
            int p = atomicAdd(&cnt[w], 1);
            if (p < CAP) fl[w][p] = ((unsigned long long)mono(v) << 32) | (unsigned)e;
        }
    }
    while (mask1) {
        int s = 32 + __ffs(mask1) - 1; mask1 &= mask1 - 1;
        int e = s * 32 + lane;
        float v = r[e];
        if (v <= Tf) {
            int p = atomicAdd(&cnt[w], 1);
            if (p < CAP) fl[w][p] = ((unsigned long long)mono(v) << 32) | (unsigned)e;
        }
    }
    __syncwarp();

    int ov = cnt[w] > CAP;
    if (lane == 0) ovflag[row] = ov;
    if (ov) return;                       // exact fallback kernel handles this row

    // ---- phase 3: exact select of 20 by (val, idx) ----
    unsigned long long c0 = fl[w][lane], c1 = fl[w][lane + 32], c2 = fl[w][lane + 64];
#pragma unroll
    for (int k = 0; k < KNN; ++k) {
        unsigned long long loc = c0 < c1 ? c0 : c1;
        loc = c2 < loc ? c2 : loc;
        unsigned long long red = loc;
#pragma unroll
        for (int off = 16; off; off >>= 1) {
            unsigned long long o = __shfl_xor_sync(FM, red, off);
            red = o < red ? o : red;
        }
        if (lane == 0) idxout[row * KNN + k] = (int)(red & 0xffffffffu);
        if (loc == red) {
            if (c0 == red) c0 = ~0ULL;
            else if (c1 == red) c1 = ~0ULL;
            else c2 = ~0ULL;
        }
    }
}

// =================== exact fallback for overflow rows (rare / usually idle) ========
__global__ void __launch_bounds__(256)
topk_fb(const float* __restrict__ d2, const int* __restrict__ ovflag,
        int* __restrict__ idxout) {
    __shared__ unsigned long long fb[8][32 * KNN];
    int w = threadIdx.x >> 5, lane = threadIdx.x & 31;
    const unsigned FM = 0xffffffffu;
    size_t row = (size_t)blockIdx.x * 8 + w;
    if (!ovflag[row]) return;
    const float* r = d2 + row * NN;

    float key[KNN]; int ki[KNN];
#pragma unroll
    for (int j = 0; j < KNN; ++j) { key[j] = FLT_MAX; ki[j] = 0; }
    for (int j = 0; j < 16; ++j) {
        int e0 = 4 * (j * 32 + lane);
        float4 v4 = *(const float4*)(r + e0);
        float vmin = fminf(fminf(v4.x, v4.y), fminf(v4.z, v4.w));
        if (vmin < key[KNN - 1]) {
            float vals[4] = {v4.x, v4.y, v4.z, v4.w};
#pragma unroll
            for (int q = 0; q < 4; ++q) INS(key, ki, vals[q], e0 + q);
        }
    }
#pragma unroll
    for (int j = 0; j < KNN; ++j)
        fb[w][lane * KNN + j] = ((unsigned long long)mono(key[j]) << 32) | (unsigned)ki[j];
    __syncwarp();
    int h = 0;
    unsigned long long hv = fb[w][lane * KNN];
#pragma unroll
    for (int k = 0; k < KNN; ++k) {
        unsigned long long red = hv;
#pragma unroll
        for (int off = 16; off; off >>= 1) {
            unsigned long long o = __shfl_xor_sync(FM, red, off);
            red = o < red ? o : red;
        }
        if (lane == 0) idxout[row * KNN + k] = (int)(red & 0xffffffffu);
        if (hv == red) { ++h; hv = (h < KNN) ? fb[w][lane * KNN + h] : ~0ULL; }
    }
}

// =================== small kernels ===================
// warp-per-row squared norms (coalesced)
__global__ void xx_kernel(const float* __restrict__ X, int ldx, int C,
                          float* __restrict__ xx) {
    int w = threadIdx.x >> 5, lane = threadIdx.x & 31;
    int row = blockIdx.x * 8 + w;
    if (row >= BB * NN) return;
    const float* p = X + (size_t)row * ldx;
    float s = 0.f;
    for (int c = lane; c < C; c += 32) { float v = p[c]; s += v * v; }
#pragma unroll
    for (int off = 16; off; off >>= 1)
        s += __shfl_xor_sync(0xffffffffu, s, off);
    if (lane == 0) xx[row] = s;
}

// h[n,o] = leaky(max_k y[j_k,o] - y[n,o] + c[n,o])   (leaky/max commute)
__global__ void edgemax4(const float* __restrict__ yc, const int* __restrict__ idx,
                         float* __restrict__ out, int O, int ldo) {
    __shared__ int sid[KNN];
    int b = blockIdx.y, n = blockIdx.x;
    int t = threadIdx.x;
    for (int i = t; i < KNN; i += blockDim.x)
        sid[i] = idx[((size_t)b * NN + n) * KNN + i];
    __syncthreads();
    size_t mbase = (size_t)b * NN;
    int ld2 = 2 * O;
    float4 m = make_float4(-FLT_MAX, -FLT_MAX, -FLT_MAX, -FLT_MAX);
#pragma unroll
    for (int k = 0; k < KNN; ++k) {
        float4 yn = *(const float4*)(yc + (mbase + sid[k]) * ld2 + 4 * t);
        m.x = fmaxf(m.x, yn.x); m.y = fmaxf(m.y, yn.y);
        m.z = fmaxf(m.z, yn.z); m.w = fmaxf(m.w, yn.w);
    }
    const float* prow = yc + (mbase + n) * ld2 + 4 * t;
    float4 ycn = *(const float4*)prow;
    float4 ccn = *(const float4*)(prow + O);
    float v0 = m.x - ycn.x + ccn.x;
    float v1 = m.y - ycn.y + ccn.y;
    float v2 = m.z - ycn.z + ccn.z;
    float v3 = m.w - ycn.w + ccn.w;
    v0 = v0 > 0.f ? v0 : 0.2f * v0;
    v1 = v1 > 0.f ? v1 : 0.2f * v1;
    v2 = v2 > 0.f ? v2 : 0.2f * v2;
    v3 = v3 > 0.f ? v3 : 0.2f * v3;
    *(float4*)(out + (mbase + n) * ldo + 4 * t) = make_float4(v0, v1, v2, v3);
}

// two-stage global max pool over N
__global__ void maxpool1(const float* __restrict__ tmp, float* __restrict__ part) {
    int b = blockIdx.y, c = blockIdx.z;
    int f = blockIdx.x * blockDim.x + threadIdx.x;
    const float* p = tmp + ((size_t)b * NN + c * 128) * 1024 + f;
    float m = -FLT_MAX;
#pragma unroll 4
    for (int n = 0; n < 128; ++n) m = fmaxf(m, p[(size_t)n * 1024]);
    part[(c * BB + b) * 1024 + f] = m;
}
__global__ void maxpool2(const float* __restrict__ part, float* __restrict__ out) {
    int b = blockIdx.y;
    int f = blockIdx.x * blockDim.x + threadIdx.x;
    float m = -FLT_MAX;
#pragma unroll
    for (int c = 0; c < 16; ++c) m = fmaxf(m, part[(c * BB + b) * 1024 + f]);
    out[b * 1024 + f] = m;
}

// =================== launch ===================
extern "C" void kernel_launch(void* const* d_in, const int* in_sizes, int n_in,
                              void* d_out, int out_size) {
    const float* x     = (const float*)d_in[0];
    const float* Wl[4] = {(const float*)d_in[1], (const float*)d_in[3],
                          (const float*)d_in[5], (const float*)d_in[7]};
    const float* bl[4] = {(const float*)d_in[2], (const float*)d_in[4],
                          (const float*)d_in[6], (const float*)d_in[8]};
    const float* Wf = (const float*)d_in[9];
    const float* bf = (const float*)d_in[10];
    float* out = (float*)d_out;

    float *p_d2, *p_sub, *p_xx, *p_yc, *p_hcat, *p_tmp, *p_part, *p_bias2;
    __nv_bfloat16 *p_a3, *p_b3, *p_bf3, *p_w3;
    int *p_idx, *p_ov;
    cudaGetSymbolAddress((void**)&p_d2,    g_d2);
    cudaGetSymbolAddress((void**)&p_sub,   g_submin);
    cudaGetSymbolAddress((void**)&p_xx,    g_xx);
    cudaGetSymbolAddress((void**)&p_idx,   g_idx);
    cudaGetSymbolAddress((void**)&p_ov,    g_ov);
    cudaGetSymbolAddress((void**)&p_yc,    g_yc);
    cudaGetSymbolAddress((void**)&p_hcat,  g_hcat);
    cudaGetSymbolAddress((void**)&p_tmp,   g_tmp);
    cudaGetSymbolAddress((void**)&p_part,  g_part);
    cudaGetSymbolAddress((void**)&p_bias2, g_bias2);
    cudaGetSymbolAddress((void**)&p_a3,    g_a3);
    cudaGetSymbolAddress((void**)&p_b3,    g_b3);
    cudaGetSymbolAddress((void**)&p_bf3,   g_bf3);
    cudaGetSymbolAddress((void**)&p_w3,    g_w3);

    cudaFuncSetAttribute(mma_gemm, cudaFuncAttributeMaxDynamicSharedMemorySize,
                         MMA_SMEM);

    const int Cs[4]  = {3, 64, 64, 128};
    const int Os[4]  = {64, 64, 128, 256};
    const int off[4] = {0, 64, 128, 256};

    const float* Xin = x;
    int ldx = 3;
    for (int l = 0; l < 4; ++l) {
        int C = Cs[l], O = Os[l];
        int K3 = ((3 * C + 63) / 64) * 64;     // 64, 192, 192, 384

        xx_kernel<<<(BB * NN) / 8, 256>>>(Xin, ldx, C, p_xx);
        convAB_kernel<<<dim3((K3 + 255) / 256, BB * NN), 256>>>(
            Xin, ldx, C, p_a3, p_b3, K3);
        // pairwise d2 + subtile mins (batched over z)
        mma_gemm<<<dim3(16, 16, BB), 256, MMA_SMEM>>>(
            p_a3, K3, (size_t)NN * K3, p_b3, K3, (size_t)NN * K3,
            NN, K3, p_d2, NN, (size_t)NN * NN, nullptr, 0, 1, p_xx, NN, p_sub);
        topk_sel<<<(BB * NN) / 8, 256>>>(p_d2, p_sub, p_idx, p_ov);
        topk_fb<<<(BB * NN) / 8, 256>>>(p_d2, p_ov, p_idx);
        // combined yc = X * [Wy|Wc]^T + [0|b]
        convB_kernel<<<dim3((K3 + 255) / 256, O), 256>>>(Wl[l], 2 * C, C, p_w3, K3);
        convB_kernel<<<dim3((K3 + 255) / 256, O), 256>>>(Wl[l] + C, 2 * C, C,
                                                         p_w3 + (size_t)O * K3, K3);
        biascat<<<1, 512>>>(bl[l], p_bias2, O);
        mma_gemm<<<dim3((2 * O + 127) / 128, (BB * NN) / 128, 1), 256, MMA_SMEM>>>(
            p_a3, K3, 0, p_w3, K3, 0, 2 * O, K3,
            p_yc, 2 * O, 0, p_bias2, 0, 0, nullptr, 0, nullptr);
        edgemax4<<<dim3(NN, BB), O / 4>>>(p_yc, p_idx, p_hcat + off[l], O, 512);
        Xin = p_hcat + off[l];
        ldx = 512;
    }
    // final 512 -> 1024 linear + leaky, then max over N (two-stage pool)
    convA_kernel<<<dim3(1536 / 256, BB * NN), 256>>>(p_hcat, 512, 512, p_a3, 1536);
    convB_kernel<<<dim3(1536 / 256, 1024), 256>>>(Wf, 512, 512, p_bf3, 1536);
    mma_gemm<<<dim3(1024 / 128, (BB * NN) / 128, 1), 256, MMA_SMEM>>>(
        p_a3, 1536, 0, p_bf3, 1536, 0, 1024, 1536,
        p_tmp, 1024, 0, bf, 1, 0, nullptr, 0, nullptr);
    maxpool1<<<dim3(1024 / 256, BB, 16), 256>>>(p_tmp, p_part);
    maxpool2<<<dim3(1024 / 256, BB), 256>>>(p_part, out);
}

// round 12
// speedup vs baseline: 2.4119x; 1.0281x over previous
#include <cuda_runtime.h>
#include <cuda_bf16.h>
#include <float.h>
#include <math.h>
#include <cstdint>

#define BB  8
#define NN  2048
#define KNN 20
#define CAP 128   // candidate cap per row before fallback (= bitonic width)

// ---------------- scratch (device globals; no allocations) ----------------
__device__ __align__(16) float g_d2[(size_t)BB * NN * NN];
__device__ __align__(16) float g_submin[(size_t)BB * NN * 64];
__device__ __align__(16) float g_xx[BB * NN];
__device__ __align__(16) int   g_idx[BB * NN * KNN];
__device__ __align__(16) int   g_ov[BB * NN];
__device__ __align__(16) float g_yc[(size_t)BB * NN * 512];    // y | c combined
__device__ __align__(16) float g_hcat[(size_t)BB * NN * 512];
__device__ __align__(16) float g_tmp[(size_t)BB * NN * 1024];
__device__ __align__(16) float g_part[16 * BB * 1024];
__device__ __align__(16) float g_bias2[512];
__device__ __align__(16) __nv_bfloat16 g_a3[(size_t)BB * NN * 1536];  // split A (h|l|h)
__device__ __align__(16) __nv_bfloat16 g_b3[(size_t)BB * NN * 384];   // split B (h|h|l)
__device__ __align__(16) __nv_bfloat16 g_bf3[1024 * 1536];            // split Wf
__device__ __align__(16) __nv_bfloat16 g_w3[512 * 384];               // split layer W (y|c)

// =================== split-precision conversion kernels ===================
__global__ void convAB_kernel(const float* __restrict__ in, int ld, int C,
                              __nv_bfloat16* __restrict__ a3,
                              __nv_bfloat16* __restrict__ b3, int K3) {
    int r = blockIdx.y;
    int c = blockIdx.x * 256 + threadIdx.x;
    if (c >= K3) return;
    size_t ro = (size_t)r * K3;
    if (c < C) {
        float xv = in[(size_t)r * ld + c];
        __nv_bfloat16 h = __float2bfloat16(xv);
        __nv_bfloat16 l = __float2bfloat16(xv - __bfloat162float(h));
        a3[ro + c] = h; a3[ro + C + c] = l; a3[ro + 2 * C + c] = h;
        b3[ro + c] = h; b3[ro + C + c] = h; b3[ro + 2 * C + c] = l;
    } else if (c >= 3 * C) {
        __nv_bfloat16 z = __float2bfloat16(0.f);
        a3[ro + c] = z; b3[ro + c] = z;
    }
}
__global__ void convA_kernel(const float* __restrict__ in, int ld, int C,
                             __nv_bfloat16* __restrict__ out, int K3) {
    int r = blockIdx.y;
    int c = blockIdx.x * 256 + threadIdx.x;
    if (c >= K3) return;
    size_t ro = (size_t)r * K3;
    if (c < C) {
        float xv = in[(size_t)r * ld + c];
        __nv_bfloat16 h = __float2bfloat16(xv);
        __nv_bfloat16 l = __float2bfloat16(xv - __bfloat162float(h));
        out[ro + c] = h; out[ro + C + c] = l; out[ro + 2 * C + c] = h;
    } else if (c >= 3 * C) {
        out[ro + c] = __float2bfloat16(0.f);
    }
}
__global__ void convB_kernel(const float* __restrict__ in, int ld, int C,
                             __nv_bfloat16* __restrict__ out, int K3) {
    int r = blockIdx.y;
    int c = blockIdx.x * 256 + threadIdx.x;
    if (c >= K3) return;
    size_t ro = (size_t)r * K3;
    if (c < C) {
        float xv = in[(size_t)r * ld + c];
        __nv_bfloat16 h = __float2bfloat16(xv);
        __nv_bfloat16 l = __float2bfloat16(xv - __bfloat162float(h));
        out[ro + c] = h; out[ro + C + c] = h; out[ro + 2 * C + c] = l;
    } else if (c >= 3 * C) {
        out[ro + c] = __float2bfloat16(0.f);
    }
}
__global__ void biascat(const float* __restrict__ bl, float* __restrict__ out, int O) {
    int i = threadIdx.x;
    if (i < O) out[i] = 0.f;
    else if (i < 2 * O) out[i] = bl[i - O];
}

#define LDP 72

__device__ __forceinline__ void mma16816(float* d, const uint32_t* a, const uint32_t* b) {
    asm volatile(
        "mma.sync.aligned.m16n8k16.row.col.f32.bf16.bf16.f32 "
        "{%0,%1,%2,%3}, {%4,%5,%6,%7}, {%8,%9}, {%0,%1,%2,%3};"
        : "+f"(d[0]), "+f"(d[1]), "+f"(d[2]), "+f"(d[3])
        : "r"(a[0]), "r"(a[1]), "r"(a[2]), "r"(a[3]), "r"(b[0]), "r"(b[1]));
}
__device__ __forceinline__ uint32_t smem_u32(const void* p) {
    uint32_t a;
    asm("{ .reg .u64 t; cvta.to.shared.u64 t, %1; cvt.u32.u64 %0, t; }" : "=r"(a) : "l"(p));
    return a;
}
__device__ __forceinline__ unsigned mono(float v) {
    unsigned u = __float_as_uint(v);
    return (u & 0x80000000u) ? ~u : (u | 0x80000000u);
}
__device__ __forceinline__ float unmono(unsigned m) {
    unsigned u = (m & 0x80000000u) ? (m ^ 0x80000000u) : ~m;
    return __uint_as_float(u);
}
#define CPA(dst, src, n) \
    asm volatile("cp.async.cg.shared.global [%0], [%1], 16, %2;" \
                 :: "r"(dst), "l"(src), "r"(n))
#define CPA_COMMIT() asm volatile("cp.async.commit_group;" ::: "memory")
#define CPA_WAIT1()  asm volatile("cp.async.wait_group 1;" ::: "memory")
#define CPA_WAIT0()  asm volatile("cp.async.wait_group 0;" ::: "memory")

// register insertion into sorted KNN list (strict < keeps lowest idx on ties)
#define INS(keys, kidx, v, ix) do { \
    if ((v) < keys[KNN - 1]) { \
        float _cv = (v); int _ci = (ix); \
        _Pragma("unroll") \
        for (int _j = 0; _j < KNN; ++_j) { \
            if (_cv < keys[_j]) { \
                float _tv = keys[_j]; keys[_j] = _cv; _cv = _tv; \
                int _ti = kidx[_j]; kidx[_j] = _ci; _ci = _ti; \
            } \
        } \
    } } while (0)

#define MMA_SMEM (2 * 2 * 128 * LDP * 2)

// =================== cp.async-pipelined mma.sync GEMM, 128x128 tile ===============
// mode 0: out[m][o] = acc + bias[o]  (leaky if act)
// mode 1: out[m][o] = xx[m] - 2*acc + xx[o]; also emits 32-col subtile row-mins
__global__ void __launch_bounds__(256)
mma_gemm(const __nv_bfloat16* __restrict__ A3, int lda3, size_t zsA,
         const __nv_bfloat16* __restrict__ B3, int ldb3, size_t zsB,
         int Nvalid, int K3,
         float* __restrict__ out, int ldo, size_t zsO,
         const float* __restrict__ bias, int act,
         int mode, const float* __restrict__ xx, int zsXX,
         float* __restrict__ submin) {
    extern __shared__ __nv_bfloat16 sm[];
    int tid = threadIdx.x;
    int wid = tid >> 5, lane = tid & 31;
    int wr = wid & 3, wc = wid >> 2;
    int gr = lane >> 2, tg = lane & 3;

    int m0 = blockIdx.y * 128, o0 = blockIdx.x * 128;
    const __nv_bfloat16* Ab = A3 + blockIdx.z * zsA;
    const __nv_bfloat16* Bb = B3 + blockIdx.z * zsB;
    uint32_t sbase = smem_u32(sm);
    int nch = K3 / 64;

    auto issue = [&](int s, int k0) {
#pragma unroll
        for (int i = 0; i < 4; ++i) {
            int e = tid + i * 256;
            int row = e >> 3, seg = e & 7;
            uint32_t da = sbase + (uint32_t)(s * 2 * 128 * LDP + row * LDP + seg * 8) * 2;
            CPA(da, Ab + (size_t)(m0 + row) * lda3 + k0 + seg * 8, 16);
            int brow = o0 + row;
            int srow = brow < Nvalid ? brow : (Nvalid - 1);
            uint32_t db = sbase + (uint32_t)((s * 2 + 1) * 128 * LDP + row * LDP + seg * 8) * 2;
            CPA(db, Bb + (size_t)srow * ldb3 + k0 + seg * 8, brow < Nvalid ? 16 : 0);
        }
        CPA_COMMIT();
    };

    float acc[2][8][4] = {};
    issue(0, 0);
    for (int ch = 0; ch < nch; ++ch) {
        if (ch + 1 < nch) { issue((ch + 1) & 1, (ch + 1) * 64); CPA_WAIT1(); }
        else              { CPA_WAIT0(); }
        __syncthreads();
        const __nv_bfloat16 (*As)[LDP] =
            (const __nv_bfloat16(*)[LDP])(sm + (ch & 1) * 2 * 128 * LDP);
        const __nv_bfloat16 (*Bs)[LDP] = As + 128;
#pragma unroll
        for (int kk = 0; kk < 64; kk += 16) {
            uint32_t af[2][4], bfr[8][2];
#pragma unroll
            for (int mi = 0; mi < 2; ++mi) {
                const __nv_bfloat16* pa = &As[wr * 32 + mi * 16 + gr][kk + tg * 2];
                af[mi][0] = *(const uint32_t*)pa;
                af[mi][1] = *(const uint32_t*)(pa + 8 * LDP);
                af[mi][2] = *(const uint32_t*)(pa + 8);
                af[mi][3] = *(const uint32_t*)(pa + 8 * LDP + 8);
            }
#pragma unroll
            for (int ni = 0; ni < 8; ++ni) {
                const __nv_bfloat16* pb = &Bs[wc * 64 + ni * 8 + gr][kk + tg * 2];
                bfr[ni][0] = *(const uint32_t*)pb;
                bfr[ni][1] = *(const uint32_t*)(pb + 8);
            }
#pragma unroll
            for (int mi = 0; mi < 2; ++mi)
#pragma unroll
                for (int ni = 0; ni < 8; ++ni)
                    mma16816(acc[mi][ni], af[mi], bfr[ni]);
        }
        __syncthreads();
    }

    float* outb = out + blockIdx.z * zsO;
    const float* xxb = (mode == 1) ? xx + (size_t)blockIdx.z * zsXX : nullptr;
    float rmn[2][2][2];
#pragma unroll
    for (int i = 0; i < 2; ++i)
#pragma unroll
        for (int j = 0; j < 2; ++j) { rmn[i][j][0] = FLT_MAX; rmn[i][j][1] = FLT_MAX; }

#pragma unroll
    for (int mi = 0; mi < 2; ++mi) {
        int mA = m0 + wr * 32 + mi * 16 + gr;
        float xrA = 0.f, xrB = 0.f;
        if (mode == 1) { xrA = xxb[mA]; xrB = xxb[mA + 8]; }
#pragma unroll
        for (int ni = 0; ni < 8; ++ni) {
            int o = o0 + wc * 64 + ni * 8 + tg * 2;
            if (o < Nvalid) {
                float u0 = acc[mi][ni][0], u1 = acc[mi][ni][1];
                float u2 = acc[mi][ni][2], u3 = acc[mi][ni][3];
                if (mode == 0) {
                    float b0 = bias ? bias[o] : 0.f, b1 = bias ? bias[o + 1] : 0.f;
                    u0 += b0; u1 += b1; u2 += b0; u3 += b1;
                    if (act) {
                        u0 = u0 > 0.f ? u0 : 0.2f * u0;
                        u1 = u1 > 0.f ? u1 : 0.2f * u1;
                        u2 = u2 > 0.f ? u2 : 0.2f * u2;
                        u3 = u3 > 0.f ? u3 : 0.2f * u3;
                    }
                } else {
                    float xc0 = xxb[o], xc1 = xxb[o + 1];
                    u0 = xrA - 2.f * u0 + xc0; u1 = xrA - 2.f * u1 + xc1;
                    u2 = xrB - 2.f * u2 + xc0; u3 = xrB - 2.f * u3 + xc1;
                    int s = ni >> 2;
                    rmn[mi][s][0] = fminf(rmn[mi][s][0], fminf(u0, u1));
                    rmn[mi][s][1] = fminf(rmn[mi][s][1], fminf(u2, u3));
                }
                *(float2*)(outb + (size_t)mA * ldo + o)       = make_float2(u0, u1);
                *(float2*)(outb + (size_t)(mA + 8) * ldo + o) = make_float2(u2, u3);
            }
        }
    }
    if (mode == 1) {
        float* sb = submin + (size_t)blockIdx.z * NN * 64;
#pragma unroll
        for (int mi = 0; mi < 2; ++mi)
#pragma unroll
            for (int s = 0; s < 2; ++s)
#pragma unroll
                for (int rr = 0; rr < 2; ++rr) {
                    float v = rmn[mi][s][rr];
                    v = fminf(v, __shfl_xor_sync(0xffffffffu, v, 1));
                    v = fminf(v, __shfl_xor_sync(0xffffffffu, v, 2));
                    if (tg == 0) {
                        int grow = m0 + wr * 32 + mi * 16 + gr + rr * 8;
                        sb[(size_t)grow * 64 + blockIdx.x * 4 + wc * 2 + s] = v;
                    }
                }
    }
}

// =================== threshold-filter top-K, bitonic select (exact) ===============
// Phase 1: bitonic-sort 64 subtile-mins -> T = rank-19 (20th smallest).
// Phase 2: scan only subtiles with min <= T (coalesced 128B loads).
// Phase 3: bitonic-sort <=128 (val,idx) u64 keys -> ranks 0..19 stored coalesced.
__global__ void __launch_bounds__(256, 4)
topk_sel(const float* __restrict__ d2, const float* __restrict__ submin,
         int* __restrict__ idxout, int* __restrict__ ovflag) {
    __shared__ unsigned long long fl[8][CAP];
    __shared__ int cnt[8];
    int w = threadIdx.x >> 5, lane = threadIdx.x & 31;
    const unsigned FM = 0xffffffffu;
    size_t row = (size_t)blockIdx.x * 8 + w;
    const float* r = d2 + row * NN;

    if (lane == 0) cnt[w] = 0;
    fl[w][lane] = ~0ULL; fl[w][lane + 32] = ~0ULL;
    fl[w][lane + 64] = ~0ULL; fl[w][lane + 96] = ~0ULL;
    __syncwarp();

    // ---- phase 1: bitonic sort of 64 submins (2 u32/lane), T = rank 19 ----
    float s0f = submin[row * 64 + lane];
    float s1f = submin[row * 64 + 32 + lane];
    unsigned sv[2] = { mono(s0f), mono(s1f) };
#pragma unroll
    for (unsigned k = 2; k <= 64; k <<= 1) {
#pragma unroll
        for (unsigned d = 32; d; d >>= 1) {
            if (d >= k) continue;
            if (d == 32) {   // cross-register (only when k == 64, dir ascending)
                unsigned a = sv[0], b = sv[1];
                sv[0] = a < b ? a : b;
                sv[1] = a < b ? b : a;
            } else {
#pragma unroll
                for (int j = 0; j < 2; ++j) {
                    unsigned v = j * 32 + lane;
                    unsigned o = __shfl_xor_sync(FM, sv[j], d);
                    bool dir = ((v & k) == 0);
                    bool lower = ((lane & d) == 0);
                    bool takeMin = (lower == dir);
                    unsigned mn = o < sv[j] ? o : sv[j];
                    unsigned mx = o < sv[j] ? sv[j] : o;
                    sv[j] = takeMin ? mn : mx;
                }
            }
        }
    }
    unsigned T = __shfl_sync(FM, sv[0], 19);
    float Tf = unmono(T);

    // ---- phase 2: scan ONLY qualifying subtiles (submin <= Tf) ----
    unsigned mask0 = __ballot_sync(FM, s0f <= Tf);
    unsigned mask1 = __ballot_sync(FM, s1f <= Tf);
    while (mask0) {
        int s = __ffs(mask0) - 1; mask0 &= mask0 - 1;
        int e = s * 32 + lane;
        float v = r[e];
        if (v <= Tf) {
            int p = atomicAdd(&cnt[w], 1);
            if (p < CAP) fl[w][p] = ((unsigned long long)mono(v) << 32) | (unsigned)e;
        }
    }
    while (mask1) {
        int s = 32 + __ffs(mask1) - 1; mask1 &= mask1 - 1;
        int e = s * 32 + lane;
        float v = r[e];
        if (v <= Tf) {
            int p = atomicAdd(&cnt[w], 1);
            if (p < CAP) fl[w][p] = ((unsigned long long)mono(v) << 32) | (unsigned)e;
        }
    }
    __syncwarp();

    int ov = cnt[w] > CAP;
    if (lane == 0) ovflag[row] = ov;
    if (ov) return;                       // exact fallback kernel handles this row

    // ---- phase 3: bitonic sort of 128 u64 keys (4/lane); ranks 0..19 out ----
    unsigned long long cv[4] = { fl[w][lane], fl[w][lane + 32],
                                 fl[w][lane + 64], fl[w][lane + 96] };
#pragma unroll
    for (unsigned k = 2; k <= 128; k <<= 1) {
#pragma unroll
        for (unsigned d = 64; d; d >>= 1) {
            if (d >= k) continue;
            if (d >= 32) {   // cross-register compare (same lane)
                int dj = d >> 5;   // 1 or 2
#pragma unroll
                for (int j = 0; j < 4; ++j) {
                    if (j & dj) continue;
                    unsigned v = j * 32 + lane;
                    bool dir = ((v & k) == 0);
                    unsigned long long a = cv[j], b = cv[j ^ dj];
                    unsigned long long mn = a < b ? a : b;
                    unsigned long long mx = a < b ? b : a;
                    cv[j]      = dir ? mn : mx;
                    cv[j ^ dj] = dir ? mx : mn;
                }
            } else {
#pragma unroll
                for (int j = 0; j < 4; ++j) {
                    unsigned v = j * 32 + lane;
                    unsigned long long o = __shfl_xor_sync(FM, cv[j], d);
                    bool dir = ((v & k) == 0);
                    bool lower = ((lane & d) == 0);
                    bool takeMin = (lower == dir);
                    unsigned long long mn = o < cv[j] ? o : cv[j];
                    unsigned long long mx = o < cv[j] ? cv[j] : o;
                    cv[j] = takeMin ? mn : mx;
                }
            }
        }
    }
    if (lane < KNN)
        idxout[row * KNN + lane] = (int)(cv[0] & 0xffffffffu);
}

// =================== exact fallback for overflow rows (rare / usually idle) ========
__global__ void __launch_bounds__(256)
topk_fb(const float* __restrict__ d2, const int* __restrict__ ovflag,
        int* __restrict__ idxout) {
    __shared__ unsigned long long fb[8][32 * KNN];
    int w = threadIdx.x >> 5, lane = threadIdx.x & 31;
    const unsigned FM = 0xffffffffu;
    size_t row = (size_t)blockIdx.x * 8 + w;
    if (!ovflag[row]) return;
    const float* r = d2 + row * NN;

    float key[KNN]; int ki[KNN];
#pragma unroll
    for (int j = 0; j < KNN; ++j) { key[j] = FLT_MAX; ki[j] = 0; }
    for (int j = 0; j < 16; ++j) {
        int e0 = 4 * (j * 32 + lane);
        float4 v4 = *(const float4*)(r + e0);
        float vmin = fminf(fminf(v4.x, v4.y), fminf(v4.z, v4.w));
        if (vmin < key[KNN - 1]) {
            float vals[4] = {v4.x, v4.y, v4.z, v4.w};
#pragma unroll
            for (int q = 0; q < 4; ++q) INS(key, ki, vals[q], e0 + q);
        }
    }
#pragma unroll
    for (int j = 0; j < KNN; ++j)
        fb[w][lane * KNN + j] = ((unsigned long long)mono(key[j]) << 32) | (unsigned)ki[j];
    __syncwarp();
    int h = 0;
    unsigned long long hv = fb[w][lane * KNN];
#pragma unroll
    for (int k = 0; k < KNN; ++k) {
        unsigned long long red = hv;
#pragma unroll
        for (int off = 16; off; off >>= 1) {
            unsigned long long o = __shfl_xor_sync(FM, red, off);
            red = o < red ? o : red;
        }
        if (lane == 0) idxout[row * KNN + k] = (int)(red & 0xffffffffu);
        if (hv == red) { ++h; hv = (h < KNN) ? fb[w][lane * KNN + h] : ~0ULL; }
    }
}

// =================== small kernels ===================
// warp-per-row squared norms (coalesced)
__global__ void xx_kernel(const float* __restrict__ X, int ldx, int C,
                          float* __restrict__ xx) {
    int w = threadIdx.x >> 5, lane = threadIdx.x & 31;
    int row = blockIdx.x * 8 + w;
    if (row >= BB * NN) return;
    const float* p = X + (size_t)row * ldx;
    float s = 0.f;
    for (int c = lane; c < C; c += 32) { float v = p[c]; s += v * v; }
#pragma unroll
    for (int off = 16; off; off >>= 1)
        s += __shfl_xor_sync(0xffffffffu, s, off);
    if (lane == 0) xx[row] = s;
}

// h[n,o] = leaky(max_k y[j_k,o] - y[n,o] + c[n,o])   (leaky/max commute)
__global__ void edgemax4(const float* __restrict__ yc, const int* __restrict__ idx,
                         float* __restrict__ out, int O, int ldo) {
    __shared__ int sid[KNN];
    int b = blockIdx.y, n = blockIdx.x;
    int t = threadIdx.x;
    for (int i = t; i < KNN; i += blockDim.x)
        sid[i] = idx[((size_t)b * NN + n) * KNN + i];
    __syncthreads();
    size_t mbase = (size_t)b * NN;
    int ld2 = 2 * O;
    float4 m = make_float4(-FLT_MAX, -FLT_MAX, -FLT_MAX, -FLT_MAX);
#pragma unroll
    for (int k = 0; k < KNN; ++k) {
        float4 yn = *(const float4*)(yc + (mbase + sid[k]) * ld2 + 4 * t);
        m.x = fmaxf(m.x, yn.x); m.y = fmaxf(m.y, yn.y);
        m.z = fmaxf(m.z, yn.z); m.w = fmaxf(m.w, yn.w);
    }
    const float* prow = yc + (mbase + n) * ld2 + 4 * t;
    float4 ycn = *(const float4*)prow;
    float4 ccn = *(const float4*)(prow + O);
    float v0 = m.x - ycn.x + ccn.x;
    float v1 = m.y - ycn.y + ccn.y;
    float v2 = m.z - ycn.z + ccn.z;
    float v3 = m.w - ycn.w + ccn.w;
    v0 = v0 > 0.f ? v0 : 0.2f * v0;
    v1 = v1 > 0.f ? v1 : 0.2f * v1;
    v2 = v2 > 0.f ? v2 : 0.2f * v2;
    v3 = v3 > 0.f ? v3 : 0.2f * v3;
    *(float4*)(out + (mbase + n) * ldo + 4 * t) = make_float4(v0, v1, v2, v3);
}

// two-stage global max pool over N
__global__ void maxpool1(const float* __restrict__ tmp, float* __restrict__ part) {
    int b = blockIdx.y, c = blockIdx.z;
    int f = blockIdx.x * blockDim.x + threadIdx.x;
    const float* p = tmp + ((size_t)b * NN + c * 128) * 1024 + f;
    float m = -FLT_MAX;
#pragma unroll 4
    for (int n = 0; n < 128; ++n) m = fmaxf(m, p[(size_t)n * 1024]);
    part[(c * BB + b) * 1024 + f] = m;
}
__global__ void maxpool2(const float* __restrict__ part, float* __restrict__ out) {
    int b = blockIdx.y;
    int f = blockIdx.x * blockDim.x + threadIdx.x;
    float m = -FLT_MAX;
#pragma unroll
    for (int c = 0; c < 16; ++c) m = fmaxf(m, part[(c * BB + b) * 1024 + f]);
    out[b * 1024 + f] = m;
}

// =================== launch ===================
extern "C" void kernel_launch(void* const* d_in, const int* in_sizes, int n_in,
                              void* d_out, int out_size) {
    const float* x     = (const float*)d_in[0];
    const float* Wl[4] = {(const float*)d_in[1], (const float*)d_in[3],
                          (const float*)d_in[5], (const float*)d_in[7]};
    const float* bl[4] = {(const float*)d_in[2], (const float*)d_in[4],
                          (const float*)d_in[6], (const float*)d_in[8]};
    const float* Wf = (const float*)d_in[9];
    const float* bf = (const float*)d_in[10];
    float* out = (float*)d_out;

    float *p_d2, *p_sub, *p_xx, *p_yc, *p_hcat, *p_tmp, *p_part, *p_bias2;
    __nv_bfloat16 *p_a3, *p_b3, *p_bf3, *p_w3;
    int *p_idx, *p_ov;
    cudaGetSymbolAddress((void**)&p_d2,    g_d2);
    cudaGetSymbolAddress((void**)&p_sub,   g_submin);
    cudaGetSymbolAddress((void**)&p_xx,    g_xx);
    cudaGetSymbolAddress((void**)&p_idx,   g_idx);
    cudaGetSymbolAddress((void**)&p_ov,    g_ov);
    cudaGetSymbolAddress((void**)&p_yc,    g_yc);
    cudaGetSymbolAddress((void**)&p_hcat,  g_hcat);
    cudaGetSymbolAddress((void**)&p_tmp,   g_tmp);
    cudaGetSymbolAddress((void**)&p_part,  g_part);
    cudaGetSymbolAddress((void**)&p_bias2, g_bias2);
    cudaGetSymbolAddress((void**)&p_a3,    g_a3);
    cudaGetSymbolAddress((void**)&p_b3,    g_b3);
    cudaGetSymbolAddress((void**)&p_bf3,   g_bf3);
    cudaGetSymbolAddress((void**)&p_w3,    g_w3);

    cudaFuncSetAttribute(mma_gemm, cudaFuncAttributeMaxDynamicSharedMemorySize,
                         MMA_SMEM);

    const int Cs[4]  = {3, 64, 64, 128};
    const int Os[4]  = {64, 64, 128, 256};
    const int off[4] = {0, 64, 128, 256};

    const float* Xin = x;
    int ldx = 3;
    for (int l = 0; l < 4; ++l) {
        int C = Cs[l], O = Os[l];
        int K3 = ((3 * C + 63) / 64) * 64;     // 64, 192, 192, 384

        xx_kernel<<<(BB * NN) / 8, 256>>>(Xin, ldx, C, p_xx);
        convAB_kernel<<<dim3((K3 + 255) / 256, BB * NN), 256>>>(
            Xin, ldx, C, p_a3, p_b3, K3);
        // pairwise d2 + subtile mins (batched over z)
        mma_gemm<<<dim3(16, 16, BB), 256, MMA_SMEM>>>(
            p_a3, K3, (size_t)NN * K3, p_b3, K3, (size_t)NN * K3,
            NN, K3, p_d2, NN, (size_t)NN * NN, nullptr, 0, 1, p_xx, NN, p_sub);
        topk_sel<<<(BB * NN) / 8, 256>>>(p_d2, p_sub, p_idx, p_ov);
        topk_fb<<<(BB * NN) / 8, 256>>>(p_d2, p_ov, p_idx);
        // combined yc = X * [Wy|Wc]^T + [0|b]
        convB_kernel<<<dim3((K3 + 255) / 256, O), 256>>>(Wl[l], 2 * C, C, p_w3, K3);
        convB_kernel<<<dim3((K3 + 255) / 256, O), 256>>>(Wl[l] + C, 2 * C, C,
                                                         p_w3 + (size_t)O * K3, K3);
        biascat<<<1, 512>>>(bl[l], p_bias2, O);
        mma_gemm<<<dim3((2 * O + 127) / 128, (BB * NN) / 128, 1), 256, MMA_SMEM>>>(
            p_a3, K3, 0, p_w3, K3, 0, 2 * O, K3,
            p_yc, 2 * O, 0, p_bias2, 0, 0, nullptr, 0, nullptr);
        edgemax4<<<dim3(NN, BB), O / 4>>>(p_yc, p_idx, p_hcat + off[l], O, 512);
        Xin = p_hcat + off[l];
        ldx = 512;
    }
    // final 512 -> 1024 linear + leaky, then max over N (two-stage pool)
    convA_kernel<<<dim3(1536 / 256, BB * NN), 256>>>(p_hcat, 512, 512, p_a3, 1536);
    convB_kernel<<<dim3(1536 / 256, 1024), 256>>>(Wf, 512, 512, p_bf3, 1536);
    mma_gemm<<<dim3(1024 / 128, (BB * NN) / 128, 1), 256, MMA_SMEM>>>(
        p_a3, 1536, 0, p_bf3, 1536, 0, 1024, 1536,
        p_tmp, 1024, 0, bf, 1, 0, nullptr, 0, nullptr);
    maxpool1<<<dim3(1024 / 256, BB, 16), 256>>>(p_tmp, p_part);
    maxpool2<<<dim3(1024 / 256, BB), 256>>>(p_part, out);
}

// round 13
// speedup vs baseline: 2.6068x; 1.0808x over previous
#include <cuda_runtime.h>
#include <cuda_bf16.h>
#include <float.h>
#include <math.h>
#include <cstdint>

#define BB  8
#define NN  2048
#define KNN 20
#define CAP 128   // candidate cap per row before fallback (= bitonic width)

// ---------------- scratch (device globals; no allocations) ----------------
__device__ __align__(16) float g_d2[(size_t)BB * NN * NN];
__device__ __align__(16) float g_submin[(size_t)BB * NN * 64];
__device__ __align__(16) float g_xx[BB * NN];
__device__ __align__(16) int   g_idx[BB * NN * KNN];
__device__ __align__(16) int   g_ov[BB * NN];
__device__ __align__(16) float g_yc[(size_t)BB * NN * 512];    // y | c combined
__device__ __align__(16) float g_hcat[(size_t)BB * NN * 512];
__device__ __align__(16) float g_tmp[(size_t)BB * NN * 1024];
__device__ __align__(16) float g_part[16 * BB * 1024];
__device__ __align__(16) float g_bias2[512];
__device__ __align__(16) __nv_bfloat16 g_a3[(size_t)BB * NN * 1536];  // split A (h|l|h)
__device__ __align__(16) __nv_bfloat16 g_b3[(size_t)BB * NN * 384];   // split B (h|h|l)
__device__ __align__(16) __nv_bfloat16 g_bf3[1024 * 1536];            // split Wf
__device__ __align__(16) __nv_bfloat16 g_w3[512 * 384];               // split layer W (y|c)

// =================== split-precision conversion kernels ===================
__global__ void convAB_kernel(const float* __restrict__ in, int ld, int C,
                              __nv_bfloat16* __restrict__ a3,
                              __nv_bfloat16* __restrict__ b3, int K3) {
    int r = blockIdx.y;
    int c = blockIdx.x * 256 + threadIdx.x;
    if (c >= K3) return;
    size_t ro = (size_t)r * K3;
    if (c < C) {
        float xv = in[(size_t)r * ld + c];
        __nv_bfloat16 h = __float2bfloat16(xv);
        __nv_bfloat16 l = __float2bfloat16(xv - __bfloat162float(h));
        a3[ro + c] = h; a3[ro + C + c] = l; a3[ro + 2 * C + c] = h;
        b3[ro + c] = h; b3[ro + C + c] = h; b3[ro + 2 * C + c] = l;
    } else if (c >= 3 * C) {
        __nv_bfloat16 z = __float2bfloat16(0.f);
        a3[ro + c] = z; b3[ro + c] = z;
    }
}
__global__ void convA_kernel(const float* __restrict__ in, int ld, int C,
                             __nv_bfloat16* __restrict__ out, int K3) {
    int r = blockIdx.y;
    int c = blockIdx.x * 256 + threadIdx.x;
    if (c >= K3) return;
    size_t ro = (size_t)r * K3;
    if (c < C) {
        float xv = in[(size_t)r * ld + c];
        __nv_bfloat16 h = __float2bfloat16(xv);
        __nv_bfloat16 l = __float2bfloat16(xv - __bfloat162float(h));
        out[ro + c] = h; out[ro + C + c] = l; out[ro + 2 * C + c] = h;
    } else if (c >= 3 * C) {
        out[ro + c] = __float2bfloat16(0.f);
    }
}
__global__ void convB_kernel(const float* __restrict__ in, int ld, int C,
                             __nv_bfloat16* __restrict__ out, int K3) {
    int r = blockIdx.y;
    int c = blockIdx.x * 256 + threadIdx.x;
    if (c >= K3) return;
    size_t ro = (size_t)r * K3;
    if (c < C) {
        float xv = in[(size_t)r * ld + c];
        __nv_bfloat16 h = __float2bfloat16(xv);
        __nv_bfloat16 l = __float2bfloat16(xv - __bfloat162float(h));
        out[ro + c] = h; out[ro + C + c] = h; out[ro + 2 * C + c] = l;
    } else if (c >= 3 * C) {
        out[ro + c] = __float2bfloat16(0.f);
    }
}
__global__ void biascat(const float* __restrict__ bl, float* __restrict__ out, int O) {
    int i = threadIdx.x;
    if (i < O) out[i] = 0.f;
    else if (i < 2 * O) out[i] = bl[i - O];
}

#define LDP 72

__device__ __forceinline__ void mma16816(float* d, const uint32_t* a, const uint32_t* b) {
    asm volatile(
        "mma.sync.aligned.m16n8k16.row.col.f32.bf16.bf16.f32 "
        "{%0,%1,%2,%3}, {%4,%5,%6,%7}, {%8,%9}, {%0,%1,%2,%3};"
        : "+f"(d[0]), "+f"(d[1]), "+f"(d[2]), "+f"(d[3])
        : "r"(a[0]), "r"(a[1]), "r"(a[2]), "r"(a[3]), "r"(b[0]), "r"(b[1]));
}
__device__ __forceinline__ uint32_t smem_u32(const void* p) {
    uint32_t a;
    asm("{ .reg .u64 t; cvta.to.shared.u64 t, %1; cvt.u32.u64 %0, t; }" : "=r"(a) : "l"(p));
    return a;
}
__device__ __forceinline__ unsigned mono(float v) {
    unsigned u = __float_as_uint(v);
    return (u & 0x80000000u) ? ~u : (u | 0x80000000u);
}
__device__ __forceinline__ float unmono(unsigned m) {
    unsigned u = (m & 0x80000000u) ? (m ^ 0x80000000u) : ~m;
    return __uint_as_float(u);
}
#define CPA(dst, src, n) \
    asm volatile("cp.async.cg.shared.global [%0], [%1], 16, %2;" \
                 :: "r"(dst), "l"(src), "r"(n))
#define CPA_COMMIT() asm volatile("cp.async.commit_group;" ::: "memory")
#define CPA_WAIT1()  asm volatile("cp.async.wait_group 1;" ::: "memory")
#define CPA_WAIT0()  asm volatile("cp.async.wait_group 0;" ::: "memory")

// register insertion into sorted KNN list (strict < keeps lowest idx on ties)
#define INS(keys, kidx, v, ix) do { \
    if ((v) < keys[KNN - 1]) { \
        float _cv = (v); int _ci = (ix); \
        _Pragma("unroll") \
        for (int _j = 0; _j < KNN; ++_j) { \
            if (_cv < keys[_j]) { \
                float _tv = keys[_j]; keys[_j] = _cv; _cv = _tv; \
                int _ti = kidx[_j]; kidx[_j] = _ci; _ci = _ti; \
            } \
        } \
    } } while (0)

#define MMA_SMEM (2 * 2 * 128 * LDP * 2)

// =================== cp.async-pipelined mma.sync GEMM, 128x128 tile ===============
// mode 0: out[m][o] = acc + bias[o]  (leaky if act)
// mode 1: out[m][o] = xx[m] - 2*acc + xx[o]; also emits 32-col subtile row-mins
__global__ void __launch_bounds__(256)
mma_gemm(const __nv_bfloat16* __restrict__ A3, int lda3, size_t zsA,
         const __nv_bfloat16* __restrict__ B3, int ldb3, size_t zsB,
         int Nvalid, int K3,
         float* __restrict__ out, int ldo, size_t zsO,
         const float* __restrict__ bias, int act,
         int mode, const float* __restrict__ xx, int zsXX,
         float* __restrict__ submin) {
    extern __shared__ __nv_bfloat16 sm[];
    int tid = threadIdx.x;
    int wid = tid >> 5, lane = tid & 31;
    int wr = wid & 3, wc = wid >> 2;
    int gr = lane >> 2, tg = lane & 3;

    int m0 = blockIdx.y * 128, o0 = blockIdx.x * 128;
    const __nv_bfloat16* Ab = A3 + blockIdx.z * zsA;
    const __nv_bfloat16* Bb = B3 + blockIdx.z * zsB;
    uint32_t sbase = smem_u32(sm);
    int nch = K3 / 64;

    auto issue = [&](int s, int k0) {
#pragma unroll
        for (int i = 0; i < 4; ++i) {
            int e = tid + i * 256;
            int row = e >> 3, seg = e & 7;
            uint32_t da = sbase + (uint32_t)(s * 2 * 128 * LDP + row * LDP + seg * 8) * 2;
            CPA(da, Ab + (size_t)(m0 + row) * lda3 + k0 + seg * 8, 16);
            int brow = o0 + row;
            int srow = brow < Nvalid ? brow : (Nvalid - 1);
            uint32_t db = sbase + (uint32_t)((s * 2 + 1) * 128 * LDP + row * LDP + seg * 8) * 2;
            CPA(db, Bb + (size_t)srow * ldb3 + k0 + seg * 8, brow < Nvalid ? 16 : 0);
        }
        CPA_COMMIT();
    };

    float acc[2][8][4] = {};
    issue(0, 0);
    for (int ch = 0; ch < nch; ++ch) {
        if (ch + 1 < nch) { issue((ch + 1) & 1, (ch + 1) * 64); CPA_WAIT1(); }
        else              { CPA_WAIT0(); }
        __syncthreads();
        const __nv_bfloat16 (*As)[LDP] =
            (const __nv_bfloat16(*)[LDP])(sm + (ch & 1) * 2 * 128 * LDP);
        const __nv_bfloat16 (*Bs)[LDP] = As + 128;
#pragma unroll
        for (int kk = 0; kk < 64; kk += 16) {
            uint32_t af[2][4], bfr[8][2];
#pragma unroll
            for (int mi = 0; mi < 2; ++mi) {
                const __nv_bfloat16* pa = &As[wr * 32 + mi * 16 + gr][kk + tg * 2];
                af[mi][0] = *(const uint32_t*)pa;
                af[mi][1] = *(const uint32_t*)(pa + 8 * LDP);
                af[mi][2] = *(const uint32_t*)(pa + 8);
                af[mi][3] = *(const uint32_t*)(pa + 8 * LDP + 8);
            }
#pragma unroll
            for (int ni = 0; ni < 8; ++ni) {
                const __nv_bfloat16* pb = &Bs[wc * 64 + ni * 8 + gr][kk + tg * 2];
                bfr[ni][0] = *(const uint32_t*)pb;
                bfr[ni][1] = *(const uint32_t*)(pb + 8);
            }
#pragma unroll
            for (int mi = 0; mi < 2; ++mi)
#pragma unroll
                for (int ni = 0; ni < 8; ++ni)
                    mma16816(acc[mi][ni], af[mi], bfr[ni]);
        }
        __syncthreads();
    }

    float* outb = out + blockIdx.z * zsO;
    const float* xxb = (mode == 1) ? xx + (size_t)blockIdx.z * zsXX : nullptr;
    float rmn[2][2][2];
#pragma unroll
    for (int i = 0; i < 2; ++i)
#pragma unroll
        for (int j = 0; j < 2; ++j) { rmn[i][j][0] = FLT_MAX; rmn[i][j][1] = FLT_MAX; }

#pragma unroll
    for (int mi = 0; mi < 2; ++mi) {
        int mA = m0 + wr * 32 + mi * 16 + gr;
        float xrA = 0.f, xrB = 0.f;
        if (mode == 1) { xrA = xxb[mA]; xrB = xxb[mA + 8]; }
#pragma unroll
        for (int ni = 0; ni < 8; ++ni) {
            int o = o0 + wc * 64 + ni * 8 + tg * 2;
            if (o < Nvalid) {
                float u0 = acc[mi][ni][0], u1 = acc[mi][ni][1];
                float u2 = acc[mi][ni][2], u3 = acc[mi][ni][3];
                if (mode == 0) {
                    float b0 = bias ? bias[o] : 0.f, b1 = bias ? bias[o + 1] : 0.f;
                    u0 += b0; u1 += b1; u2 += b0; u3 += b1;
                    if (act) {
                        u0 = u0 > 0.f ? u0 : 0.2f * u0;
                        u1 = u1 > 0.f ? u1 : 0.2f * u1;
                        u2 = u2 > 0.f ? u2 : 0.2f * u2;
                        u3 = u3 > 0.f ? u3 : 0.2f * u3;
                    }
                } else {
                    float xc0 = xxb[o], xc1 = xxb[o + 1];
                    u0 = xrA - 2.f * u0 + xc0; u1 = xrA - 2.f * u1 + xc1;
                    u2 = xrB - 2.f * u2 + xc0; u3 = xrB - 2.f * u3 + xc1;
                    int s = ni >> 2;
                    rmn[mi][s][0] = fminf(rmn[mi][s][0], fminf(u0, u1));
                    rmn[mi][s][1] = fminf(rmn[mi][s][1], fminf(u2, u3));
                }
                *(float2*)(outb + (size_t)mA * ldo + o)       = make_float2(u0, u1);
                *(float2*)(outb + (size_t)(mA + 8) * ldo + o) = make_float2(u2, u3);
            }
        }
    }
    if (mode == 1) {
        float* sb = submin + (size_t)blockIdx.z * NN * 64;
#pragma unroll
        for (int mi = 0; mi < 2; ++mi)
#pragma unroll
            for (int s = 0; s < 2; ++s)
#pragma unroll
                for (int rr = 0; rr < 2; ++rr) {
                    float v = rmn[mi][s][rr];
                    v = fminf(v, __shfl_xor_sync(0xffffffffu, v, 1));
                    v = fminf(v, __shfl_xor_sync(0xffffffffu, v, 2));
                    if (tg == 0) {
                        int grow = m0 + wr * 32 + mi * 16 + gr + rr * 8;
                        sb[(size_t)grow * 64 + blockIdx.x * 4 + wc * 2 + s] = v;
                    }
                }
    }
}

// =================== threshold-filter top-K, bitonic select (exact) ===============
// Phase 1: bitonic-sort 64 subtile-mins -> T = rank-19 (20th smallest).
// Phase 2: scan only subtiles with min <= T (coalesced 128B loads).
// Phase 3: fast path cnt<=32: 32-wide single-reg bitonic; else 128-wide 4-reg.
__global__ void __launch_bounds__(256, 4)
topk_sel(const float* __restrict__ d2, const float* __restrict__ submin,
         int* __restrict__ idxout, int* __restrict__ ovflag) {
    __shared__ unsigned long long fl[8][CAP];
    __shared__ int cnt[8];
    int w = threadIdx.x >> 5, lane = threadIdx.x & 31;
    const unsigned FM = 0xffffffffu;
    size_t row = (size_t)blockIdx.x * 8 + w;
    const float* r = d2 + row * NN;

    if (lane == 0) cnt[w] = 0;
    fl[w][lane] = ~0ULL; fl[w][lane + 32] = ~0ULL;
    fl[w][lane + 64] = ~0ULL; fl[w][lane + 96] = ~0ULL;
    __syncwarp();

    // ---- phase 1: bitonic sort of 64 submins (2 u32/lane), T = rank 19 ----
    float s0f = submin[row * 64 + lane];
    float s1f = submin[row * 64 + 32 + lane];
    unsigned sv[2] = { mono(s0f), mono(s1f) };
#pragma unroll
    for (unsigned k = 2; k <= 64; k <<= 1) {
#pragma unroll
        for (unsigned d = 32; d; d >>= 1) {
            if (d >= k) continue;
            if (d == 32) {
                unsigned a = sv[0], b = sv[1];
                sv[0] = a < b ? a : b;
                sv[1] = a < b ? b : a;
            } else {
#pragma unroll
                for (int j = 0; j < 2; ++j) {
                    unsigned v = j * 32 + lane;
                    unsigned o = __shfl_xor_sync(FM, sv[j], d);
                    bool dir = ((v & k) == 0);
                    bool lower = ((lane & d) == 0);
                    bool takeMin = (lower == dir);
                    unsigned mn = o < sv[j] ? o : sv[j];
                    unsigned mx = o < sv[j] ? sv[j] : o;
                    sv[j] = takeMin ? mn : mx;
                }
            }
        }
    }
    unsigned T = __shfl_sync(FM, sv[0], 19);
    float Tf = unmono(T);

    // ---- phase 2: scan ONLY qualifying subtiles (submin <= Tf) ----
    unsigned mask0 = __ballot_sync(FM, s0f <= Tf);
    unsigned mask1 = __ballot_sync(FM, s1f <= Tf);
    while (mask0) {
        int s = __ffs(mask0) - 1; mask0 &= mask0 - 1;
        int e = s * 32 + lane;
        float v = r[e];
        if (v <= Tf) {
            int p = atomicAdd(&cnt[w], 1);
            if (p < CAP) fl[w][p] = ((unsigned long long)mono(v) << 32) | (unsigned)e;
        }
    }
    while (mask1) {
        int s = 32 + __ffs(mask1) - 1; mask1 &= mask1 - 1;
        int e = s * 32 + lane;
        float v = r[e];
        if (v <= Tf) {
            int p = atomicAdd(&cnt[w], 1);
            if (p < CAP) fl[w][p] = ((unsigned long long)mono(v) << 32) | (unsigned)e;
        }
    }
    __syncwarp();

    int nc = cnt[w];
    int ov = nc > CAP;
    if (lane == 0) ovflag[row] = ov;
    if (ov) return;                       // exact fallback kernel handles this row

    if (nc <= 32) {
        // ---- phase 3 fast: bitonic sort 32 u64 keys (1/lane) ----
        unsigned long long c0 = fl[w][lane];
#pragma unroll
        for (unsigned k = 2; k <= 32; k <<= 1) {
#pragma unroll
            for (unsigned d = k >> 1; d; d >>= 1) {
                unsigned long long o = __shfl_xor_sync(FM, c0, d);
                bool dir = ((lane & k) == 0);
                bool lower = ((lane & d) == 0);
                bool takeMin = (lower == dir);
                unsigned long long mn = o < c0 ? o : c0;
                unsigned long long mx = o < c0 ? c0 : o;
                c0 = takeMin ? mn : mx;
            }
        }
        if (lane < KNN)
            idxout[row * KNN + lane] = (int)(c0 & 0xffffffffu);
        return;
    }

    // ---- phase 3 full: bitonic sort of 128 u64 keys (4/lane) ----
    unsigned long long cv[4] = { fl[w][lane], fl[w][lane + 32],
                                 fl[w][lane + 64], fl[w][lane + 96] };
#pragma unroll
    for (unsigned k = 2; k <= 128; k <<= 1) {
#pragma unroll
        for (unsigned d = 64; d; d >>= 1) {
            if (d >= k) continue;
            if (d >= 32) {
                int dj = d >> 5;
#pragma unroll
                for (int j = 0; j < 4; ++j) {
                    if (j & dj) continue;
                    unsigned v = j * 32 + lane;
                    bool dir = ((v & k) == 0);
                    unsigned long long a = cv[j], b = cv[j ^ dj];
                    unsigned long long mn = a < b ? a : b;
                    unsigned long long mx = a < b ? b : a;
                    cv[j]      = dir ? mn : mx;
                    cv[j ^ dj] = dir ? mx : mn;
                }
            } else {
#pragma unroll
                for (int j = 0; j < 4; ++j) {
                    unsigned v = j * 32 + lane;
                    unsigned long long o = __shfl_xor_sync(FM, cv[j], d);
                    bool dir = ((v & k) == 0);
                    bool lower = ((lane & d) == 0);
                    bool takeMin = (lower == dir);
                    unsigned long long mn = o < cv[j] ? o : cv[j];
                    unsigned long long mx = o < cv[j] ? cv[j] : o;
                    cv[j] = takeMin ? mn : mx;
                }
            }
        }
    }
    if (lane < KNN)
        idxout[row * KNN + lane] = (int)(cv[0] & 0xffffffffu);
}

// =================== exact fallback for overflow rows (rare / usually idle) ========
__global__ void __launch_bounds__(256)
topk_fb(const float* __restrict__ d2, const int* __restrict__ ovflag,
        int* __restrict__ idxout) {
    __shared__ unsigned long long fb[8][32 * KNN];
    int w = threadIdx.x >> 5, lane = threadIdx.x & 31;
    const unsigned FM = 0xffffffffu;
    size_t row = (size_t)blockIdx.x * 8 + w;
    if (!ovflag[row]) return;
    const float* r = d2 + row * NN;

    float key[KNN]; int ki[KNN];
#pragma unroll
    for (int j = 0; j < KNN; ++j) { key[j] = FLT_MAX; ki[j] = 0; }
    for (int j = 0; j < 16; ++j) {
        int e0 = 4 * (j * 32 + lane);
        float4 v4 = *(const float4*)(r + e0);
        float vmin = fminf(fminf(v4.x, v4.y), fminf(v4.z, v4.w));
        if (vmin < key[KNN - 1]) {
            float vals[4] = {v4.x, v4.y, v4.z, v4.w};
#pragma unroll
            for (int q = 0; q < 4; ++q) INS(key, ki, vals[q], e0 + q);
        }
    }
#pragma unroll
    for (int j = 0; j < KNN; ++j)
        fb[w][lane * KNN + j] = ((unsigned long long)mono(key[j]) << 32) | (unsigned)ki[j];
    __syncwarp();
    int h = 0;
    unsigned long long hv = fb[w][lane * KNN];
#pragma unroll
    for (int k = 0; k < KNN; ++k) {
        unsigned long long red = hv;
#pragma unroll
        for (int off = 16; off; off >>= 1) {
            unsigned long long o = __shfl_xor_sync(FM, red, off);
            red = o < red ? o : red;
        }
        if (lane == 0) idxout[row * KNN + k] = (int)(red & 0xffffffffu);
        if (hv == red) { ++h; hv = (h < KNN) ? fb[w][lane * KNN + h] : ~0ULL; }
    }
}

// =================== small kernels ===================
// warp-per-row squared norms (coalesced)
__global__ void xx_kernel(const float* __restrict__ X, int ldx, int C,
                          float* __restrict__ xx) {
    int w = threadIdx.x >> 5, lane = threadIdx.x & 31;
    int row = blockIdx.x * 8 + w;
    if (row >= BB * NN) return;
    const float* p = X + (size_t)row * ldx;
    float s = 0.f;
    for (int c = lane; c < C; c += 32) { float v = p[c]; s += v * v; }
#pragma unroll
    for (int off = 16; off; off >>= 1)
        s += __shfl_xor_sync(0xffffffffu, s, off);
    if (lane == 0) xx[row] = s;
}

// h[n,o] = leaky(max_k y[j_k,o] - y[n,o] + c[n,o])   (leaky/max commute)
// 128 threads per block; each block handles G = 512/O points.
__global__ void __launch_bounds__(128)
edgemax4(const float* __restrict__ yc, const int* __restrict__ idx,
         float* __restrict__ out, int O, int ldo) {
    __shared__ int sid[8 * KNN];
    int cpp = O >> 2;                 // float4 cols per point
    int G = 128 / cpp;                // points per block
    int b = blockIdx.y;
    int n0 = blockIdx.x * G;
    int t = threadIdx.x;
    for (int i = t; i < G * KNN; i += 128)
        sid[i] = idx[((size_t)b * NN + n0 + i / KNN) * KNN + (i % KNN)];
    __syncthreads();
    int p = t / cpp, c = t % cpp;
    int n = n0 + p;
    size_t mbase = (size_t)b * NN;
    int ld2 = 2 * O;
    const int* sp = &sid[p * KNN];
    float4 m = make_float4(-FLT_MAX, -FLT_MAX, -FLT_MAX, -FLT_MAX);
#pragma unroll
    for (int k = 0; k < KNN; ++k) {
        float4 yn = *(const float4*)(yc + (mbase + sp[k]) * ld2 + 4 * c);
        m.x = fmaxf(m.x, yn.x); m.y = fmaxf(m.y, yn.y);
        m.z = fmaxf(m.z, yn.z); m.w = fmaxf(m.w, yn.w);
    }
    const float* prow = yc + (mbase + n) * ld2 + 4 * c;
    float4 ycn = *(const float4*)prow;
    float4 ccn = *(const float4*)(prow + O);
    float v0 = m.x - ycn.x + ccn.x;
    float v1 = m.y - ycn.y + ccn.y;
    float v2 = m.z - ycn.z + ccn.z;
    float v3 = m.w - ycn.w + ccn.w;
    v0 = v0 > 0.f ? v0 : 0.2f * v0;
    v1 = v1 > 0.f ? v1 : 0.2f * v1;
    v2 = v2 > 0.f ? v2 : 0.2f * v2;
    v3 = v3 > 0.f ? v3 : 0.2f * v3;
    *(float4*)(out + (mbase + n) * ldo + 4 * c) = make_float4(v0, v1, v2, v3);
}

// two-stage global max pool over N
__global__ void maxpool1(const float* __restrict__ tmp, float* __restrict__ part) {
    int b = blockIdx.y, c = blockIdx.z;
    int f = blockIdx.x * blockDim.x + threadIdx.x;
    const float* p = tmp + ((size_t)b * NN + c * 128) * 1024 + f;
    float m = -FLT_MAX;
#pragma unroll 4
    for (int n = 0; n < 128; ++n) m = fmaxf(m, p[(size_t)n * 1024]);
    part[(c * BB + b) * 1024 + f] = m;
}
__global__ void maxpool2(const float* __restrict__ part, float* __restrict__ out) {
    int b = blockIdx.y;
    int f = blockIdx.x * blockDim.x + threadIdx.x;
    float m = -FLT_MAX;
#pragma unroll
    for (int c = 0; c < 16; ++c) m = fmaxf(m, part[(c * BB + b) * 1024 + f]);
    out[b * 1024 + f] = m;
}

// =================== launch ===================
extern "C" void kernel_launch(void* const* d_in, const int* in_sizes, int n_in,
                              void* d_out, int out_size) {
    const float* x     = (const float*)d_in[0];
    const float* Wl[4] = {(const float*)d_in[1], (const float*)d_in[3],
                          (const float*)d_in[5], (const float*)d_in[7]};
    const float* bl[4] = {(const float*)d_in[2], (const float*)d_in[4],
                          (const float*)d_in[6], (const float*)d_in[8]};
    const float* Wf = (const float*)d_in[9];
    const float* bf = (const float*)d_in[10];
    float* out = (float*)d_out;

    float *p_d2, *p_sub, *p_xx, *p_yc, *p_hcat, *p_tmp, *p_part, *p_bias2;
    __nv_bfloat16 *p_a3, *p_b3, *p_bf3, *p_w3;
    int *p_idx, *p_ov;
    cudaGetSymbolAddress((void**)&p_d2,    g_d2);
    cudaGetSymbolAddress((void**)&p_sub,   g_submin);
    cudaGetSymbolAddress((void**)&p_xx,    g_xx);
    cudaGetSymbolAddress((void**)&p_idx,   g_idx);
    cudaGetSymbolAddress((void**)&p_ov,    g_ov);
    cudaGetSymbolAddress((void**)&p_yc,    g_yc);
    cudaGetSymbolAddress((void**)&p_hcat,  g_hcat);
    cudaGetSymbolAddress((void**)&p_tmp,   g_tmp);
    cudaGetSymbolAddress((void**)&p_part,  g_part);
    cudaGetSymbolAddress((void**)&p_bias2, g_bias2);
    cudaGetSymbolAddress((void**)&p_a3,    g_a3);
    cudaGetSymbolAddress((void**)&p_b3,    g_b3);
    cudaGetSymbolAddress((void**)&p_bf3,   g_bf3);
    cudaGetSymbolAddress((void**)&p_w3,    g_w3);

    cudaFuncSetAttribute(mma_gemm, cudaFuncAttributeMaxDynamicSharedMemorySize,
                         MMA_SMEM);

    const int Cs[4]  = {3, 64, 64, 128};
    const int Os[4]  = {64, 64, 128, 256};
    const int off[4] = {0, 64, 128, 256};

    const float* Xin = x;
    int ldx = 3;
    for (int l = 0; l < 4; ++l) {
        int C = Cs[l], O = Os[l];
        int K3 = ((3 * C + 63) / 64) * 64;     // 64, 192, 192, 384
        int G = 512 / O;                       // points per edgemax block

        xx_kernel<<<(BB * NN) / 8, 256>>>(Xin, ldx, C, p_xx);
        convAB_kernel<<<dim3((K3 + 255) / 256, BB * NN), 256>>>(
            Xin, ldx, C, p_a3, p_b3, K3);
        // pairwise d2 + subtile mins (batched over z)
        mma_gemm<<<dim3(16, 16, BB), 256, MMA_SMEM>>>(
            p_a3, K3, (size_t)NN * K3, p_b3, K3, (size_t)NN * K3,
            NN, K3, p_d2, NN, (size_t)NN * NN, nullptr, 0, 1, p_xx, NN, p_sub);
        topk_sel<<<(BB * NN) / 8, 256>>>(p_d2, p_sub, p_idx, p_ov);
        topk_fb<<<(BB * NN) / 8, 256>>>(p_d2, p_ov, p_idx);
        // combined yc = X * [Wy|Wc]^T + [0|b]
        convB_kernel<<<dim3((K3 + 255) / 256, O), 256>>>(Wl[l], 2 * C, C, p_w3, K3);
        convB_kernel<<<dim3((K3 + 255) / 256, O), 256>>>(Wl[l] + C, 2 * C, C,
                                                         p_w3 + (size_t)O * K3, K3);
        biascat<<<1, 512>>>(bl[l], p_bias2, O);
        mma_gemm<<<dim3((2 * O + 127) / 128, (BB * NN) / 128, 1), 256, MMA_SMEM>>>(
            p_a3, K3, 0, p_w3, K3, 0, 2 * O, K3,
            p_yc, 2 * O, 0, p_bias2, 0, 0, nullptr, 0, nullptr);
        edgemax4<<<dim3(NN / G, BB), 128>>>(p_yc, p_idx, p_hcat + off[l], O, 512);
        Xin = p_hcat + off[l];
        ldx = 512;
    }
    // final 512 -> 1024 linear + leaky, then max over N (two-stage pool)
    convA_kernel<<<dim3(1536 / 256, BB * NN), 256>>>(p_hcat, 512, 512, p_a3, 1536);
    convB_kernel<<<dim3(1536 / 256, 1024), 256>>>(Wf, 512, 512, p_bf3, 1536);
    mma_gemm<<<dim3(1024 / 128, (BB * NN) / 128, 1), 256, MMA_SMEM>>>(
        p_a3, 1536, 0, p_bf3, 1536, 0, 1024, 1536,
        p_tmp, 1024, 0, bf, 1, 0, nullptr, 0, nullptr);
    maxpool1<<<dim3(1024 / 256, BB, 16), 256>>>(p_tmp, p_part);
    maxpool2<<<dim3(1024 / 256, BB), 256>>>(p_part, out);
}

// round 14
// speedup vs baseline: 2.6514x; 1.0171x over previous
#include <cuda_runtime.h>
#include <cuda_bf16.h>
#include <float.h>
#include <math.h>
#include <cstdint>

#define BB  8
#define NN  2048
#define KNN 20
#define CAP 128   // candidate cap per row before fallback (= bitonic width)

// ---------------- scratch (device globals; no allocations) ----------------
__device__ __align__(16) float g_d2[(size_t)BB * NN * NN];
__device__ __align__(16) float g_submin[(size_t)BB * NN * 64];
__device__ __align__(16) float g_xx[BB * NN];
__device__ __align__(16) int   g_idx[BB * NN * KNN];
__device__ __align__(16) int   g_ov[BB * NN];
__device__ __align__(16) float g_yc[(size_t)BB * NN * 512];    // y | c combined
__device__ __align__(16) float g_hcat[(size_t)BB * NN * 512];
__device__ __align__(16) float g_tmp[(size_t)BB * NN * 1024];
__device__ __align__(16) float g_part[16 * BB * 1024];
__device__ __align__(16) float g_bias2[512];
__device__ __align__(16) __nv_bfloat16 g_a3[(size_t)BB * NN * 1536];  // split A (h|l|h)
__device__ __align__(16) __nv_bfloat16 g_b3[(size_t)BB * NN * 384];   // split B (h|h|l)
__device__ __align__(16) __nv_bfloat16 g_bf3[1024 * 1536];            // split Wf
__device__ __align__(16) __nv_bfloat16 g_w3[512 * 384];               // split layer W (y|c)

// =================== split-precision conversion kernels ===================
__global__ void convAB_kernel(const float* __restrict__ in, int ld, int C,
                              __nv_bfloat16* __restrict__ a3,
                              __nv_bfloat16* __restrict__ b3, int K3) {
    int r = blockIdx.y;
    int c = blockIdx.x * 256 + threadIdx.x;
    if (c >= K3) return;
    size_t ro = (size_t)r * K3;
    if (c < C) {
        float xv = in[(size_t)r * ld + c];
        __nv_bfloat16 h = __float2bfloat16(xv);
        __nv_bfloat16 l = __float2bfloat16(xv - __bfloat162float(h));
        a3[ro + c] = h; a3[ro + C + c] = l; a3[ro + 2 * C + c] = h;
        b3[ro + c] = h; b3[ro + C + c] = h; b3[ro + 2 * C + c] = l;
    } else if (c >= 3 * C) {
        __nv_bfloat16 z = __float2bfloat16(0.f);
        a3[ro + c] = z; b3[ro + c] = z;
    }
}
__global__ void convA_kernel(const float* __restrict__ in, int ld, int C,
                             __nv_bfloat16* __restrict__ out, int K3) {
    int r = blockIdx.y;
    int c = blockIdx.x * 256 + threadIdx.x;
    if (c >= K3) return;
    size_t ro = (size_t)r * K3;
    if (c < C) {
        float xv = in[(size_t)r * ld + c];
        __nv_bfloat16 h = __float2bfloat16(xv);
        __nv_bfloat16 l = __float2bfloat16(xv - __bfloat162float(h));
        out[ro + c] = h; out[ro + C + c] = l; out[ro + 2 * C + c] = h;
    } else if (c >= 3 * C) {
        out[ro + c] = __float2bfloat16(0.f);
    }
}
__global__ void convB_kernel(const float* __restrict__ in, int ld, int C,
                             __nv_bfloat16* __restrict__ out, int K3) {
    int r = blockIdx.y;
    int c = blockIdx.x * 256 + threadIdx.x;
    if (c >= K3) return;
    size_t ro = (size_t)r * K3;
    if (c < C) {
        float xv = in[(size_t)r * ld + c];
        __nv_bfloat16 h = __float2bfloat16(xv);
        __nv_bfloat16 l = __float2bfloat16(xv - __bfloat162float(h));
        out[ro + c] = h; out[ro + C + c] = h; out[ro + 2 * C + c] = l;
    } else if (c >= 3 * C) {
        out[ro + c] = __float2bfloat16(0.f);
    }
}
__global__ void biascat(const float* __restrict__ bl, float* __restrict__ out, int O) {
    int i = threadIdx.x;
    if (i < O) out[i] = 0.f;
    else if (i < 2 * O) out[i] = bl[i - O];
}

#define LDP 72

__device__ __forceinline__ void mma16816(float* d, const uint32_t* a, const uint32_t* b) {
    asm volatile(
        "mma.sync.aligned.m16n8k16.row.col.f32.bf16.bf16.f32 "
        "{%0,%1,%2,%3}, {%4,%5,%6,%7}, {%8,%9}, {%0,%1,%2,%3};"
        : "+f"(d[0]), "+f"(d[1]), "+f"(d[2]), "+f"(d[3])
        : "r"(a[0]), "r"(a[1]), "r"(a[2]), "r"(a[3]), "r"(b[0]), "r"(b[1]));
}
__device__ __forceinline__ void ldsm4(uint32_t* r, uint32_t addr) {
    asm volatile("ldmatrix.sync.aligned.m8n8.x4.shared.b16 {%0,%1,%2,%3}, [%4];"
        : "=r"(r[0]), "=r"(r[1]), "=r"(r[2]), "=r"(r[3]) : "r"(addr));
}
__device__ __forceinline__ uint32_t smem_u32(const void* p) {
    uint32_t a;
    asm("{ .reg .u64 t; cvta.to.shared.u64 t, %1; cvt.u32.u64 %0, t; }" : "=r"(a) : "l"(p));
    return a;
}
__device__ __forceinline__ unsigned mono(float v) {
    unsigned u = __float_as_uint(v);
    return (u & 0x80000000u) ? ~u : (u | 0x80000000u);
}
__device__ __forceinline__ float unmono(unsigned m) {
    unsigned u = (m & 0x80000000u) ? (m ^ 0x80000000u) : ~m;
    return __uint_as_float(u);
}
#define CPA(dst, src, n) \
    asm volatile("cp.async.cg.shared.global [%0], [%1], 16, %2;" \
                 :: "r"(dst), "l"(src), "r"(n))
#define CPA_COMMIT() asm volatile("cp.async.commit_group;" ::: "memory")
#define CPA_WAIT1()  asm volatile("cp.async.wait_group 1;" ::: "memory")
#define CPA_WAIT0()  asm volatile("cp.async.wait_group 0;" ::: "memory")

// register insertion into sorted KNN list (strict < keeps lowest idx on ties)
#define INS(keys, kidx, v, ix) do { \
    if ((v) < keys[KNN - 1]) { \
        float _cv = (v); int _ci = (ix); \
        _Pragma("unroll") \
        for (int _j = 0; _j < KNN; ++_j) { \
            if (_cv < keys[_j]) { \
                float _tv = keys[_j]; keys[_j] = _cv; _cv = _tv; \
                int _ti = kidx[_j]; kidx[_j] = _ci; _ci = _ti; \
            } \
        } \
    } } while (0)

#define MMA_SMEM (2 * 2 * 128 * LDP * 2)

// =================== cp.async-pipelined mma.sync GEMM, 128x128 tile ===============
// ldmatrix fragment loads (6 LDSM.x4 per warp per k-step for 16 MMAs).
// mode 0: out[m][o] = acc + bias[o]  (leaky if act)
// mode 1: out[m][o] = xx[m] - 2*acc + xx[o]; also emits 32-col subtile row-mins
__global__ void __launch_bounds__(256)
mma_gemm(const __nv_bfloat16* __restrict__ A3, int lda3, size_t zsA,
         const __nv_bfloat16* __restrict__ B3, int ldb3, size_t zsB,
         int Nvalid, int K3,
         float* __restrict__ out, int ldo, size_t zsO,
         const float* __restrict__ bias, int act,
         int mode, const float* __restrict__ xx, int zsXX,
         float* __restrict__ submin) {
    extern __shared__ __nv_bfloat16 sm[];
    int tid = threadIdx.x;
    int wid = tid >> 5, lane = tid & 31;
    int wr = wid & 3, wc = wid >> 2;
    int gr = lane >> 2, tg = lane & 3;
    int lane15 = lane & 15, laneHi = (lane >> 4) * 8;

    int m0 = blockIdx.y * 128, o0 = blockIdx.x * 128;
    const __nv_bfloat16* Ab = A3 + blockIdx.z * zsA;
    const __nv_bfloat16* Bb = B3 + blockIdx.z * zsB;
    uint32_t sbase = smem_u32(sm);
    int nch = K3 / 64;

    auto issue = [&](int s, int k0) {
#pragma unroll
        for (int i = 0; i < 4; ++i) {
            int e = tid + i * 256;
            int row = e >> 3, seg = e & 7;
            uint32_t da = sbase + (uint32_t)(s * 2 * 128 * LDP + row * LDP + seg * 8) * 2;
            CPA(da, Ab + (size_t)(m0 + row) * lda3 + k0 + seg * 8, 16);
            int brow = o0 + row;
            int srow = brow < Nvalid ? brow : (Nvalid - 1);
            uint32_t db = sbase + (uint32_t)((s * 2 + 1) * 128 * LDP + row * LDP + seg * 8) * 2;
            CPA(db, Bb + (size_t)srow * ldb3 + k0 + seg * 8, brow < Nvalid ? 16 : 0);
        }
        CPA_COMMIT();
    };

    float acc[2][8][4] = {};
    issue(0, 0);
    for (int ch = 0; ch < nch; ++ch) {
        if (ch + 1 < nch) { issue((ch + 1) & 1, (ch + 1) * 64); CPA_WAIT1(); }
        else              { CPA_WAIT0(); }
        __syncthreads();
        uint32_t stage = sbase + (uint32_t)((ch & 1) * 2 * 128 * LDP) * 2;
        uint32_t aRow = stage + (uint32_t)((wr * 32 + lane15) * LDP + laneHi) * 2;
        uint32_t bRow = stage + (uint32_t)(128 * LDP) * 2
                      + (uint32_t)((wc * 64 + lane15) * LDP + laneHi) * 2;
#pragma unroll
        for (int kk = 0; kk < 64; kk += 16) {
            uint32_t af[2][4], bfr[8][2];
            ldsm4(af[0], aRow + kk * 2);
            ldsm4(af[1], aRow + (16 * LDP + kk) * 2);
#pragma unroll
            for (int q = 0; q < 4; ++q) {
                uint32_t t[4];
                ldsm4(t, bRow + (q * 16 * LDP + kk) * 2);
                bfr[2 * q][0]     = t[0];
                bfr[2 * q + 1][0] = t[1];
                bfr[2 * q][1]     = t[2];
                bfr[2 * q + 1][1] = t[3];
            }
#pragma unroll
            for (int mi = 0; mi < 2; ++mi)
#pragma unroll
                for (int ni = 0; ni < 8; ++ni)
                    mma16816(acc[mi][ni], af[mi], bfr[ni]);
        }
        __syncthreads();
    }

    float* outb = out + blockIdx.z * zsO;
    const float* xxb = (mode == 1) ? xx + (size_t)blockIdx.z * zsXX : nullptr;
    float rmn[2][2][2];
#pragma unroll
    for (int i = 0; i < 2; ++i)
#pragma unroll
        for (int j = 0; j < 2; ++j) { rmn[i][j][0] = FLT_MAX; rmn[i][j][1] = FLT_MAX; }

#pragma unroll
    for (int mi = 0; mi < 2; ++mi) {
        int mA = m0 + wr * 32 + mi * 16 + gr;
        float xrA = 0.f, xrB = 0.f;
        if (mode == 1) { xrA = xxb[mA]; xrB = xxb[mA + 8]; }
#pragma unroll
        for (int ni = 0; ni < 8; ++ni) {
            int o = o0 + wc * 64 + ni * 8 + tg * 2;
            if (o < Nvalid) {
                float u0 = acc[mi][ni][0], u1 = acc[mi][ni][1];
                float u2 = acc[mi][ni][2], u3 = acc[mi][ni][3];
                if (mode == 0) {
                    float b0 = bias ? bias[o] : 0.f, b1 = bias ? bias[o + 1] : 0.f;
                    u0 += b0; u1 += b1; u2 += b0; u3 += b1;
                    if (act) {
                        u0 = u0 > 0.f ? u0 : 0.2f * u0;
                        u1 = u1 > 0.f ? u1 : 0.2f * u1;
                        u2 = u2 > 0.f ? u2 : 0.2f * u2;
                        u3 = u3 > 0.f ? u3 : 0.2f * u3;
                    }
                } else {
                    float xc0 = xxb[o], xc1 = xxb[o + 1];
                    u0 = xrA - 2.f * u0 + xc0; u1 = xrA - 2.f * u1 + xc1;
                    u2 = xrB - 2.f * u2 + xc0; u3 = xrB - 2.f * u3 + xc1;
                    int s = ni >> 2;
                    rmn[mi][s][0] = fminf(rmn[mi][s][0], fminf(u0, u1));
                    rmn[mi][s][1] = fminf(rmn[mi][s][1], fminf(u2, u3));
                }
                *(float2*)(outb + (size_t)mA * ldo + o)       = make_float2(u0, u1);
                *(float2*)(outb + (size_t)(mA + 8) * ldo + o) = make_float2(u2, u3);
            }
        }
    }
    if (mode == 1) {
        float* sb = submin + (size_t)blockIdx.z * NN * 64;
#pragma unroll
        for (int mi = 0; mi < 2; ++mi)
#pragma unroll
            for (int s = 0; s < 2; ++s)
#pragma unroll
                for (int rr = 0; rr < 2; ++rr) {
                    float v = rmn[mi][s][rr];
                    v = fminf(v, __shfl_xor_sync(0xffffffffu, v, 1));
                    v = fminf(v, __shfl_xor_sync(0xffffffffu, v, 2));
                    if (tg == 0) {
                        int grow = m0 + wr * 32 + mi * 16 + gr + rr * 8;
                        sb[(size_t)grow * 64 + blockIdx.x * 4 + wc * 2 + s] = v;
                    }
                }
    }
}

// =================== threshold-filter top-K, bitonic select (exact) ===============
// Phase 1: bitonic-sort 64 subtile-mins -> T = rank-19 (20th smallest).
// Phase 2: scan only qualifying subtiles; ballot-prefix compaction (no atomics),
//          two subtile loads in flight per iteration.
// Phase 3: fast path cnt<=32: 32-wide single-reg bitonic; else 128-wide 4-reg.
__global__ void __launch_bounds__(256, 6)
topk_sel(const float* __restrict__ d2, const float* __restrict__ submin,
         int* __restrict__ idxout, int* __restrict__ ovflag) {
    __shared__ unsigned long long fl[8][CAP];
    int w = threadIdx.x >> 5, lane = threadIdx.x & 31;
    const unsigned FM = 0xffffffffu;
    size_t row = (size_t)blockIdx.x * 8 + w;
    const float* r = d2 + row * NN;

    fl[w][lane] = ~0ULL; fl[w][lane + 32] = ~0ULL;
    fl[w][lane + 64] = ~0ULL; fl[w][lane + 96] = ~0ULL;
    __syncwarp();

    // ---- phase 1: bitonic sort of 64 submins (2 u32/lane), T = rank 19 ----
    float s0f = submin[row * 64 + lane];
    float s1f = submin[row * 64 + 32 + lane];
    unsigned sv[2] = { mono(s0f), mono(s1f) };
#pragma unroll
    for (unsigned k = 2; k <= 64; k <<= 1) {
#pragma unroll
        for (unsigned d = 32; d; d >>= 1) {
            if (d >= k) continue;
            if (d == 32) {
                unsigned a = sv[0], b = sv[1];
                sv[0] = a < b ? a : b;
                sv[1] = a < b ? b : a;
            } else {
#pragma unroll
                for (int j = 0; j < 2; ++j) {
                    unsigned v = j * 32 + lane;
                    unsigned o = __shfl_xor_sync(FM, sv[j], d);
                    bool dir = ((v & k) == 0);
                    bool lower = ((lane & d) == 0);
                    bool takeMin = (lower == dir);
                    unsigned mn = o < sv[j] ? o : sv[j];
                    unsigned mx = o < sv[j] ? sv[j] : o;
                    sv[j] = takeMin ? mn : mx;
                }
            }
        }
    }
    unsigned T = __shfl_sync(FM, sv[0], 19);
    float Tf = unmono(T);

    // ---- phase 2: qualifying subtiles only; ballot-prefix compaction ----
    unsigned mask0 = __ballot_sync(FM, s0f <= Tf);
    unsigned mask1 = __ballot_sync(FM, s1f <= Tf);
    unsigned long long mask = ((unsigned long long)mask1 << 32) | mask0;
    unsigned lmlt = (1u << lane) - 1;
    int base = 0;
    while (mask) {
        int s0 = __ffsll((long long)mask) - 1; mask &= mask - 1;
        int s1 = -1;
        if (mask) { s1 = __ffsll((long long)mask) - 1; mask &= mask - 1; }
        float v0 = r[s0 * 32 + lane];
        float v1 = (s1 >= 0) ? r[s1 * 32 + lane] : FLT_MAX;
        bool h0 = v0 <= Tf;
        unsigned bm0 = __ballot_sync(FM, h0);
        if (h0) {
            int p = base + __popc(bm0 & lmlt);
            if (p < CAP)
                fl[w][p] = ((unsigned long long)mono(v0) << 32) | (unsigned)(s0 * 32 + lane);
        }
        base += __popc(bm0);
        if (s1 >= 0) {
            bool h1 = v1 <= Tf;
            unsigned bm1 = __ballot_sync(FM, h1);
            if (h1) {
                int p = base + __popc(bm1 & lmlt);
                if (p < CAP)
                    fl[w][p] = ((unsigned long long)mono(v1) << 32) | (unsigned)(s1 * 32 + lane);
            }
            base += __popc(bm1);
        }
    }
    __syncwarp();

    int nc = base;
    int ov = nc > CAP;
    if (lane == 0) ovflag[row] = ov;
    if (ov) return;                       // exact fallback kernel handles this row

    if (nc <= 32) {
        // ---- phase 3 fast: bitonic sort 32 u64 keys (1/lane) ----
        unsigned long long c0 = fl[w][lane];
#pragma unroll
        for (unsigned k = 2; k <= 32; k <<= 1) {
#pragma unroll
            for (unsigned d = k >> 1; d; d >>= 1) {
                unsigned long long o = __shfl_xor_sync(FM, c0, d);
                bool dir = ((lane & k) == 0);
                bool lower = ((lane & d) == 0);
                bool takeMin = (lower == dir);
                unsigned long long mn = o < c0 ? o : c0;
                unsigned long long mx = o < c0 ? c0 : o;
                c0 = takeMin ? mn : mx;
            }
        }
        if (lane < KNN)
            idxout[row * KNN + lane] = (int)(c0 & 0xffffffffu);
        return;
    }

    // ---- phase 3 full: bitonic sort of 128 u64 keys (4/lane) ----
    unsigned long long cv[4] = { fl[w][lane], fl[w][lane + 32],
                                 fl[w][lane + 64], fl[w][lane + 96] };
#pragma unroll
    for (unsigned k = 2; k <= 128; k <<= 1) {
#pragma unroll
        for (unsigned d = 64; d; d >>= 1) {
            if (d >= k) continue;
            if (d >= 32) {
                int dj = d >> 5;
#pragma unroll
                for (int j = 0; j < 4; ++j) {
                    if (j & dj) continue;
                    unsigned v = j * 32 + lane;
                    bool dir = ((v & k) == 0);
                    unsigned long long a = cv[j], b = cv[j ^ dj];
                    unsigned long long mn = a < b ? a : b;
                    unsigned long long mx = a < b ? b : a;
                    cv[j]      = dir ? mn : mx;
                    cv[j ^ dj] = dir ? mx : mn;
                }
            } else {
#pragma unroll
                for (int j = 0; j < 4; ++j) {
                    unsigned v = j * 32 + lane;
                    unsigned long long o = __shfl_xor_sync(FM, cv[j], d);
                    bool dir = ((v & k) == 0);
                    bool lower = ((lane & d) == 0);
                    bool takeMin = (lower == dir);
                    unsigned long long mn = o < cv[j] ? o : cv[j];
                    unsigned long long mx = o < cv[j] ? cv[j] : o;
                    cv[j] = takeMin ? mn : mx;
                }
            }
        }
    }
    if (lane < KNN)
        idxout[row * KNN + lane] = (int)(cv[0] & 0xffffffffu);
}

// =================== exact fallback for overflow rows (rare / usually idle) ========
__global__ void __launch_bounds__(256)
topk_fb(const float* __restrict__ d2, const int* __restrict__ ovflag,
        int* __restrict__ idxout) {
    __shared__ unsigned long long fb[8][32 * KNN];
    int w = threadIdx.x >> 5, lane = threadIdx.x & 31;
    const unsigned FM = 0xffffffffu;
    size_t row = (size_t)blockIdx.x * 8 + w;
    if (!ovflag[row]) return;
    const float* r = d2 + row * NN;

    float key[KNN]; int ki[KNN];
#pragma unroll
    for (int j = 0; j < KNN; ++j) { key[j] = FLT_MAX; ki[j] = 0; }
    for (int j = 0; j < 16; ++j) {
        int e0 = 4 * (j * 32 + lane);
        float4 v4 = *(const float4*)(r + e0);
        float vmin = fminf(fminf(v4.x, v4.y), fminf(v4.z, v4.w));
        if (vmin < key[KNN - 1]) {
            float vals[4] = {v4.x, v4.y, v4.z, v4.w};
#pragma unroll
            for (int q = 0; q < 4; ++q) INS(key, ki, vals[q], e0 + q);
        }
    }
#pragma unroll
    for (int j = 0; j < KNN; ++j)
        fb[w][lane * KNN + j] = ((unsigned long long)mono(key[j]) << 32) | (unsigned)ki[j];
    __syncwarp();
    int h = 0;
    unsigned long long hv = fb[w][lane * KNN];
#pragma unroll
    for (int k = 0; k < KNN; ++k) {
        unsigned long long red = hv;
#pragma unroll
        for (int off = 16; off; off >>= 1) {
            unsigned long long o = __shfl_xor_sync(FM, red, off);
            red = o < red ? o : red;
        }
        if (lane == 0) idxout[row * KNN + k] = (int)(red & 0xffffffffu);
        if (hv == red) { ++h; hv = (h < KNN) ? fb[w][lane * KNN + h] : ~0ULL; }
    }
}

// =================== small kernels ===================
// warp-per-row squared norms (coalesced)
__global__ void xx_kernel(const float* __restrict__ X, int ldx, int C,
                          float* __restrict__ xx) {
    int w = threadIdx.x >> 5, lane = threadIdx.x & 31;
    int row = blockIdx.x * 8 + w;
    if (row >= BB * NN) return;
    const float* p = X + (size_t)row * ldx;
    float s = 0.f;
    for (int c = lane; c < C; c += 32) { float v = p[c]; s += v * v; }
#pragma unroll
    for (int off = 16; off; off >>= 1)
        s += __shfl_xor_sync(0xffffffffu, s, off);
    if (lane == 0) xx[row] = s;
}

// h[n,o] = leaky(max_k y[j_k,o] - y[n,o] + c[n,o])   (leaky/max commute)
// 128 threads per block; each block handles G = 512/O points.
__global__ void __launch_bounds__(128)
edgemax4(const float* __restrict__ yc, const int* __restrict__ idx,
         float* __restrict__ out, int O, int ldo) {
    __shared__ int sid[8 * KNN];
    int cpp = O >> 2;                 // float4 cols per point
    int G = 128 / cpp;                // points per block
    int b = blockIdx.y;
    int n0 = blockIdx.x * G;
    int t = threadIdx.x;
    for (int i = t; i < G * KNN; i += 128)
        sid[i] = idx[((size_t)b * NN + n0 + i / KNN) * KNN + (i % KNN)];
    __syncthreads();
    int p = t / cpp, c = t % cpp;
    int n = n0 + p;
    size_t mbase = (size_t)b * NN;
    int ld2 = 2 * O;
    const int* sp = &sid[p * KNN];
    float4 m = make_float4(-FLT_MAX, -FLT_MAX, -FLT_MAX, -FLT_MAX);
#pragma unroll
    for (int k = 0; k < KNN; ++k) {
        float4 yn = *(const float4*)(yc + (mbase + sp[k]) * ld2 + 4 * c);
        m.x = fmaxf(m.x, yn.x); m.y = fmaxf(m.y, yn.y);
        m.z = fmaxf(m.z, yn.z); m.w = fmaxf(m.w, yn.w);
    }
    const float* prow = yc + (mbase + n) * ld2 + 4 * c;
    float4 ycn = *(const float4*)prow;
    float4 ccn = *(const float4*)(prow + O);
    float v0 = m.x - ycn.x + ccn.x;
    float v1 = m.y - ycn.y + ccn.y;
    float v2 = m.z - ycn.z + ccn.z;
    float v3 = m.w - ycn.w + ccn.w;
    v0 = v0 > 0.f ? v0 : 0.2f * v0;
    v1 = v1 > 0.f ? v1 : 0.2f * v1;
    v2 = v2 > 0.f ? v2 : 0.2f * v2;
    v3 = v3 > 0.f ? v3 : 0.2f * v3;
    *(float4*)(out + (mbase + n) * ldo + 4 * c) = make_float4(v0, v1, v2, v3);
}

// two-stage global max pool over N
__global__ void maxpool1(const float* __restrict__ tmp, float* __restrict__ part) {
    int b = blockIdx.y, c = blockIdx.z;
    int f = blockIdx.x * blockDim.x + threadIdx.x;
    const float* p = tmp + ((size_t)b * NN + c * 128) * 1024 + f;
    float m = -FLT_MAX;
#pragma unroll 4
    for (int n = 0; n < 128; ++n) m = fmaxf(m, p[(size_t)n * 1024]);
    part[(c * BB + b) * 1024 + f] = m;
}
__global__ void maxpool2(const float* __restrict__ part, float* __restrict__ out) {
    int b = blockIdx.y;
    int f = blockIdx.x * blockDim.x + threadIdx.x;
    float m = -FLT_MAX;
#pragma unroll
    for (int c = 0; c < 16; ++c) m = fmaxf(m, part[(c * BB + b) * 1024 + f]);
    out[b * 1024 + f] = m;
}

// =================== launch ===================
extern "C" void kernel_launch(void* const* d_in, const int* in_sizes, int n_in,
                              void* d_out, int out_size) {
    const float* x     = (const float*)d_in[0];
    const float* Wl[4] = {(const float*)d_in[1], (const float*)d_in[3],
                          (const float*)d_in[5], (const float*)d_in[7]};
    const float* bl[4] = {(const float*)d_in[2], (const float*)d_in[4],
                          (const float*)d_in[6], (const float*)d_in[8]};
    const float* Wf = (const float*)d_in[9];
    const float* bf = (const float*)d_in[10];
    float* out = (float*)d_out;

    float *p_d2, *p_sub, *p_xx, *p_yc, *p_hcat, *p_tmp, *p_part, *p_bias2;
    __nv_bfloat16 *p_a3, *p_b3, *p_bf3, *p_w3;
    int *p_idx, *p_ov;
    cudaGetSymbolAddress((void**)&p_d2,    g_d2);
    cudaGetSymbolAddress((void**)&p_sub,   g_submin);
    cudaGetSymbolAddress((void**)&p_xx,    g_xx);
    cudaGetSymbolAddress((void**)&p_idx,   g_idx);
    cudaGetSymbolAddress((void**)&p_ov,    g_ov);
    cudaGetSymbolAddress((void**)&p_yc,    g_yc);
    cudaGetSymbolAddress((void**)&p_hcat,  g_hcat);
    cudaGetSymbolAddress((void**)&p_tmp,   g_tmp);
    cudaGetSymbolAddress((void**)&p_part,  g_part);
    cudaGetSymbolAddress((void**)&p_bias2, g_bias2);
    cudaGetSymbolAddress((void**)&p_a3,    g_a3);
    cudaGetSymbolAddress((void**)&p_b3,    g_b3);
    cudaGetSymbolAddress((void**)&p_bf3,   g_bf3);
    cudaGetSymbolAddress((void**)&p_w3,    g_w3);

    cudaFuncSetAttribute(mma_gemm, cudaFuncAttributeMaxDynamicSharedMemorySize,
                         MMA_SMEM);

    const int Cs[4]  = {3, 64, 64, 128};
    const int Os[4]  = {64, 64, 128, 256};
    const int off[4] = {0, 64, 128, 256};

    const float* Xin = x;
    int ldx = 3;
    for (int l = 0; l < 4; ++l) {
        int C = Cs[l], O = Os[l];
        int K3 = ((3 * C + 63) / 64) * 64;     // 64, 192, 192, 384
        int G = 512 / O;                       // points per edgemax block

        xx_kernel<<<(BB * NN) / 8, 256>>>(Xin, ldx, C, p_xx);
        convAB_kernel<<<dim3((K3 + 255) / 256, BB * NN), 256>>>(
            Xin, ldx, C, p_a3, p_b3, K3);
        // pairwise d2 + subtile mins (batched over z)
        mma_gemm<<<dim3(16, 16, BB), 256, MMA_SMEM>>>(
            p_a3, K3, (size_t)NN * K3, p_b3, K3, (size_t)NN * K3,
            NN, K3, p_d2, NN, (size_t)NN * NN, nullptr, 0, 1, p_xx, NN, p_sub);
        topk_sel<<<(BB * NN) / 8, 256>>>(p_d2, p_sub, p_idx, p_ov);
        topk_fb<<<(BB * NN) / 8, 256>>>(p_d2, p_ov, p_idx);
        // combined yc = X * [Wy|Wc]^T + [0|b]
        convB_kernel<<<dim3((K3 + 255) / 256, O), 256>>>(Wl[l], 2 * C, C, p_w3, K3);
        convB_kernel<<<dim3((K3 + 255) / 256, O), 256>>>(Wl[l] + C, 2 * C, C,
                                                         p_w3 + (size_t)O * K3, K3);
        biascat<<<1, 512>>>(bl[l], p_bias2, O);
        mma_gemm<<<dim3((2 * O + 127) / 128, (BB * NN) / 128, 1), 256, MMA_SMEM>>>(
            p_a3, K3, 0, p_w3, K3, 0, 2 * O, K3,
            p_yc, 2 * O, 0, p_bias2, 0, 0, nullptr, 0, nullptr);
        edgemax4<<<dim3(NN / G, BB), 128>>>(p_yc, p_idx, p_hcat + off[l], O, 512);
        Xin = p_hcat + off[l];
        ldx = 512;
    }
    // final 512 -> 1024 linear + leaky, then max over N (two-stage pool)
    convA_kernel<<<dim3(1536 / 256, BB * NN), 256>>>(p_hcat, 512, 512, p_a3, 1536);
    convB_kernel<<<dim3(1536 / 256, 1024), 256>>>(Wf, 512, 512, p_bf3, 1536);
    mma_gemm<<<dim3(1024 / 128, (BB * NN) / 128, 1), 256, MMA_SMEM>>>(
        p_a3, 1536, 0, p_bf3, 1536, 0, 1024, 1536,
        p_tmp, 1024, 0, bf, 1, 0, nullptr, 0, nullptr);
    maxpool1<<<dim3(1024 / 256, BB, 16), 256>>>(p_tmp, p_part);
    maxpool2<<<dim3(1024 / 256, BB), 256>>>(p_part, out);
}

// round 15
// speedup vs baseline: 2.8174x; 1.0626x over previous
#include <cuda_runtime.h>
#include <cuda_bf16.h>
#include <float.h>
#include <math.h>
#include <cstdint>

#define BB  8
#define NN  2048
#define KNN 20
#define CAP 128   // candidate cap per row before fallback (= bitonic width)

// ---------------- scratch (device globals; no allocations) ----------------
__device__ __align__(16) float g_d2[(size_t)BB * NN * NN];
__device__ __align__(16) float g_submin[(size_t)BB * NN * 64];
__device__ __align__(16) float g_xx[BB * NN];
__device__ __align__(16) int   g_idx[BB * NN * KNN];
__device__ __align__(16) int   g_ov[BB * NN];
__device__ __align__(16) float g_yc[(size_t)BB * NN * 512];    // y | c combined
__device__ __align__(16) float g_hcat[(size_t)BB * NN * 512];
__device__ __align__(16) float g_tmp[(size_t)BB * NN * 1024];
__device__ __align__(16) float g_part[16 * BB * 1024];
__device__ __align__(16) float g_bias2[512];
__device__ __align__(16) __nv_bfloat16 g_a3[(size_t)BB * NN * 1536];  // split A (h|l|h)
__device__ __align__(16) __nv_bfloat16 g_b3[(size_t)BB * NN * 384];   // split B (h|h|l)
__device__ __align__(16) __nv_bfloat16 g_bf3[1024 * 1536];            // split Wf
__device__ __align__(16) __nv_bfloat16 g_w3[512 * 384];               // split layer W (y|c)

// =================== split-precision conversion kernels (linear index) =============
__global__ void convAB_kernel(const float* __restrict__ in, int ld, int C,
                              __nv_bfloat16* __restrict__ a3,
                              __nv_bfloat16* __restrict__ b3, int K3, int total) {
    int i = blockIdx.x * 256 + threadIdx.x;
    if (i >= total) return;
    int r = i / K3, c = i - r * K3;
    size_t ro = (size_t)r * K3;
    if (c < C) {
        float xv = in[(size_t)r * ld + c];
        __nv_bfloat16 h = __float2bfloat16(xv);
        __nv_bfloat16 l = __float2bfloat16(xv - __bfloat162float(h));
        a3[ro + c] = h; a3[ro + C + c] = l; a3[ro + 2 * C + c] = h;
        b3[ro + c] = h; b3[ro + C + c] = h; b3[ro + 2 * C + c] = l;
    } else if (c >= 3 * C) {
        __nv_bfloat16 z = __float2bfloat16(0.f);
        a3[ro + c] = z; b3[ro + c] = z;
    }
}
__global__ void convA_kernel(const float* __restrict__ in, int ld, int C,
                             __nv_bfloat16* __restrict__ out, int K3, int total) {
    int i = blockIdx.x * 256 + threadIdx.x;
    if (i >= total) return;
    int r = i / K3, c = i - r * K3;
    size_t ro = (size_t)r * K3;
    if (c < C) {
        float xv = in[(size_t)r * ld + c];
        __nv_bfloat16 h = __float2bfloat16(xv);
        __nv_bfloat16 l = __float2bfloat16(xv - __bfloat162float(h));
        out[ro + c] = h; out[ro + C + c] = l; out[ro + 2 * C + c] = h;
    } else if (c >= 3 * C) {
        out[ro + c] = __float2bfloat16(0.f);
    }
}
__global__ void convB_kernel(const float* __restrict__ in, int ld, int C,
                             __nv_bfloat16* __restrict__ out, int K3, int total) {
    int i = blockIdx.x * 256 + threadIdx.x;
    if (i >= total) return;
    int r = i / K3, c = i - r * K3;
    size_t ro = (size_t)r * K3;
    if (c < C) {
        float xv = in[(size_t)r * ld + c];
        __nv_bfloat16 h = __float2bfloat16(xv);
        __nv_bfloat16 l = __float2bfloat16(xv - __bfloat162float(h));
        out[ro + c] = h; out[ro + C + c] = h; out[ro + 2 * C + c] = l;
    } else if (c >= 3 * C) {
        out[ro + c] = __float2bfloat16(0.f);
    }
}
__global__ void biascat(const float* __restrict__ bl, float* __restrict__ out, int O) {
    int i = threadIdx.x;
    if (i < O) out[i] = 0.f;
    else if (i < 2 * O) out[i] = bl[i - O];
}

#define LDP 72

__device__ __forceinline__ void mma16816(float* d, const uint32_t* a, const uint32_t* b) {
    asm volatile(
        "mma.sync.aligned.m16n8k16.row.col.f32.bf16.bf16.f32 "
        "{%0,%1,%2,%3}, {%4,%5,%6,%7}, {%8,%9}, {%0,%1,%2,%3};"
        : "+f"(d[0]), "+f"(d[1]), "+f"(d[2]), "+f"(d[3])
        : "r"(a[0]), "r"(a[1]), "r"(a[2]), "r"(a[3]), "r"(b[0]), "r"(b[1]));
}
__device__ __forceinline__ void ldsm4(uint32_t* r, uint32_t addr) {
    asm volatile("ldmatrix.sync.aligned.m8n8.x4.shared.b16 {%0,%1,%2,%3}, [%4];"
        : "=r"(r[0]), "=r"(r[1]), "=r"(r[2]), "=r"(r[3]) : "r"(addr));
}
__device__ __forceinline__ uint32_t smem_u32(const void* p) {
    uint32_t a;
    asm("{ .reg .u64 t; cvta.to.shared.u64 t, %1; cvt.u32.u64 %0, t; }" : "=r"(a) : "l"(p));
    return a;
}
__device__ __forceinline__ unsigned mono(float v) {
    unsigned u = __float_as_uint(v);
    return (u & 0x80000000u) ? ~u : (u | 0x80000000u);
}
__device__ __forceinline__ float unmono(unsigned m) {
    unsigned u = (m & 0x80000000u) ? (m ^ 0x80000000u) : ~m;
    return __uint_as_float(u);
}
#define CPA(dst, src, n) \
    asm volatile("cp.async.cg.shared.global [%0], [%1], 16, %2;" \
                 :: "r"(dst), "l"(src), "r"(n))
#define CPA_COMMIT() asm volatile("cp.async.commit_group;" ::: "memory")
#define CPA_WAIT1()  asm volatile("cp.async.wait_group 1;" ::: "memory")
#define CPA_WAIT0()  asm volatile("cp.async.wait_group 0;" ::: "memory")

// register insertion into sorted KNN list (strict < keeps lowest idx on ties)
#define INS(keys, kidx, v, ix) do { \
    if ((v) < keys[KNN - 1]) { \
        float _cv = (v); int _ci = (ix); \
        _Pragma("unroll") \
        for (int _j = 0; _j < KNN; ++_j) { \
            if (_cv < keys[_j]) { \
                float _tv = keys[_j]; keys[_j] = _cv; _cv = _tv; \
                int _ti = kidx[_j]; kidx[_j] = _ci; _ci = _ti; \
            } \
        } \
    } } while (0)

#define MMA_SMEM (2 * 2 * 128 * LDP * 2)

// =================== cp.async-pipelined mma.sync GEMM, 128x128 tile ===============
__global__ void __launch_bounds__(256)
mma_gemm(const __nv_bfloat16* __restrict__ A3, int lda3, size_t zsA,
         const __nv_bfloat16* __restrict__ B3, int ldb3, size_t zsB,
         int Nvalid, int K3,
         float* __restrict__ out, int ldo, size_t zsO,
         const float* __restrict__ bias, int act,
         int mode, const float* __restrict__ xx, int zsXX,
         float* __restrict__ submin) {
    extern __shared__ __nv_bfloat16 sm[];
    int tid = threadIdx.x;
    int wid = tid >> 5, lane = tid & 31;
    int wr = wid & 3, wc = wid >> 2;
    int gr = lane >> 2, tg = lane & 3;
    int lane15 = lane & 15, laneHi = (lane >> 4) * 8;

    int m0 = blockIdx.y * 128, o0 = blockIdx.x * 128;
    const __nv_bfloat16* Ab = A3 + blockIdx.z * zsA;
    const __nv_bfloat16* Bb = B3 + blockIdx.z * zsB;
    uint32_t sbase = smem_u32(sm);
    int nch = K3 / 64;

    auto issue = [&](int s, int k0) {
#pragma unroll
        for (int i = 0; i < 4; ++i) {
            int e = tid + i * 256;
            int row = e >> 3, seg = e & 7;
            uint32_t da = sbase + (uint32_t)(s * 2 * 128 * LDP + row * LDP + seg * 8) * 2;
            CPA(da, Ab + (size_t)(m0 + row) * lda3 + k0 + seg * 8, 16);
            int brow = o0 + row;
            int srow = brow < Nvalid ? brow : (Nvalid - 1);
            uint32_t db = sbase + (uint32_t)((s * 2 + 1) * 128 * LDP + row * LDP + seg * 8) * 2;
            CPA(db, Bb + (size_t)srow * ldb3 + k0 + seg * 8, brow < Nvalid ? 16 : 0);
        }
        CPA_COMMIT();
    };

    float acc[2][8][4] = {};
    issue(0, 0);
    for (int ch = 0; ch < nch; ++ch) {
        if (ch + 1 < nch) { issue((ch + 1) & 1, (ch + 1) * 64); CPA_WAIT1(); }
        else              { CPA_WAIT0(); }
        __syncthreads();
        uint32_t stage = sbase + (uint32_t)((ch & 1) * 2 * 128 * LDP) * 2;
        uint32_t aRow = stage + (uint32_t)((wr * 32 + lane15) * LDP + laneHi) * 2;
        uint32_t bRow = stage + (uint32_t)(128 * LDP) * 2
                      + (uint32_t)((wc * 64 + lane15) * LDP + laneHi) * 2;
#pragma unroll
        for (int kk = 0; kk < 64; kk += 16) {
            uint32_t af[2][4], bfr[8][2];
            ldsm4(af[0], aRow + kk * 2);
            ldsm4(af[1], aRow + (16 * LDP + kk) * 2);
#pragma unroll
            for (int q = 0; q < 4; ++q) {
                uint32_t t[4];
                ldsm4(t, bRow + (q * 16 * LDP + kk) * 2);
                bfr[2 * q][0]     = t[0];
                bfr[2 * q + 1][0] = t[1];
                bfr[2 * q][1]     = t[2];
                bfr[2 * q + 1][1] = t[3];
            }
#pragma unroll
            for (int mi = 0; mi < 2; ++mi)
#pragma unroll
                for (int ni = 0; ni < 8; ++ni)
                    mma16816(acc[mi][ni], af[mi], bfr[ni]);
        }
        __syncthreads();
    }

    float* outb = out + blockIdx.z * zsO;
    const float* xxb = (mode == 1) ? xx + (size_t)blockIdx.z * zsXX : nullptr;
    float rmn[2][2][2];
#pragma unroll
    for (int i = 0; i < 2; ++i)
#pragma unroll
        for (int j = 0; j < 2; ++j) { rmn[i][j][0] = FLT_MAX; rmn[i][j][1] = FLT_MAX; }

#pragma unroll
    for (int mi = 0; mi < 2; ++mi) {
        int mA = m0 + wr * 32 + mi * 16 + gr;
        float xrA = 0.f, xrB = 0.f;
        if (mode == 1) { xrA = xxb[mA]; xrB = xxb[mA + 8]; }
#pragma unroll
        for (int ni = 0; ni < 8; ++ni) {
            int o = o0 + wc * 64 + ni * 8 + tg * 2;
            if (o < Nvalid) {
                float u0 = acc[mi][ni][0], u1 = acc[mi][ni][1];
                float u2 = acc[mi][ni][2], u3 = acc[mi][ni][3];
                if (mode == 0) {
                    float b0 = bias ? bias[o] : 0.f, b1 = bias ? bias[o + 1] : 0.f;
                    u0 += b0; u1 += b1; u2 += b0; u3 += b1;
                    if (act) {
                        u0 = u0 > 0.f ? u0 : 0.2f * u0;
                        u1 = u1 > 0.f ? u1 : 0.2f * u1;
                        u2 = u2 > 0.f ? u2 : 0.2f * u2;
                        u3 = u3 > 0.f ? u3 : 0.2f * u3;
                    }
                } else {
                    float xc0 = xxb[o], xc1 = xxb[o + 1];
                    u0 = xrA - 2.f * u0 + xc0; u1 = xrA - 2.f * u1 + xc1;
                    u2 = xrB - 2.f * u2 + xc0; u3 = xrB - 2.f * u3 + xc1;
                    int s = ni >> 2;
                    rmn[mi][s][0] = fminf(rmn[mi][s][0], fminf(u0, u1));
                    rmn[mi][s][1] = fminf(rmn[mi][s][1], fminf(u2, u3));
                }
                *(float2*)(outb + (size_t)mA * ldo + o)       = make_float2(u0, u1);
                *(float2*)(outb + (size_t)(mA + 8) * ldo + o) = make_float2(u2, u3);
            }
        }
    }
    if (mode == 1) {
        float* sb = submin + (size_t)blockIdx.z * NN * 64;
#pragma unroll
        for (int mi = 0; mi < 2; ++mi)
#pragma unroll
            for (int s = 0; s < 2; ++s)
#pragma unroll
                for (int rr = 0; rr < 2; ++rr) {
                    float v = rmn[mi][s][rr];
                    v = fminf(v, __shfl_xor_sync(0xffffffffu, v, 1));
                    v = fminf(v, __shfl_xor_sync(0xffffffffu, v, 2));
                    if (tg == 0) {
                        int grow = m0 + wr * 32 + mi * 16 + gr + rr * 8;
                        sb[(size_t)grow * 64 + blockIdx.x * 4 + wc * 2 + s] = v;
                    }
                }
    }
}

// =================== threshold-filter top-K, bitonic select (exact) ===============
__global__ void __launch_bounds__(256, 6)
topk_sel(const float* __restrict__ d2, const float* __restrict__ submin,
         int* __restrict__ idxout, int* __restrict__ ovflag) {
    __shared__ unsigned long long fl[8][CAP];
    int w = threadIdx.x >> 5, lane = threadIdx.x & 31;
    const unsigned FM = 0xffffffffu;
    size_t row = (size_t)blockIdx.x * 8 + w;
    const float* r = d2 + row * NN;

    fl[w][lane] = ~0ULL; fl[w][lane + 32] = ~0ULL;
    fl[w][lane + 64] = ~0ULL; fl[w][lane + 96] = ~0ULL;
    __syncwarp();

    float s0f = submin[row * 64 + lane];
    float s1f = submin[row * 64 + 32 + lane];
    unsigned sv[2] = { mono(s0f), mono(s1f) };
#pragma unroll
    for (unsigned k = 2; k <= 64; k <<= 1) {
#pragma unroll
        for (unsigned d = 32; d; d >>= 1) {
            if (d >= k) continue;
            if (d == 32) {
                unsigned a = sv[0], b = sv[1];
                sv[0] = a < b ? a : b;
                sv[1] = a < b ? b : a;
            } else {
#pragma unroll
                for (int j = 0; j < 2; ++j) {
                    unsigned v = j * 32 + lane;
                    unsigned o = __shfl_xor_sync(FM, sv[j], d);
                    bool dir = ((v & k) == 0);
                    bool lower = ((lane & d) == 0);
                    bool takeMin = (lower == dir);
                    unsigned mn = o < sv[j] ? o : sv[j];
                    unsigned mx = o < sv[j] ? sv[j] : o;
                    sv[j] = takeMin ? mn : mx;
                }
            }
        }
    }
    unsigned T = __shfl_sync(FM, sv[0], 19);
    float Tf = unmono(T);

    unsigned mask0 = __ballot_sync(FM, s0f <= Tf);
    unsigned mask1 = __ballot_sync(FM, s1f <= Tf);
    unsigned long long mask = ((unsigned long long)mask1 << 32) | mask0;
    unsigned lmlt = (1u << lane) - 1;
    int base = 0;
    while (mask) {
        int s0 = __ffsll((long long)mask) - 1; mask &= mask - 1;
        int s1 = -1;
        if (mask) { s1 = __ffsll((long long)mask) - 1; mask &= mask - 1; }
        float v0 = r[s0 * 32 + lane];
        float v1 = (s1 >= 0) ? r[s1 * 32 + lane] : FLT_MAX;
        bool h0 = v0 <= Tf;
        unsigned bm0 = __ballot_sync(FM, h0);
        if (h0) {
            int p = base + __popc(bm0 & lmlt);
            if (p < CAP)
                fl[w][p] = ((unsigned long long)mono(v0) << 32) | (unsigned)(s0 * 32 + lane);
        }
        base += __popc(bm0);
        if (s1 >= 0) {
            bool h1 = v1 <= Tf;
            unsigned bm1 = __ballot_sync(FM, h1);
            if (h1) {
                int p = base + __popc(bm1 & lmlt);
                if (p < CAP)
                    fl[w][p] = ((unsigned long long)mono(v1) << 32) | (unsigned)(s1 * 32 + lane);
            }
            base += __popc(bm1);
        }
    }
    __syncwarp();

    int nc = base;
    int ov = nc > CAP;
    if (lane == 0) ovflag[row] = ov;
    if (ov) return;

    if (nc <= 32) {
        unsigned long long c0 = fl[w][lane];
#pragma unroll
        for (unsigned k = 2; k <= 32; k <<= 1) {
#pragma unroll
            for (unsigned d = k >> 1; d; d >>= 1) {
                unsigned long long o = __shfl_xor_sync(FM, c0, d);
                bool dir = ((lane & k) == 0);
                bool lower = ((lane & d) == 0);
                bool takeMin = (lower == dir);
                unsigned long long mn = o < c0 ? o : c0;
                unsigned long long mx = o < c0 ? c0 : o;
                c0 = takeMin ? mn : mx;
            }
        }
        if (lane < KNN)
            idxout[row * KNN + lane] = (int)(c0 & 0xffffffffu);
        return;
    }

    unsigned long long cv[4] = { fl[w][lane], fl[w][lane + 32],
                                 fl[w][lane + 64], fl[w][lane + 96] };
#pragma unroll
    for (unsigned k = 2; k <= 128; k <<= 1) {
#pragma unroll
        for (unsigned d = 64; d; d >>= 1) {
            if (d >= k) continue;
            if (d >= 32) {
                int dj = d >> 5;
#pragma unroll
                for (int j = 0; j < 4; ++j) {
                    if (j & dj) continue;
                    unsigned v = j * 32 + lane;
                    bool dir = ((v & k) == 0);
                    unsigned long long a = cv[j], b = cv[j ^ dj];
                    unsigned long long mn = a < b ? a : b;
                    unsigned long long mx = a < b ? b : a;
                    cv[j]      = dir ? mn : mx;
                    cv[j ^ dj] = dir ? mx : mn;
                }
            } else {
#pragma unroll
                for (int j = 0; j < 4; ++j) {
                    unsigned v = j * 32 + lane;
                    unsigned long long o = __shfl_xor_sync(FM, cv[j], d);
                    bool dir = ((v & k) == 0);
                    bool lower = ((lane & d) == 0);
                    bool takeMin = (lower == dir);
                    unsigned long long mn = o < cv[j] ? o : cv[j];
                    unsigned long long mx = o < cv[j] ? cv[j] : o;
                    cv[j] = takeMin ? mn : mx;
                }
            }
        }
    }
    if (lane < KNN)
        idxout[row * KNN + lane] = (int)(cv[0] & 0xffffffffu);
}

// =================== exact fallback for overflow rows (rare / usually idle) ========
__global__ void __launch_bounds__(256)
topk_fb(const float* __restrict__ d2, const int* __restrict__ ovflag,
        int* __restrict__ idxout) {
    __shared__ unsigned long long fb[8][32 * KNN];
    int w = threadIdx.x >> 5, lane = threadIdx.x & 31;
    const unsigned FM = 0xffffffffu;
    size_t row = (size_t)blockIdx.x * 8 + w;
    if (!ovflag[row]) return;
    const float* r = d2 + row * NN;

    float key[KNN]; int ki[KNN];
#pragma unroll
    for (int j = 0; j < KNN; ++j) { key[j] = FLT_MAX; ki[j] = 0; }
    for (int j = 0; j < 16; ++j) {
        int e0 = 4 * (j * 32 + lane);
        float4 v4 = *(const float4*)(r + e0);
        float vmin = fminf(fminf(v4.x, v4.y), fminf(v4.z, v4.w));
        if (vmin < key[KNN - 1]) {
            float vals[4] = {v4.x, v4.y, v4.z, v4.w};
#pragma unroll
            for (int q = 0; q < 4; ++q) INS(key, ki, vals[q], e0 + q);
        }
    }
#pragma unroll
    for (int j = 0; j < KNN; ++j)
        fb[w][lane * KNN + j] = ((unsigned long long)mono(key[j]) << 32) | (unsigned)ki[j];
    __syncwarp();
    int h = 0;
    unsigned long long hv = fb[w][lane * KNN];
#pragma unroll
    for (int k = 0; k < KNN; ++k) {
        unsigned long long red = hv;
#pragma unroll
        for (int off = 16; off; off >>= 1) {
            unsigned long long o = __shfl_xor_sync(FM, red, off);
            red = o < red ? o : red;
        }
        if (lane == 0) idxout[row * KNN + k] = (int)(red & 0xffffffffu);
        if (hv == red) { ++h; hv = (h < KNN) ? fb[w][lane * KNN + h] : ~0ULL; }
    }
}

// =================== small kernels ===================
__global__ void xx_kernel(const float* __restrict__ X, int ldx, int C,
                          float* __restrict__ xx) {
    int w = threadIdx.x >> 5, lane = threadIdx.x & 31;
    int row = blockIdx.x * 8 + w;
    if (row >= BB * NN) return;
    const float* p = X + (size_t)row * ldx;
    float s = 0.f;
    for (int c = lane; c < C; c += 32) { float v = p[c]; s += v * v; }
#pragma unroll
    for (int off = 16; off; off >>= 1)
        s += __shfl_xor_sync(0xffffffffu, s, off);
    if (lane == 0) xx[row] = s;
}

__global__ void __launch_bounds__(128)
edgemax4(const float* __restrict__ yc, const int* __restrict__ idx,
         float* __restrict__ out, int O, int ldo) {
    __shared__ int sid[8 * KNN];
    int cpp = O >> 2;
    int G = 128 / cpp;
    int b = blockIdx.y;
    int n0 = blockIdx.x * G;
    int t = threadIdx.x;
    for (int i = t; i < G * KNN; i += 128)
        sid[i] = idx[((size_t)b * NN + n0 + i / KNN) * KNN + (i % KNN)];
    __syncthreads();
    int p = t / cpp, c = t % cpp;
    int n = n0 + p;
    size_t mbase = (size_t)b * NN;
    int ld2 = 2 * O;
    const int* sp = &sid[p * KNN];
    float4 m = make_float4(-FLT_MAX, -FLT_MAX, -FLT_MAX, -FLT_MAX);
#pragma unroll
    for (int k = 0; k < KNN; ++k) {
        float4 yn = *(const float4*)(yc + (mbase + sp[k]) * ld2 + 4 * c);
        m.x = fmaxf(m.x, yn.x); m.y = fmaxf(m.y, yn.y);
        m.z = fmaxf(m.z, yn.z); m.w = fmaxf(m.w, yn.w);
    }
    const float* prow = yc + (mbase + n) * ld2 + 4 * c;
    float4 ycn = *(const float4*)prow;
    float4 ccn = *(const float4*)(prow + O);
    float v0 = m.x - ycn.x + ccn.x;
    float v1 = m.y - ycn.y + ccn.y;
    float v2 = m.z - ycn.z + ccn.z;
    float v3 = m.w - ycn.w + ccn.w;
    v0 = v0 > 0.f ? v0 : 0.2f * v0;
    v1 = v1 > 0.f ? v1 : 0.2f * v1;
    v2 = v2 > 0.f ? v2 : 0.2f * v2;
    v3 = v3 > 0.f ? v3 : 0.2f * v3;
    *(float4*)(out + (mbase + n) * ldo + 4 * c) = make_float4(v0, v1, v2, v3);
}

__global__ void maxpool1(const float* __restrict__ tmp, float* __restrict__ part) {
    int b = blockIdx.y, c = blockIdx.z;
    int f = blockIdx.x * blockDim.x + threadIdx.x;
    const float* p = tmp + ((size_t)b * NN + c * 128) * 1024 + f;
    float m = -FLT_MAX;
#pragma unroll 4
    for (int n = 0; n < 128; ++n) m = fmaxf(m, p[(size_t)n * 1024]);
    part[(c * BB + b) * 1024 + f] = m;
}
__global__ void maxpool2(const float* __restrict__ part, float* __restrict__ out) {
    int b = blockIdx.y;
    int f = blockIdx.x * blockDim.x + threadIdx.x;
    float m = -FLT_MAX;
#pragma unroll
    for (int c = 0; c < 16; ++c) m = fmaxf(m, part[(c * BB + b) * 1024 + f]);
    out[b * 1024 + f] = m;
}

// =================== launch ===================
extern "C" void kernel_launch(void* const* d_in, const int* in_sizes, int n_in,
                              void* d_out, int out_size) {
    const float* x     = (const float*)d_in[0];
    const float* Wl[4] = {(const float*)d_in[1], (const float*)d_in[3],
                          (const float*)d_in[5], (const float*)d_in[7]};
    const float* bl[4] = {(const float*)d_in[2], (const float*)d_in[4],
                          (const float*)d_in[6], (const float*)d_in[8]};
    const float* Wf = (const float*)d_in[9];
    const float* bf = (const float*)d_in[10];
    float* out = (float*)d_out;

    float *p_d2, *p_sub, *p_xx, *p_yc, *p_hcat, *p_tmp, *p_part, *p_bias2;
    __nv_bfloat16 *p_a3, *p_b3, *p_bf3, *p_w3;
    int *p_idx, *p_ov;
    cudaGetSymbolAddress((void**)&p_d2,    g_d2);
    cudaGetSymbolAddress((void**)&p_sub,   g_submin);
    cudaGetSymbolAddress((void**)&p_xx,    g_xx);
    cudaGetSymbolAddress((void**)&p_idx,   g_idx);
    cudaGetSymbolAddress((void**)&p_ov,    g_ov);
    cudaGetSymbolAddress((void**)&p_yc,    g_yc);
    cudaGetSymbolAddress((void**)&p_hcat,  g_hcat);
    cudaGetSymbolAddress((void**)&p_tmp,   g_tmp);
    cudaGetSymbolAddress((void**)&p_part,  g_part);
    cudaGetSymbolAddress((void**)&p_bias2, g_bias2);
    cudaGetSymbolAddress((void**)&p_a3,    g_a3);
    cudaGetSymbolAddress((void**)&p_b3,    g_b3);
    cudaGetSymbolAddress((void**)&p_bf3,   g_bf3);
    cudaGetSymbolAddress((void**)&p_w3,    g_w3);

    cudaFuncSetAttribute(mma_gemm, cudaFuncAttributeMaxDynamicSharedMemorySize,
                         MMA_SMEM);

    // one-time host-side stream/event resources (no device memory)
    static cudaStream_t s_aux = nullptr;
    static cudaEvent_t evF = nullptr, evJ = nullptr;
    if (!s_aux) {
        cudaStreamCreateWithFlags(&s_aux, cudaStreamNonBlocking);
        cudaEventCreateWithFlags(&evF, cudaEventDisableTiming);
        cudaEventCreateWithFlags(&evJ, cudaEventDisableTiming);
    }

    const int Cs[4]  = {3, 64, 64, 128};
    const int Os[4]  = {64, 64, 128, 256};
    const int off[4] = {0, 64, 128, 256};

    // Wf conversion depends only on input: fork it onto aux stream immediately.
    cudaEventRecord(evF, 0);
    cudaStreamWaitEvent(s_aux, evF, 0);
    {
        int tot = 1024 * 1536;
        convB_kernel<<<(tot + 255) / 256, 256, 0, s_aux>>>(Wf, 512, 512, p_bf3, 1536, tot);
    }

    const float* Xin = x;
    int ldx = 3;
    for (int l = 0; l < 4; ++l) {
        int C = Cs[l], O = Os[l];
        int K3 = ((3 * C + 63) / 64) * 64;     // 64, 192, 192, 384
        int G = 512 / O;                       // points per edgemax block

        xx_kernel<<<(BB * NN) / 8, 256>>>(Xin, ldx, C, p_xx);
        {
            int tot = BB * NN * K3;
            convAB_kernel<<<(tot + 255) / 256, 256>>>(Xin, ldx, C, p_a3, p_b3, K3, tot);
        }
        // fork: stream0 = knn chain; s_aux = yc chain
        cudaEventRecord(evF, 0);
        cudaStreamWaitEvent(s_aux, evF, 0);

        mma_gemm<<<dim3(16, 16, BB), 256, MMA_SMEM>>>(
            p_a3, K3, (size_t)NN * K3, p_b3, K3, (size_t)NN * K3,
            NN, K3, p_d2, NN, (size_t)NN * NN, nullptr, 0, 1, p_xx, NN, p_sub);
        topk_sel<<<(BB * NN) / 8, 256>>>(p_d2, p_sub, p_idx, p_ov);
        topk_fb<<<(BB * NN) / 8, 256>>>(p_d2, p_ov, p_idx);

        {
            int totw = O * K3;
            convB_kernel<<<(totw + 255) / 256, 256, 0, s_aux>>>(
                Wl[l], 2 * C, C, p_w3, K3, totw);
            convB_kernel<<<(totw + 255) / 256, 256, 0, s_aux>>>(
                Wl[l] + C, 2 * C, C, p_w3 + (size_t)O * K3, K3, totw);
        }
        biascat<<<1, 512, 0, s_aux>>>(bl[l], p_bias2, O);
        mma_gemm<<<dim3((2 * O + 127) / 128, (BB * NN) / 128, 1), 256, MMA_SMEM, s_aux>>>(
            p_a3, K3, 0, p_w3, K3, 0, 2 * O, K3,
            p_yc, 2 * O, 0, p_bias2, 0, 0, nullptr, 0, nullptr);
        cudaEventRecord(evJ, s_aux);
        cudaStreamWaitEvent(0, evJ, 0);

        edgemax4<<<dim3(NN / G, BB), 128>>>(p_yc, p_idx, p_hcat + off[l], O, 512);
        Xin = p_hcat + off[l];
        ldx = 512;
    }
    // final 512 -> 1024 linear + leaky, then max over N (two-stage pool)
    {
        int tot = BB * NN * 1536;
        convA_kernel<<<(tot + 255) / 256, 256>>>(p_hcat, 512, 512, p_a3, 1536, tot);
    }
    mma_gemm<<<dim3(1024 / 128, (BB * NN) / 128, 1), 256, MMA_SMEM>>>(
        p_a3, 1536, 0, p_bf3, 1536, 0, 1024, 1536,
        p_tmp, 1024, 0, bf, 1, 0, nullptr, 0, nullptr);
    maxpool1<<<dim3(1024 / 256, BB, 16), 256>>>(p_tmp, p_part);
    maxpool2<<<dim3(1024 / 256, BB), 256>>>(p_part, out);
}

// round 16
// speedup vs baseline: 2.9243x; 1.0379x over previous
#include <cuda_runtime.h>
#include <cuda_bf16.h>
#include <float.h>
#include <math.h>
#include <cstdint>

#define BB  8
#define NN  2048
#define KNN 20
#define CAP 128   // candidate cap per row before fallback (= bitonic width)

// ---------------- scratch (device globals; no allocations) ----------------
__device__ __align__(16) float g_d2[(size_t)BB * NN * NN];
__device__ __align__(16) float g_submin[(size_t)BB * NN * 64];
__device__ __align__(16) float g_xx[BB * NN];
__device__ __align__(16) int   g_idx[BB * NN * KNN];
__device__ __align__(16) int   g_ov[BB * NN];
__device__ __align__(16) float g_yc[(size_t)BB * NN * 512];    // y | c combined
__device__ __align__(16) float g_hcat[(size_t)BB * NN * 512];
__device__ __align__(16) float g_part[16 * BB * 1024];
__device__ __align__(16) float g_bias2[512];
__device__ __align__(16) __nv_bfloat16 g_a3[(size_t)BB * NN * 1536];  // split A (h|l|h)
__device__ __align__(16) __nv_bfloat16 g_b3[(size_t)BB * NN * 384];   // split B (h|h|l)
__device__ __align__(16) __nv_bfloat16 g_bf3[1024 * 1536];            // split Wf
__device__ __align__(16) __nv_bfloat16 g_w3[512 * 384];               // split layer W (y|c)

// =================== split-precision conversion kernels (linear index) =============
__global__ void convAB_kernel(const float* __restrict__ in, int ld, int C,
                              __nv_bfloat16* __restrict__ a3,
                              __nv_bfloat16* __restrict__ b3, int K3, int total) {
    int i = blockIdx.x * 256 + threadIdx.x;
    if (i >= total) return;
    int r = i / K3, c = i - r * K3;
    size_t ro = (size_t)r * K3;
    if (c < C) {
        float xv = in[(size_t)r * ld + c];
        __nv_bfloat16 h = __float2bfloat16(xv);
        __nv_bfloat16 l = __float2bfloat16(xv - __bfloat162float(h));
        a3[ro + c] = h; a3[ro + C + c] = l; a3[ro + 2 * C + c] = h;
        b3[ro + c] = h; b3[ro + C + c] = h; b3[ro + 2 * C + c] = l;
    } else if (c >= 3 * C) {
        __nv_bfloat16 z = __float2bfloat16(0.f);
        a3[ro + c] = z; b3[ro + c] = z;
    }
}
__global__ void convA_kernel(const float* __restrict__ in, int ld, int C,
                             __nv_bfloat16* __restrict__ out, int K3, int total) {
    int i = blockIdx.x * 256 + threadIdx.x;
    if (i >= total) return;
    int r = i / K3, c = i - r * K3;
    size_t ro = (size_t)r * K3;
    if (c < C) {
        float xv = in[(size_t)r * ld + c];
        __nv_bfloat16 h = __float2bfloat16(xv);
        __nv_bfloat16 l = __float2bfloat16(xv - __bfloat162float(h));
        out[ro + c] = h; out[ro + C + c] = l; out[ro + 2 * C + c] = h;
    } else if (c >= 3 * C) {
        out[ro + c] = __float2bfloat16(0.f);
    }
}
__global__ void convB_kernel(const float* __restrict__ in, int ld, int C,
                             __nv_bfloat16* __restrict__ out, int K3, int total) {
    int i = blockIdx.x * 256 + threadIdx.x;
    if (i >= total) return;
    int r = i / K3, c = i - r * K3;
    size_t ro = (size_t)r * K3;
    if (c < C) {
        float xv = in[(size_t)r * ld + c];
        __nv_bfloat16 h = __float2bfloat16(xv);
        __nv_bfloat16 l = __float2bfloat16(xv - __bfloat162float(h));
        out[ro + c] = h; out[ro + C + c] = h; out[ro + 2 * C + c] = l;
    } else if (c >= 3 * C) {
        out[ro + c] = __float2bfloat16(0.f);
    }
}
__global__ void biascat(const float* __restrict__ bl, float* __restrict__ out, int O) {
    int i = threadIdx.x;
    if (i < O) out[i] = 0.f;
    else if (i < 2 * O) out[i] = bl[i - O];
}

#define LDP 72

__device__ __forceinline__ void mma16816(float* d, const uint32_t* a, const uint32_t* b) {
    asm volatile(
        "mma.sync.aligned.m16n8k16.row.col.f32.bf16.bf16.f32 "
        "{%0,%1,%2,%3}, {%4,%5,%6,%7}, {%8,%9}, {%0,%1,%2,%3};"
        : "+f"(d[0]), "+f"(d[1]), "+f"(d[2]), "+f"(d[3])
        : "r"(a[0]), "r"(a[1]), "r"(a[2]), "r"(a[3]), "r"(b[0]), "r"(b[1]));
}
__device__ __forceinline__ void ldsm4(uint32_t* r, uint32_t addr) {
    asm volatile("ldmatrix.sync.aligned.m8n8.x4.shared.b16 {%0,%1,%2,%3}, [%4];"
        : "=r"(r[0]), "=r"(r[1]), "=r"(r[2]), "=r"(r[3]) : "r"(addr));
}
__device__ __forceinline__ uint32_t smem_u32(const void* p) {
    uint32_t a;
    asm("{ .reg .u64 t; cvta.to.shared.u64 t, %1; cvt.u32.u64 %0, t; }" : "=r"(a) : "l"(p));
    return a;
}
__device__ __forceinline__ unsigned mono(float v) {
    unsigned u = __float_as_uint(v);
    return (u & 0x80000000u) ? ~u : (u | 0x80000000u);
}
__device__ __forceinline__ float unmono(unsigned m) {
    unsigned u = (m & 0x80000000u) ? (m ^ 0x80000000u) : ~m;
    return __uint_as_float(u);
}
#define CPA(dst, src, n) \
    asm volatile("cp.async.cg.shared.global [%0], [%1], 16, %2;" \
                 :: "r"(dst), "l"(src), "r"(n))
#define CPA_COMMIT() asm volatile("cp.async.commit_group;" ::: "memory")
#define CPA_WAIT1()  asm volatile("cp.async.wait_group 1;" ::: "memory")
#define CPA_WAIT0()  asm volatile("cp.async.wait_group 0;" ::: "memory")

#define INS(keys, kidx, v, ix) do { \
    if ((v) < keys[KNN - 1]) { \
        float _cv = (v); int _ci = (ix); \
        _Pragma("unroll") \
        for (int _j = 0; _j < KNN; ++_j) { \
            if (_cv < keys[_j]) { \
                float _tv = keys[_j]; keys[_j] = _cv; _cv = _tv; \
                int _ti = kidx[_j]; kidx[_j] = _ci; _ci = _ti; \
            } \
        } \
    } } while (0)

#define MMA_SMEM (2 * 2 * 128 * LDP * 2)

// =================== cp.async-pipelined mma.sync GEMM, 128x128 tile ===============
// mode 0: out[m][o] = acc + bias[o]  (leaky if act)
// mode 1: out[m][o] = xx[m] - 2*acc + xx[o]; also emits 32-col subtile row-mins
__global__ void __launch_bounds__(256)
mma_gemm(const __nv_bfloat16* __restrict__ A3, int lda3, size_t zsA,
         const __nv_bfloat16* __restrict__ B3, int ldb3, size_t zsB,
         int Nvalid, int K3,
         float* __restrict__ out, int ldo, size_t zsO,
         const float* __restrict__ bias, int act,
         int mode, const float* __restrict__ xx, int zsXX,
         float* __restrict__ submin) {
    extern __shared__ __nv_bfloat16 sm[];
    int tid = threadIdx.x;
    int wid = tid >> 5, lane = tid & 31;
    int wr = wid & 3, wc = wid >> 2;
    int gr = lane >> 2, tg = lane & 3;
    int lane15 = lane & 15, laneHi = (lane >> 4) * 8;

    int m0 = blockIdx.y * 128, o0 = blockIdx.x * 128;
    const __nv_bfloat16* Ab = A3 + blockIdx.z * zsA;
    const __nv_bfloat16* Bb = B3 + blockIdx.z * zsB;
    uint32_t sbase = smem_u32(sm);
    int nch = K3 / 64;

    auto issue = [&](int s, int k0) {
#pragma unroll
        for (int i = 0; i < 4; ++i) {
            int e = tid + i * 256;
            int row = e >> 3, seg = e & 7;
            uint32_t da = sbase + (uint32_t)(s * 2 * 128 * LDP + row * LDP + seg * 8) * 2;
            CPA(da, Ab + (size_t)(m0 + row) * lda3 + k0 + seg * 8, 16);
            int brow = o0 + row;
            int srow = brow < Nvalid ? brow : (Nvalid - 1);
            uint32_t db = sbase + (uint32_t)((s * 2 + 1) * 128 * LDP + row * LDP + seg * 8) * 2;
            CPA(db, Bb + (size_t)srow * ldb3 + k0 + seg * 8, brow < Nvalid ? 16 : 0);
        }
        CPA_COMMIT();
    };

    float acc[2][8][4] = {};
    issue(0, 0);
    for (int ch = 0; ch < nch; ++ch) {
        if (ch + 1 < nch) { issue((ch + 1) & 1, (ch + 1) * 64); CPA_WAIT1(); }
        else              { CPA_WAIT0(); }
        __syncthreads();
        uint32_t stage = sbase + (uint32_t)((ch & 1) * 2 * 128 * LDP) * 2;
        uint32_t aRow = stage + (uint32_t)((wr * 32 + lane15) * LDP + laneHi) * 2;
        uint32_t bRow = stage + (uint32_t)(128 * LDP) * 2
                      + (uint32_t)((wc * 64 + lane15) * LDP + laneHi) * 2;
#pragma unroll
        for (int kk = 0; kk < 64; kk += 16) {
            uint32_t af[2][4], bfr[8][2];
            ldsm4(af[0], aRow + kk * 2);
            ldsm4(af[1], aRow + (16 * LDP + kk) * 2);
#pragma unroll
            for (int q = 0; q < 4; ++q) {
                uint32_t t[4];
                ldsm4(t, bRow + (q * 16 * LDP + kk) * 2);
                bfr[2 * q][0]     = t[0];
                bfr[2 * q + 1][0] = t[1];
                bfr[2 * q][1]     = t[2];
                bfr[2 * q + 1][1] = t[3];
            }
#pragma unroll
            for (int mi = 0; mi < 2; ++mi)
#pragma unroll
                for (int ni = 0; ni < 8; ++ni)
                    mma16816(acc[mi][ni], af[mi], bfr[ni]);
        }
        __syncthreads();
    }

    float* outb = out + blockIdx.z * zsO;
    const float* xxb = (mode == 1) ? xx + (size_t)blockIdx.z * zsXX : nullptr;
    float rmn[2][2][2];
#pragma unroll
    for (int i = 0; i < 2; ++i)
#pragma unroll
        for (int j = 0; j < 2; ++j) { rmn[i][j][0] = FLT_MAX; rmn[i][j][1] = FLT_MAX; }

#pragma unroll
    for (int mi = 0; mi < 2; ++mi) {
        int mA = m0 + wr * 32 + mi * 16 + gr;
        float xrA = 0.f, xrB = 0.f;
        if (mode == 1) { xrA = xxb[mA]; xrB = xxb[mA + 8]; }
#pragma unroll
        for (int ni = 0; ni < 8; ++ni) {
            int o = o0 + wc * 64 + ni * 8 + tg * 2;
            if (o < Nvalid) {
                float u0 = acc[mi][ni][0], u1 = acc[mi][ni][1];
                float u2 = acc[mi][ni][2], u3 = acc[mi][ni][3];
                if (mode == 0) {
                    float b0 = bias ? bias[o] : 0.f, b1 = bias ? bias[o + 1] : 0.f;
                    u0 += b0; u1 += b1; u2 += b0; u3 += b1;
                    if (act) {
                        u0 = u0 > 0.f ? u0 : 0.2f * u0;
                        u1 = u1 > 0.f ? u1 : 0.2f * u1;
                        u2 = u2 > 0.f ? u2 : 0.2f * u2;
                        u3 = u3 > 0.f ? u3 : 0.2f * u3;
                    }
                } else {
                    float xc0 = xxb[o], xc1 = xxb[o + 1];
                    u0 = xrA - 2.f * u0 + xc0; u1 = xrA - 2.f * u1 + xc1;
                    u2 = xrB - 2.f * u2 + xc0; u3 = xrB - 2.f * u3 + xc1;
                    int s = ni >> 2;
                    rmn[mi][s][0] = fminf(rmn[mi][s][0], fminf(u0, u1));
                    rmn[mi][s][1] = fminf(rmn[mi][s][1], fminf(u2, u3));
                }
                *(float2*)(outb + (size_t)mA * ldo + o)       = make_float2(u0, u1);
                *(float2*)(outb + (size_t)(mA + 8) * ldo + o) = make_float2(u2, u3);
            }
        }
    }
    if (mode == 1) {
        float* sb = submin + (size_t)blockIdx.z * NN * 64;
#pragma unroll
        for (int mi = 0; mi < 2; ++mi)
#pragma unroll
            for (int s = 0; s < 2; ++s)
#pragma unroll
                for (int rr = 0; rr < 2; ++rr) {
                    float v = rmn[mi][s][rr];
                    v = fminf(v, __shfl_xor_sync(0xffffffffu, v, 1));
                    v = fminf(v, __shfl_xor_sync(0xffffffffu, v, 2));
                    if (tg == 0) {
                        int grow = m0 + wr * 32 + mi * 16 + gr + rr * 8;
                        sb[(size_t)grow * 64 + blockIdx.x * 4 + wc * 2 + s] = v;
                    }
                }
    }
}

// ============ final GEMM with fused bias+leaky+max-over-rows epilogue =============
// Each block owns a 128x128 tile (rows all in one batch); writes one 128-col
// partial max to part[(tile_in_batch*BB + b)*1024 + o].
__global__ void __launch_bounds__(256)
mma_gemm_pool(const __nv_bfloat16* __restrict__ A3, int lda3,
              const __nv_bfloat16* __restrict__ B3, int ldb3, int K3,
              const float* __restrict__ bias, float* __restrict__ part) {
    extern __shared__ __nv_bfloat16 sm[];
    int tid = threadIdx.x;
    int wid = tid >> 5, lane = tid & 31;
    int wr = wid & 3, wc = wid >> 2;
    int gr = lane >> 2, tg = lane & 3;
    int lane15 = lane & 15, laneHi = (lane >> 4) * 8;

    int m0 = blockIdx.y * 128, o0 = blockIdx.x * 128;
    uint32_t sbase = smem_u32(sm);
    int nch = K3 / 64;

    auto issue = [&](int s, int k0) {
#pragma unroll
        for (int i = 0; i < 4; ++i) {
            int e = tid + i * 256;
            int row = e >> 3, seg = e & 7;
            uint32_t da = sbase + (uint32_t)(s * 2 * 128 * LDP + row * LDP + seg * 8) * 2;
            CPA(da, A3 + (size_t)(m0 + row) * lda3 + k0 + seg * 8, 16);
            uint32_t db = sbase + (uint32_t)((s * 2 + 1) * 128 * LDP + row * LDP + seg * 8) * 2;
            CPA(db, B3 + (size_t)(o0 + row) * ldb3 + k0 + seg * 8, 16);
        }
        CPA_COMMIT();
    };

    float acc[2][8][4] = {};
    issue(0, 0);
    for (int ch = 0; ch < nch; ++ch) {
        if (ch + 1 < nch) { issue((ch + 1) & 1, (ch + 1) * 64); CPA_WAIT1(); }
        else              { CPA_WAIT0(); }
        __syncthreads();
        uint32_t stage = sbase + (uint32_t)((ch & 1) * 2 * 128 * LDP) * 2;
        uint32_t aRow = stage + (uint32_t)((wr * 32 + lane15) * LDP + laneHi) * 2;
        uint32_t bRow = stage + (uint32_t)(128 * LDP) * 2
                      + (uint32_t)((wc * 64 + lane15) * LDP + laneHi) * 2;
#pragma unroll
        for (int kk = 0; kk < 64; kk += 16) {
            uint32_t af[2][4], bfr[8][2];
            ldsm4(af[0], aRow + kk * 2);
            ldsm4(af[1], aRow + (16 * LDP + kk) * 2);
#pragma unroll
            for (int q = 0; q < 4; ++q) {
                uint32_t t[4];
                ldsm4(t, bRow + (q * 16 * LDP + kk) * 2);
                bfr[2 * q][0]     = t[0];
                bfr[2 * q + 1][0] = t[1];
                bfr[2 * q][1]     = t[2];
                bfr[2 * q + 1][1] = t[3];
            }
#pragma unroll
            for (int mi = 0; mi < 2; ++mi)
#pragma unroll
                for (int ni = 0; ni < 8; ++ni)
                    mma16816(acc[mi][ni], af[mi], bfr[ni]);
        }
        __syncthreads();
    }

    // bias + leaky + per-column max over this block's 128 rows
    float cm[8][2];
#pragma unroll
    for (int ni = 0; ni < 8; ++ni) { cm[ni][0] = -FLT_MAX; cm[ni][1] = -FLT_MAX; }
#pragma unroll
    for (int mi = 0; mi < 2; ++mi)
#pragma unroll
        for (int ni = 0; ni < 8; ++ni) {
            int o = o0 + wc * 64 + ni * 8 + tg * 2;
            float b0 = bias[o], b1 = bias[o + 1];
            float u0 = acc[mi][ni][0] + b0, u1 = acc[mi][ni][1] + b1;
            float u2 = acc[mi][ni][2] + b0, u3 = acc[mi][ni][3] + b1;
            u0 = u0 > 0.f ? u0 : 0.2f * u0;
            u1 = u1 > 0.f ? u1 : 0.2f * u1;
            u2 = u2 > 0.f ? u2 : 0.2f * u2;
            u3 = u3 > 0.f ? u3 : 0.2f * u3;
            cm[ni][0] = fmaxf(cm[ni][0], fmaxf(u0, u2));
            cm[ni][1] = fmaxf(cm[ni][1], fmaxf(u1, u3));
        }
    // reduce over gr (lane bits 2..4)
#pragma unroll
    for (int off = 4; off <= 16; off <<= 1)
#pragma unroll
        for (int ni = 0; ni < 8; ++ni) {
            cm[ni][0] = fmaxf(cm[ni][0], __shfl_xor_sync(0xffffffffu, cm[ni][0], off));
            cm[ni][1] = fmaxf(cm[ni][1], __shfl_xor_sync(0xffffffffu, cm[ni][1], off));
        }
    float* smax = (float*)sm;                     // [4][128]
    if (gr == 0) {
#pragma unroll
        for (int ni = 0; ni < 8; ++ni) {
            int c = wc * 64 + ni * 8 + tg * 2;
            smax[wr * 128 + c]     = cm[ni][0];
            smax[wr * 128 + c + 1] = cm[ni][1];
        }
    }
    __syncthreads();
    if (tid < 128) {
        float m = fmaxf(fmaxf(smax[tid], smax[128 + tid]),
                        fmaxf(smax[256 + tid], smax[384 + tid]));
        int ty = blockIdx.y;
        int b = ty >> 4, tb = ty & 15;
        part[(tb * BB + b) * 1024 + o0 + tid] = m;
    }
}

// =================== threshold-filter top-K, bitonic select (exact) ===============
__global__ void __launch_bounds__(256, 6)
topk_sel(const float* __restrict__ d2, const float* __restrict__ submin,
         int* __restrict__ idxout, int* __restrict__ ovflag) {
    __shared__ unsigned long long fl[8][CAP];
    int w = threadIdx.x >> 5, lane = threadIdx.x & 31;
    const unsigned FM = 0xffffffffu;
    size_t row = (size_t)blockIdx.x * 8 + w;
    const float* r = d2 + row * NN;

    fl[w][lane] = ~0ULL; fl[w][lane + 32] = ~0ULL;
    fl[w][lane + 64] = ~0ULL; fl[w][lane + 96] = ~0ULL;
    __syncwarp();

    float s0f = submin[row * 64 + lane];
    float s1f = submin[row * 64 + 32 + lane];
    unsigned sv[2] = { mono(s0f), mono(s1f) };
#pragma unroll
    for (unsigned k = 2; k <= 64; k <<= 1) {
#pragma unroll
        for (unsigned d = 32; d; d >>= 1) {
            if (d >= k) continue;
            if (d == 32) {
                unsigned a = sv[0], b = sv[1];
                sv[0] = a < b ? a : b;
                sv[1] = a < b ? b : a;
            } else {
#pragma unroll
                for (int j = 0; j < 2; ++j) {
                    unsigned v = j * 32 + lane;
                    unsigned o = __shfl_xor_sync(FM, sv[j], d);
                    bool dir = ((v & k) == 0);
                    bool lower = ((lane & d) == 0);
                    bool takeMin = (lower == dir);
                    unsigned mn = o < sv[j] ? o : sv[j];
                    unsigned mx = o < sv[j] ? sv[j] : o;
                    sv[j] = takeMin ? mn : mx;
                }
            }
        }
    }
    unsigned T = __shfl_sync(FM, sv[0], 19);
    float Tf = unmono(T);

    unsigned mask0 = __ballot_sync(FM, s0f <= Tf);
    unsigned mask1 = __ballot_sync(FM, s1f <= Tf);
    unsigned long long mask = ((unsigned long long)mask1 << 32) | mask0;
    unsigned lmlt = (1u << lane) - 1;
    int base = 0;
    while (mask) {
        int s0 = __ffsll((long long)mask) - 1; mask &= mask - 1;
        int s1 = -1;
        if (mask) { s1 = __ffsll((long long)mask) - 1; mask &= mask - 1; }
        float v0 = r[s0 * 32 + lane];
        float v1 = (s1 >= 0) ? r[s1 * 32 + lane] : FLT_MAX;
        bool h0 = v0 <= Tf;
        unsigned bm0 = __ballot_sync(FM, h0);
        if (h0) {
            int p = base + __popc(bm0 & lmlt);
            if (p < CAP)
                fl[w][p] = ((unsigned long long)mono(v0) << 32) | (unsigned)(s0 * 32 + lane);
        }
        base += __popc(bm0);
        if (s1 >= 0) {
            bool h1 = v1 <= Tf;
            unsigned bm1 = __ballot_sync(FM, h1);
            if (h1) {
                int p = base + __popc(bm1 & lmlt);
                if (p < CAP)
                    fl[w][p] = ((unsigned long long)mono(v1) << 32) | (unsigned)(s1 * 32 + lane);
            }
            base += __popc(bm1);
        }
    }
    __syncwarp();

    int nc = base;
    int ov = nc > CAP;
    if (lane == 0) ovflag[row] = ov;
    if (ov) return;

    if (nc <= 32) {
        unsigned long long c0 = fl[w][lane];
#pragma unroll
        for (unsigned k = 2; k <= 32; k <<= 1) {
#pragma unroll
            for (unsigned d = k >> 1; d; d >>= 1) {
                unsigned long long o = __shfl_xor_sync(FM, c0, d);
                bool dir = ((lane & k) == 0);
                bool lower = ((lane & d) == 0);
                bool takeMin = (lower == dir);
                unsigned long long mn = o < c0 ? o : c0;
                unsigned long long mx = o < c0 ? c0 : o;
                c0 = takeMin ? mn : mx;
            }
        }
        if (lane < KNN)
            idxout[row * KNN + lane] = (int)(c0 & 0xffffffffu);
        return;
    }

    unsigned long long cv[4] = { fl[w][lane], fl[w][lane + 32],
                                 fl[w][lane + 64], fl[w][lane + 96] };
#pragma unroll
    for (unsigned k = 2; k <= 128; k <<= 1) {
#pragma unroll
        for (unsigned d = 64; d; d >>= 1) {
            if (d >= k) continue;
            if (d >= 32) {
                int dj = d >> 5;
#pragma unroll
                for (int j = 0; j < 4; ++j) {
                    if (j & dj) continue;
                    unsigned v = j * 32 + lane;
                    bool dir = ((v & k) == 0);
                    unsigned long long a = cv[j], b = cv[j ^ dj];
                    unsigned long long mn = a < b ? a : b;
                    unsigned long long mx = a < b ? b : a;
                    cv[j]      = dir ? mn : mx;
                    cv[j ^ dj] = dir ? mx : mn;
                }
            } else {
#pragma unroll
                for (int j = 0; j < 4; ++j) {
                    unsigned v = j * 32 + lane;
                    unsigned long long o = __shfl_xor_sync(FM, cv[j], d);
                    bool dir = ((v & k) == 0);
                    bool lower = ((lane & d) == 0);
                    bool takeMin = (lower == dir);
                    unsigned long long mn = o < cv[j] ? o : cv[j];
                    unsigned long long mx = o < cv[j] ? cv[j] : o;
                    cv[j] = takeMin ? mn : mx;
                }
            }
        }
    }
    if (lane < KNN)
        idxout[row * KNN + lane] = (int)(cv[0] & 0xffffffffu);
}

// =================== exact fallback for overflow rows (rare / usually idle) ========
__global__ void __launch_bounds__(256)
topk_fb(const float* __restrict__ d2, const int* __restrict__ ovflag,
        int* __restrict__ idxout) {
    __shared__ unsigned long long fb[8][32 * KNN];
    int w = threadIdx.x >> 5, lane = threadIdx.x & 31;
    const unsigned FM = 0xffffffffu;
    size_t row = (size_t)blockIdx.x * 8 + w;
    if (!ovflag[row]) return;
    const float* r = d2 + row * NN;

    float key[KNN]; int ki[KNN];
#pragma unroll
    for (int j = 0; j < KNN; ++j) { key[j] = FLT_MAX; ki[j] = 0; }
    for (int j = 0; j < 16; ++j) {
        int e0 = 4 * (j * 32 + lane);
        float4 v4 = *(const float4*)(r + e0);
        float vmin = fminf(fminf(v4.x, v4.y), fminf(v4.z, v4.w));
        if (vmin < key[KNN - 1]) {
            float vals[4] = {v4.x, v4.y, v4.z, v4.w};
#pragma unroll
            for (int q = 0; q < 4; ++q) INS(key, ki, vals[q], e0 + q);
        }
    }
#pragma unroll
    for (int j = 0; j < KNN; ++j)
        fb[w][lane * KNN + j] = ((unsigned long long)mono(key[j]) << 32) | (unsigned)ki[j];
    __syncwarp();
    int h = 0;
    unsigned long long hv = fb[w][lane * KNN];
#pragma unroll
    for (int k = 0; k < KNN; ++k) {
        unsigned long long red = hv;
#pragma unroll
        for (int off = 16; off; off >>= 1) {
            unsigned long long o = __shfl_xor_sync(FM, red, off);
            red = o < red ? o : red;
        }
        if (lane == 0) idxout[row * KNN + k] = (int)(red & 0xffffffffu);
        if (hv == red) { ++h; hv = (h < KNN) ? fb[w][lane * KNN + h] : ~0ULL; }
    }
}

// =================== small kernels ===================
__global__ void xx_kernel(const float* __restrict__ X, int ldx, int C,
                          float* __restrict__ xx) {
    int w = threadIdx.x >> 5, lane = threadIdx.x & 31;
    int row = blockIdx.x * 8 + w;
    if (row >= BB * NN) return;
    const float* p = X + (size_t)row * ldx;
    float s = 0.f;
    for (int c = lane; c < C; c += 32) { float v = p[c]; s += v * v; }
#pragma unroll
    for (int off = 16; off; off >>= 1)
        s += __shfl_xor_sync(0xffffffffu, s, off);
    if (lane == 0) xx[row] = s;
}

__global__ void __launch_bounds__(128)
edgemax4(const float* __restrict__ yc, const int* __restrict__ idx,
         float* __restrict__ out, int O, int ldo) {
    __shared__ int sid[8 * KNN];
    int cpp = O >> 2;
    int G = 128 / cpp;
    int b = blockIdx.y;
    int n0 = blockIdx.x * G;
    int t = threadIdx.x;
    for (int i = t; i < G * KNN; i += 128)
        sid[i] = idx[((size_t)b * NN + n0 + i / KNN) * KNN + (i % KNN)];
    __syncthreads();
    int p = t / cpp, c = t % cpp;
    int n = n0 + p;
    size_t mbase = (size_t)b * NN;
    int ld2 = 2 * O;
    const int* sp = &sid[p * KNN];
    float4 m = make_float4(-FLT_MAX, -FLT_MAX, -FLT_MAX, -FLT_MAX);
#pragma unroll
    for (int k = 0; k < KNN; ++k) {
        float4 yn = *(const float4*)(yc + (mbase + sp[k]) * ld2 + 4 * c);
        m.x = fmaxf(m.x, yn.x); m.y = fmaxf(m.y, yn.y);
        m.z = fmaxf(m.z, yn.z); m.w = fmaxf(m.w, yn.w);
    }
    const float* prow = yc + (mbase + n) * ld2 + 4 * c;
    float4 ycn = *(const float4*)prow;
    float4 ccn = *(const float4*)(prow + O);
    float v0 = m.x - ycn.x + ccn.x;
    float v1 = m.y - ycn.y + ccn.y;
    float v2 = m.z - ycn.z + ccn.z;
    float v3 = m.w - ycn.w + ccn.w;
    v0 = v0 > 0.f ? v0 : 0.2f * v0;
    v1 = v1 > 0.f ? v1 : 0.2f * v1;
    v2 = v2 > 0.f ? v2 : 0.2f * v2;
    v3 = v3 > 0.f ? v3 : 0.2f * v3;
    *(float4*)(out + (mbase + n) * ldo + 4 * c) = make_float4(v0, v1, v2, v3);
}

__global__ void maxpool2(const float* __restrict__ part, float* __restrict__ out) {
    int b = blockIdx.y;
    int f = blockIdx.x * blockDim.x + threadIdx.x;
    float m = -FLT_MAX;
#pragma unroll
    for (int c = 0; c < 16; ++c) m = fmaxf(m, part[(c * BB + b) * 1024 + f]);
    out[b * 1024 + f] = m;
}

// =================== launch ===================
extern "C" void kernel_launch(void* const* d_in, const int* in_sizes, int n_in,
                              void* d_out, int out_size) {
    const float* x     = (const float*)d_in[0];
    const float* Wl[4] = {(const float*)d_in[1], (const float*)d_in[3],
                          (const float*)d_in[5], (const float*)d_in[7]};
    const float* bl[4] = {(const float*)d_in[2], (const float*)d_in[4],
                          (const float*)d_in[6], (const float*)d_in[8]};
    const float* Wf = (const float*)d_in[9];
    const float* bf = (const float*)d_in[10];
    float* out = (float*)d_out;

    float *p_d2, *p_sub, *p_xx, *p_yc, *p_hcat, *p_part, *p_bias2;
    __nv_bfloat16 *p_a3, *p_b3, *p_bf3, *p_w3;
    int *p_idx, *p_ov;
    cudaGetSymbolAddress((void**)&p_d2,    g_d2);
    cudaGetSymbolAddress((void**)&p_sub,   g_submin);
    cudaGetSymbolAddress((void**)&p_xx,    g_xx);
    cudaGetSymbolAddress((void**)&p_idx,   g_idx);
    cudaGetSymbolAddress((void**)&p_ov,    g_ov);
    cudaGetSymbolAddress((void**)&p_yc,    g_yc);
    cudaGetSymbolAddress((void**)&p_hcat,  g_hcat);
    cudaGetSymbolAddress((void**)&p_part,  g_part);
    cudaGetSymbolAddress((void**)&p_bias2, g_bias2);
    cudaGetSymbolAddress((void**)&p_a3,    g_a3);
    cudaGetSymbolAddress((void**)&p_b3,    g_b3);
    cudaGetSymbolAddress((void**)&p_bf3,   g_bf3);
    cudaGetSymbolAddress((void**)&p_w3,    g_w3);

    cudaFuncSetAttribute(mma_gemm, cudaFuncAttributeMaxDynamicSharedMemorySize,
                         MMA_SMEM);
    cudaFuncSetAttribute(mma_gemm_pool, cudaFuncAttributeMaxDynamicSharedMemorySize,
                         MMA_SMEM);

    // one-time host-side stream/event resources (no device memory)
    static cudaStream_t s_aux = nullptr;
    static cudaEvent_t evF = nullptr, evJ = nullptr;
    if (!s_aux) {
        cudaStreamCreateWithFlags(&s_aux, cudaStreamNonBlocking);
        cudaEventCreateWithFlags(&evF, cudaEventDisableTiming);
        cudaEventCreateWithFlags(&evJ, cudaEventDisableTiming);
    }

    const int Cs[4]  = {3, 64, 64, 128};
    const int Os[4]  = {64, 64, 128, 256};
    const int off[4] = {0, 64, 128, 256};

    // Wf conversion depends only on input: fork it onto aux stream immediately.
    cudaEventRecord(evF, 0);
    cudaStreamWaitEvent(s_aux, evF, 0);
    {
        int tot = 1024 * 1536;
        convB_kernel<<<(tot + 255) / 256, 256, 0, s_aux>>>(Wf, 512, 512, p_bf3, 1536, tot);
    }

    const float* Xin = x;
    int ldx = 3;
    for (int l = 0; l < 4; ++l) {
        int C = Cs[l], O = Os[l];
        int K3 = ((3 * C + 63) / 64) * 64;     // 64, 192, 192, 384
        int G = 512 / O;                       // points per edgemax block

        xx_kernel<<<(BB * NN) / 8, 256>>>(Xin, ldx, C, p_xx);
        {
            int tot = BB * NN * K3;
            convAB_kernel<<<(tot + 255) / 256, 256>>>(Xin, ldx, C, p_a3, p_b3, K3, tot);
        }
        // fork: stream0 = knn chain; s_aux = yc chain
        cudaEventRecord(evF, 0);
        cudaStreamWaitEvent(s_aux, evF, 0);

        mma_gemm<<<dim3(16, 16, BB), 256, MMA_SMEM>>>(
            p_a3, K3, (size_t)NN * K3, p_b3, K3, (size_t)NN * K3,
            NN, K3, p_d2, NN, (size_t)NN * NN, nullptr, 0, 1, p_xx, NN, p_sub);
        topk_sel<<<(BB * NN) / 8, 256>>>(p_d2, p_sub, p_idx, p_ov);
        topk_fb<<<(BB * NN) / 8, 256>>>(p_d2, p_ov, p_idx);

        {
            int totw = O * K3;
            convB_kernel<<<(totw + 255) / 256, 256, 0, s_aux>>>(
                Wl[l], 2 * C, C, p_w3, K3, totw);
            convB_kernel<<<(totw + 255) / 256, 256, 0, s_aux>>>(
                Wl[l] + C, 2 * C, C, p_w3 + (size_t)O * K3, K3, totw);
        }
        biascat<<<1, 512, 0, s_aux>>>(bl[l], p_bias2, O);
        mma_gemm<<<dim3((2 * O + 127) / 128, (BB * NN) / 128, 1), 256, MMA_SMEM, s_aux>>>(
            p_a3, K3, 0, p_w3, K3, 0, 2 * O, K3,
            p_yc, 2 * O, 0, p_bias2, 0, 0, nullptr, 0, nullptr);
        cudaEventRecord(evJ, s_aux);
        cudaStreamWaitEvent(0, evJ, 0);

        edgemax4<<<dim3(NN / G, BB), 128>>>(p_yc, p_idx, p_hcat + off[l], O, 512);
        Xin = p_hcat + off[l];
        ldx = 512;
    }
    // final 512 -> 1024 linear + leaky + fused max-over-rows, then 16-way pool
    {
        int tot = BB * NN * 1536;
        convA_kernel<<<(tot + 255) / 256, 256>>>(p_hcat, 512, 512, p_a3, 1536, tot);
    }
    mma_gemm_pool<<<dim3(1024 / 128, (BB * NN) / 128), 256, MMA_SMEM>>>(
        p_a3, 1536, p_bf3, 1536, 1536, bf, p_part);
    maxpool2<<<dim3(1024 / 256, BB), 256>>>(p_part, out);
}